// round 1
// baseline (speedup 1.0000x reference)
#include <cuda_runtime.h>
#include <math.h>

#define Bsz 2
#define Sl  2048
#define Hn  16
#define Dh  64
#define Dm  1024
#define BSR (Bsz*Sl)   // 4096 rows

// Scratch (allowed: __device__ globals, no allocation)
__device__ float g_q[(size_t)BSR*Dm];
__device__ float g_k[(size_t)BSR*Dm];
__device__ float g_v[(size_t)BSR*Dm];
__device__ float g_z[(size_t)BSR*Dm];
__device__ float g_vpart[16*Bsz*Dm];
__device__ float g_vt[Bsz*Dm];

// ---------------------------------------------------------------------------
// Kernel 1: fused QKV projection.
// C[row, n] = sum_m x[row, m] * W_t[h, m, d], n = t*1024 + h*64 + d
// Tiles: 64x64, BK=32, 256 threads, 4x4 register blocking.
// ---------------------------------------------------------------------------
__global__ __launch_bounds__(256) void qkv_kernel(
    const float* __restrict__ x,
    const float* __restrict__ WQ, const float* __restrict__ bQ,
    const float* __restrict__ WK, const float* __restrict__ bK,
    const float* __restrict__ WV, const float* __restrict__ bV)
{
    __shared__ float Ast[32][68];   // [u][row]  (transposed A)
    __shared__ float Bs [32][68];   // [u][d]
    const int r0 = blockIdx.x * 64;
    const int n0 = blockIdx.y * 64;         // 0..3071, multiple of 64
    const int t  = n0 >> 10;                // 0=Q,1=K,2=V
    const int hd0 = n0 & 1023;
    const int h = hd0 >> 6;
    const float* W  = (t==0) ? WQ : (t==1) ? WK : WV;
    const float* bb = (t==0) ? bQ : (t==1) ? bK : bV;
    float* outp     = (t==0) ? g_q : (t==1) ? g_k : g_v;
    const float* Wb = W + (size_t)h * Dm * Dh;   // element (m,d) at m*Dh + d

    const int tid = threadIdx.x;
    const int tx = tid & 15, ty = tid >> 4;

    float acc[4][4] = {};
    for (int k0 = 0; k0 < Dm; k0 += 32) {
        #pragma unroll
        for (int r = 0; r < 2; r++) {
            int e = tid + r * 256;          // float4 slot: 64 rows x 8 groups
            int row = e >> 3, ug = e & 7;
            float4 v = *reinterpret_cast<const float4*>(
                &x[(size_t)(r0 + row) * Dm + k0 + ug * 4]);
            Ast[ug*4+0][row] = v.x; Ast[ug*4+1][row] = v.y;
            Ast[ug*4+2][row] = v.z; Ast[ug*4+3][row] = v.w;
        }
        #pragma unroll
        for (int r = 0; r < 2; r++) {
            int e = tid + r * 256;          // 32 rows x 16 groups
            int row = e >> 4, c4 = e & 15;
            float4 v = *reinterpret_cast<const float4*>(
                &Wb[(size_t)(k0 + row) * Dh + c4 * 4]);
            *reinterpret_cast<float4*>(&Bs[row][c4*4]) = v;
        }
        __syncthreads();
        #pragma unroll
        for (int u = 0; u < 32; u++) {
            float4 a  = *reinterpret_cast<const float4*>(&Ast[u][ty*4]);
            float4 bv = *reinterpret_cast<const float4*>(&Bs[u][tx*4]);
            float av[4] = {a.x, a.y, a.z, a.w};
            float bw[4] = {bv.x, bv.y, bv.z, bv.w};
            #pragma unroll
            for (int i = 0; i < 4; i++)
                #pragma unroll
                for (int j = 0; j < 4; j++) acc[i][j] += av[i] * bw[j];
        }
        __syncthreads();
    }
    #pragma unroll
    for (int i = 0; i < 4; i++) {
        int row = r0 + ty*4 + i;
        float4 o;
        o.x = acc[i][0] + bb[hd0 + tx*4 + 0];
        o.y = acc[i][1] + bb[hd0 + tx*4 + 1];
        o.z = acc[i][2] + bb[hd0 + tx*4 + 2];
        o.w = acc[i][3] + bb[hd0 + tx*4 + 3];
        *reinterpret_cast<float4*>(&outp[(size_t)row * Dm + hd0 + tx*4]) = o;
    }
}

// ---------------------------------------------------------------------------
// Kernels 2+3: totalV[b, h*64+d] = sum_s v   (two-stage, atomic-free)
// ---------------------------------------------------------------------------
__global__ void vtot_part() {
    int idx = blockIdx.x * 256 + threadIdx.x;   // 0..2047  (b*1024 + hd)
    int c = blockIdx.y;                         // chunk 0..15, 128 k each
    int b = idx >> 10, hd = idx & 1023;
    const float* p = g_v + (size_t)(b * Sl + c * 128) * Dm + hd;
    float s = 0.f;
    #pragma unroll 8
    for (int k = 0; k < 128; k++) s += p[(size_t)k * Dm];
    g_vpart[c * (Bsz * Dm) + idx] = s;
}
__global__ void vtot_reduce() {
    int idx = blockIdx.x * 256 + threadIdx.x;
    float s = 0.f;
    #pragma unroll
    for (int c = 0; c < 16; c++) s += g_vpart[c * (Bsz * Dm) + idx];
    g_vt[idx] = s;
}

// ---------------------------------------------------------------------------
// Kernel 4: attention with the 0-mask softmax rewritten as:
//   p_k = exp(s_k)-1 for k<=q else 0
//   z = (totalV + sum p_k v_k) / (S + sum p_k)
// Block = (qb, h, b), BQ=64 queries, k-tiles of 32. 256 threads.
// ---------------------------------------------------------------------------
__global__ __launch_bounds__(256) void attn_kernel() {
    __shared__ float Qst[64][68];   // [d][q]
    __shared__ float Kst[64][36];   // [d][k]
    __shared__ float Vs [32][68];   // [k][d]
    __shared__ float Pst[32][68];   // [k][q]

    const int qb = (gridDim.x - 1) - blockIdx.x;   // heavy blocks first
    const int h = blockIdx.y, b = blockIdx.z;
    const int q0 = qb * 64;
    const int tid = threadIdx.x, tx = tid & 15, ty = tid >> 4;
    const size_t base = (size_t)b * Sl * Dm + h * 64;

    // Load Q tile transposed: [64 q][64 d] -> Qst[d][q]
    #pragma unroll
    for (int r = 0; r < 4; r++) {
        int e = tid + r * 256;
        int row = e >> 4, c4 = e & 15;
        float4 v = *reinterpret_cast<const float4*>(
            &g_q[base + (size_t)(q0 + row) * Dm + c4 * 4]);
        Qst[c4*4+0][row] = v.x; Qst[c4*4+1][row] = v.y;
        Qst[c4*4+2][row] = v.z; Qst[c4*4+3][row] = v.w;
    }

    float acc[4][4] = {};
    float lsum[4] = {};
    const int ntiles = 2 * qb + 2;              // covers k <= q0+63
    for (int t = 0; t < ntiles; t++) {
        const int kt0 = t * 32;
        __syncthreads();   // previous GEMM2 done reading Vs (and Qst visible at t=0)
        #pragma unroll
        for (int r = 0; r < 2; r++) {
            int e = tid + r * 256;
            int row = e >> 4, c4 = e & 15;
            float4 kv = *reinterpret_cast<const float4*>(
                &g_k[base + (size_t)(kt0 + row) * Dm + c4 * 4]);
            Kst[c4*4+0][row] = kv.x; Kst[c4*4+1][row] = kv.y;
            Kst[c4*4+2][row] = kv.z; Kst[c4*4+3][row] = kv.w;
            float4 vv = *reinterpret_cast<const float4*>(
                &g_v[base + (size_t)(kt0 + row) * Dm + c4 * 4]);
            *reinterpret_cast<float4*>(&Vs[row][c4*4]) = vv;
        }
        __syncthreads();

        // GEMM1: s[q 4][k 2] = Q K^T over d=64
        float s[4][2] = {};
        #pragma unroll
        for (int d = 0; d < 64; d++) {
            float4 qv = *reinterpret_cast<const float4*>(&Qst[d][ty*4]);
            float2 kv = *reinterpret_cast<const float2*>(&Kst[d][tx*2]);
            s[0][0] += qv.x * kv.x; s[0][1] += qv.x * kv.y;
            s[1][0] += qv.y * kv.x; s[1][1] += qv.y * kv.y;
            s[2][0] += qv.z * kv.x; s[2][1] += qv.z * kv.y;
            s[3][0] += qv.w * kv.x; s[3][1] += qv.w * kv.y;
        }
        // mask + (exp-1), accumulate row sums, write P transposed
        #pragma unroll
        for (int c = 0; c < 2; c++) {
            int kg = kt0 + tx*2 + c;
            float pa[4];
            #pragma unroll
            for (int i = 0; i < 4; i++) {
                int qg = q0 + ty*4 + i;
                float p = (kg <= qg) ? (expf(s[i][c] * 0.125f) - 1.f) : 0.f;
                lsum[i] += p;
                pa[i] = p;
            }
            float4 pv = make_float4(pa[0], pa[1], pa[2], pa[3]);
            *reinterpret_cast<float4*>(&Pst[tx*2+c][ty*4]) = pv;
        }
        __syncthreads();

        // GEMM2: acc[q 4][d 4] += P^T V over k=32
        #pragma unroll
        for (int k = 0; k < 32; k++) {
            float4 pv = *reinterpret_cast<const float4*>(&Pst[k][ty*4]);
            float4 vv = *reinterpret_cast<const float4*>(&Vs[k][tx*4]);
            float pr[4] = {pv.x, pv.y, pv.z, pv.w};
            float vr[4] = {vv.x, vv.y, vv.z, vv.w};
            #pragma unroll
            for (int i = 0; i < 4; i++)
                #pragma unroll
                for (int j = 0; j < 4; j++) acc[i][j] += pr[i] * vr[j];
        }
    }

    // Reduce lsum across the 16-lane tx group (lane bits 0..3)
    #pragma unroll
    for (int i = 0; i < 4; i++)
        #pragma unroll
        for (int o = 1; o < 16; o <<= 1)
            lsum[i] += __shfl_xor_sync(0xffffffffu, lsum[i], o);

    float4 vt = *reinterpret_cast<const float4*>(&g_vt[b * Dm + h * 64 + tx * 4]);
    float vta[4] = {vt.x, vt.y, vt.z, vt.w};
    #pragma unroll
    for (int i = 0; i < 4; i++) {
        float inv = 1.f / ((float)Sl + lsum[i]);
        float4 o;
        o.x = (vta[0] + acc[i][0]) * inv;
        o.y = (vta[1] + acc[i][1]) * inv;
        o.z = (vta[2] + acc[i][2]) * inv;
        o.w = (vta[3] + acc[i][3]) * inv;
        *reinterpret_cast<float4*>(
            &g_z[base + (size_t)(q0 + ty*4 + i) * Dm + tx * 4]) = o;
    }
}

// ---------------------------------------------------------------------------
// Kernel 5: output projection. out[row, m] = sum_hd z[row, hd] * WO[hd, m] + bO[m]
// ---------------------------------------------------------------------------
__global__ __launch_bounds__(256) void oproj_kernel(
    const float* __restrict__ WO, const float* __restrict__ bO,
    float* __restrict__ out)
{
    __shared__ float Ast[32][68];
    __shared__ float Bs [32][68];
    const int r0 = blockIdx.x * 64;
    const int n0 = blockIdx.y * 64;
    const int tid = threadIdx.x, tx = tid & 15, ty = tid >> 4;

    float acc[4][4] = {};
    for (int k0 = 0; k0 < Dm; k0 += 32) {
        #pragma unroll
        for (int r = 0; r < 2; r++) {
            int e = tid + r * 256;
            int row = e >> 3, ug = e & 7;
            float4 v = *reinterpret_cast<const float4*>(
                &g_z[(size_t)(r0 + row) * Dm + k0 + ug * 4]);
            Ast[ug*4+0][row] = v.x; Ast[ug*4+1][row] = v.y;
            Ast[ug*4+2][row] = v.z; Ast[ug*4+3][row] = v.w;
        }
        #pragma unroll
        for (int r = 0; r < 2; r++) {
            int e = tid + r * 256;
            int row = e >> 4, c4 = e & 15;
            float4 v = *reinterpret_cast<const float4*>(
                &WO[(size_t)(k0 + row) * Dm + n0 + c4 * 4]);
            *reinterpret_cast<float4*>(&Bs[row][c4*4]) = v;
        }
        __syncthreads();
        #pragma unroll
        for (int u = 0; u < 32; u++) {
            float4 a  = *reinterpret_cast<const float4*>(&Ast[u][ty*4]);
            float4 bv = *reinterpret_cast<const float4*>(&Bs[u][tx*4]);
            float av[4] = {a.x, a.y, a.z, a.w};
            float bw[4] = {bv.x, bv.y, bv.z, bv.w};
            #pragma unroll
            for (int i = 0; i < 4; i++)
                #pragma unroll
                for (int j = 0; j < 4; j++) acc[i][j] += av[i] * bw[j];
        }
        __syncthreads();
    }
    #pragma unroll
    for (int i = 0; i < 4; i++) {
        float4 o;
        o.x = acc[i][0] + bO[n0 + tx*4 + 0];
        o.y = acc[i][1] + bO[n0 + tx*4 + 1];
        o.z = acc[i][2] + bO[n0 + tx*4 + 2];
        o.w = acc[i][3] + bO[n0 + tx*4 + 3];
        *reinterpret_cast<float4*>(
            &out[(size_t)(r0 + ty*4 + i) * Dm + n0 + tx*4]) = o;
    }
}

// ---------------------------------------------------------------------------
extern "C" void kernel_launch(void* const* d_in, const int* in_sizes, int n_in,
                              void* d_out, int out_size) {
    const float* x  = (const float*)d_in[0];
    const float* WQ = (const float*)d_in[1];
    const float* bQ = (const float*)d_in[2];
    const float* WK = (const float*)d_in[3];
    const float* bK = (const float*)d_in[4];
    const float* WV = (const float*)d_in[5];
    const float* bV = (const float*)d_in[6];
    const float* WO = (const float*)d_in[7];
    const float* bO = (const float*)d_in[8];
    float* out = (float*)d_out;

    qkv_kernel<<<dim3(BSR/64, 48), 256>>>(x, WQ, bQ, WK, bK, WV, bV);
    vtot_part<<<dim3(8, 16), 256>>>();
    vtot_reduce<<<8, 256>>>();
    attn_kernel<<<dim3(Sl/64, Hn, Bsz), 256>>>();
    oproj_kernel<<<dim3(BSR/64, Dm/64), 256>>>(WO, bO, out);
}

// round 4
// speedup vs baseline: 1.9171x; 1.9171x over previous
#include <cuda_runtime.h>
#include <cuda_bf16.h>
#include <math.h>
#include <stdint.h>

#define Bsz 2
#define Sl  2048
#define Hn  16
#define Dh  64
#define Dm  1024
#define BSR 4096
#define KE  3072     // extended K = 3 * 1024

typedef __nv_bfloat16 bf16;
typedef __nv_bfloat162 bf162;

#define HEAD_ELEMS ((size_t)Bsz*Hn*Sl*Dh)

// -------- scratch: device globals only (no allocation) ----------------------
__device__ __align__(16) bf16 g_xe [(size_t)BSR*KE];    // x extended  [r][k'']
__device__ __align__(16) bf16 g_ze [(size_t)BSR*KE];    // z extended
__device__ __align__(16) bf16 g_we [(size_t)KE*KE];     // W_qkv^T ext [n][k'']
__device__ __align__(16) bf16 g_woe[(size_t)Dm*KE];     // W_O^T  ext  [n][k'']
__device__ __align__(16) bf16 g_qh[HEAD_ELEMS], g_ql[HEAD_ELEMS];  // [bh][s][d]
__device__ __align__(16) bf16 g_kh[HEAD_ELEMS], g_kl[HEAD_ELEMS];
__device__ __align__(16) bf16 g_vh[HEAD_ELEMS], g_vl[HEAD_ELEMS];
__device__ __align__(16) bf16 g_vth[HEAD_ELEMS], g_vtl[HEAD_ELEMS]; // [bh][d][s]
__device__ float g_vt[Bsz*Hn*Dh];

// -------- helpers ------------------------------------------------------------
__device__ __forceinline__ uint32_t smem_u32(const void* p) {
    uint32_t a;
    asm("{ .reg .u64 t; cvta.to.shared.u64 t, %1; cvt.u32.u64 %0, t; }"
        : "=r"(a) : "l"(p));
    return a;
}
__device__ __forceinline__ void cpa16(uint32_t dst, const void* src) {
    asm volatile("cp.async.ca.shared.global [%0], [%1], 16;" :: "r"(dst), "l"(src));
}
#define CP_COMMIT() asm volatile("cp.async.commit_group;")
#define CP_WAIT0()  asm volatile("cp.async.wait_group 0;")

__device__ __forceinline__ void mma_bf16(float c[4],
    uint32_t a0, uint32_t a1, uint32_t a2, uint32_t a3,
    uint32_t b0, uint32_t b1) {
    asm volatile(
        "mma.sync.aligned.m16n8k16.row.col.f32.bf16.bf16.f32 "
        "{%0,%1,%2,%3}, {%4,%5,%6,%7}, {%8,%9}, {%0,%1,%2,%3};"
        : "+f"(c[0]), "+f"(c[1]), "+f"(c[2]), "+f"(c[3])
        : "r"(a0), "r"(a1), "r"(a2), "r"(a3), "r"(b0), "r"(b1));
}

__device__ __forceinline__ void split2(float v, bf16& h, bf16& l) {
    h = __float2bfloat16_rn(v);
    l = __float2bfloat16_rn(v - __bfloat162float(h));
}

// -------- prep: split x into extended-K bf16 ---------------------------------
__global__ __launch_bounds__(256) void split_x(const float* __restrict__ x) {
    size_t i = ((size_t)blockIdx.x * 256 + threadIdx.x) * 4;   // < 4096*1024
    float4 v = *reinterpret_cast<const float4*>(x + i);
    int r = (int)(i >> 10), m = (int)(i & 1023);
    bf16* row = g_xe + (size_t)r * KE;
    bf16 hx, lx, hy, ly, hz, lz, hw, lw;
    split2(v.x, hx, lx); split2(v.y, hy, ly);
    split2(v.z, hz, lz); split2(v.w, hw, lw);
    bf162 h01; h01.x = hx; h01.y = hy;
    bf162 h23; h23.x = hz; h23.y = hw;
    bf162 l01; l01.x = lx; l01.y = ly;
    bf162 l23; l23.x = lz; l23.y = lw;
    *(bf162*)(row + m)          = h01; *(bf162*)(row + m + 2)        = h23;
    *(bf162*)(row + 1024 + m)   = l01; *(bf162*)(row + 1024 + m + 2) = l23;
    *(bf162*)(row + 2048 + m)   = h01; *(bf162*)(row + 2048 + m + 2) = h23;
}

// -------- prep: transpose+split QKV weights  W[h][m][d] -> g_we[n][k''] ------
__global__ __launch_bounds__(256) void tw_qkv(
    const float* __restrict__ WQ, const float* __restrict__ WK,
    const float* __restrict__ WV) {
    __shared__ float tile[64][68];
    int th = blockIdx.y;                 // 0..47
    int t = th >> 4, h = th & 15;
    int m0 = blockIdx.x * 64;
    const float* W = ((t == 0) ? WQ : (t == 1) ? WK : WV) + (size_t)h * Dm * Dh;
    int tid = threadIdx.x;
    {
        int row = tid >> 2, fg = tid & 3;
        #pragma unroll
        for (int jj = 0; jj < 4; jj++) {
            int c = fg * 16 + jj * 4;
            *(float4*)&tile[row][c] =
                *(const float4*)(W + (size_t)(m0 + row) * Dh + c);
        }
    }
    __syncthreads();
    int dd = tid >> 2, ch = tid & 3;
    __align__(16) bf16 hb[16], lb[16];
    #pragma unroll
    for (int jj = 0; jj < 16; jj++) {
        float w = tile[ch * 16 + jj][dd];
        split2(w, hb[jj], lb[jj]);
    }
    int n = t * 1024 + h * 64 + dd;
    size_t base = (size_t)n * KE + m0 + ch * 16;
    uint4* hp = (uint4*)hb; uint4* lp = (uint4*)lb;
    *(uint4*)(g_we + base)            = hp[0]; *(uint4*)(g_we + base + 8)        = hp[1];
    *(uint4*)(g_we + base + 1024)     = hp[0]; *(uint4*)(g_we + base + 1024 + 8) = hp[1];
    *(uint4*)(g_we + base + 2048)     = lp[0]; *(uint4*)(g_we + base + 2048 + 8) = lp[1];
}

// -------- prep: transpose+split WO  WO[hd][mout] -> g_woe[mout][k''] ---------
__global__ __launch_bounds__(256) void tw_o(const float* __restrict__ WO) {
    __shared__ float tile[64][68];
    int mo0 = blockIdx.x * 64, hd0 = blockIdx.y * 64;
    int tid = threadIdx.x;
    {
        int row = tid >> 2, fg = tid & 3;
        #pragma unroll
        for (int jj = 0; jj < 4; jj++) {
            int c = fg * 16 + jj * 4;
            *(float4*)&tile[row][c] =
                *(const float4*)(WO + (size_t)(hd0 + row) * Dm + mo0 + c);
        }
    }
    __syncthreads();
    int mo = tid >> 2, ch = tid & 3;
    __align__(16) bf16 hb[16], lb[16];
    #pragma unroll
    for (int jj = 0; jj < 16; jj++) {
        float w = tile[ch * 16 + jj][mo];
        split2(w, hb[jj], lb[jj]);
    }
    int n = mo0 + mo;
    size_t base = (size_t)n * KE + hd0 + ch * 16;
    uint4* hp = (uint4*)hb; uint4* lp = (uint4*)lb;
    *(uint4*)(g_woe + base)            = hp[0]; *(uint4*)(g_woe + base + 8)        = hp[1];
    *(uint4*)(g_woe + base + 1024)     = hp[0]; *(uint4*)(g_woe + base + 1024 + 8) = hp[1];
    *(uint4*)(g_woe + base + 2048)     = lp[0]; *(uint4*)(g_woe + base + 2048 + 8) = lp[1];
}

// -------- GEMM mainloop: C(128x128) += Ae(128xKE) . Be(128xKE)^T -------------
typedef bf16 SmemStage[2][128][40];

__device__ __forceinline__ void gemm_issue(
    const bf16* __restrict__ Ag, const bf16* __restrict__ Bg,
    uint32_t sA, uint32_t sB, int r0, int n0, int buf, int kt, int tid) {
    const int lrow = tid >> 1, lj = (tid & 1) * 16;   // two float4 per thread
    const bf16* ag = Ag + (size_t)(r0 + lrow) * KE + kt * 32 + lj;
    const bf16* bg = Bg + (size_t)(n0 + lrow) * KE + kt * 32 + lj;
    uint32_t da = sA + (uint32_t)buf * 10240 + (uint32_t)(lrow * 40 + lj) * 2;
    uint32_t db = sB + (uint32_t)buf * 10240 + (uint32_t)(lrow * 40 + lj) * 2;
    cpa16(da, ag); cpa16(da + 16, ag + 8);
    cpa16(db, bg); cpa16(db + 16, bg + 8);
}

__device__ __forceinline__ void gemm_main(
    const bf16* __restrict__ Ag, const bf16* __restrict__ Bg,
    int r0, int n0, SmemStage& As, SmemStage& Bs, float acc[4][4][4]) {
    const int tid = threadIdx.x, wid = tid >> 5, l = tid & 31;
    const int wy = wid >> 2, wx = wid & 3;
    const int lr = l >> 2, lc = (l & 3) * 2;
    uint32_t sA = smem_u32(&As[0][0][0]);
    uint32_t sB = smem_u32(&Bs[0][0][0]);

    gemm_issue(Ag, Bg, sA, sB, r0, n0, 0, 0, tid);
    CP_COMMIT();
    int buf = 0;
    for (int kt = 0; kt < 96; kt++) {
        CP_WAIT0();
        __syncthreads();
        if (kt + 1 < 96) { gemm_issue(Ag, Bg, sA, sB, r0, n0, buf ^ 1, kt + 1, tid); CP_COMMIT(); }
        #pragma unroll
        for (int ks = 0; ks < 2; ks++) {
            int kb = ks * 16 + lc;
            uint32_t a[4][4], bq[4][2];
            #pragma unroll
            for (int mi = 0; mi < 4; mi++) {
                int r = wy * 64 + mi * 16 + lr;
                a[mi][0] = *(const uint32_t*)&As[buf][r][kb];
                a[mi][1] = *(const uint32_t*)&As[buf][r + 8][kb];
                a[mi][2] = *(const uint32_t*)&As[buf][r][kb + 8];
                a[mi][3] = *(const uint32_t*)&As[buf][r + 8][kb + 8];
            }
            #pragma unroll
            for (int nj = 0; nj < 4; nj++) {
                int n = wx * 32 + nj * 8 + lr;
                bq[nj][0] = *(const uint32_t*)&Bs[buf][n][kb];
                bq[nj][1] = *(const uint32_t*)&Bs[buf][n][kb + 8];
            }
            #pragma unroll
            for (int mi = 0; mi < 4; mi++)
                #pragma unroll
                for (int nj = 0; nj < 4; nj++)
                    mma_bf16(acc[mi][nj], a[mi][0], a[mi][1], a[mi][2], a[mi][3],
                             bq[nj][0], bq[nj][1]);
        }
        buf ^= 1;
    }
}

// -------- QKV projection GEMM -----------------------------------------------
__global__ __launch_bounds__(256) void gemm_qkv(
    const float* __restrict__ bQ, const float* __restrict__ bK,
    const float* __restrict__ bV) {
    __shared__ SmemStage As, Bs;
    const int r0 = blockIdx.x * 128, n0 = blockIdx.y * 128;
    float acc[4][4][4] = {};
    gemm_main(g_xe, g_we, r0, n0, As, Bs, acc);

    const int tid = threadIdx.x, wid = tid >> 5, l = tid & 31;
    const int wy = wid >> 2, wx = wid & 3;
    const int t = n0 >> 10, hd0 = n0 & 1023;
    const float* bb = (t == 0) ? bQ : (t == 1) ? bK : bV;
    bf16* dh = (t == 0) ? g_qh : (t == 1) ? g_kh : g_vh;
    bf16* dl = (t == 0) ? g_ql : (t == 1) ? g_kl : g_vl;
    #pragma unroll
    for (int mi = 0; mi < 4; mi++)
        #pragma unroll
        for (int nj = 0; nj < 4; nj++)
            #pragma unroll
            for (int p = 0; p < 2; p++) {
                int row = r0 + wy * 64 + mi * 16 + (l >> 2) + 8 * p;
                int hd = hd0 + wx * 32 + nj * 8 + (l & 3) * 2;
                float v0 = acc[mi][nj][2 * p]     + bb[hd];
                float v1 = acc[mi][nj][2 * p + 1] + bb[hd + 1];
                int h = hd >> 6, d = hd & 63, b = row >> 11, s = row & 2047;
                size_t o = ((size_t)(b * Hn + h) * Sl + s) * 64 + d;
                bf16 h0, l0, h1, l1;
                split2(v0, h0, l0); split2(v1, h1, l1);
                bf162 hv; hv.x = h0; hv.y = h1;
                bf162 lv; lv.x = l0; lv.y = l1;
                *(bf162*)(dh + o) = hv;
                *(bf162*)(dl + o) = lv;
            }
}

// -------- output projection GEMM --------------------------------------------
__global__ __launch_bounds__(256) void gemm_o(
    const float* __restrict__ bO, float* __restrict__ out) {
    __shared__ SmemStage As, Bs;
    const int r0 = blockIdx.x * 128, n0 = blockIdx.y * 128;
    float acc[4][4][4] = {};
    gemm_main(g_ze, g_woe, r0, n0, As, Bs, acc);

    const int tid = threadIdx.x, wid = tid >> 5, l = tid & 31;
    const int wy = wid >> 2, wx = wid & 3;
    #pragma unroll
    for (int mi = 0; mi < 4; mi++)
        #pragma unroll
        for (int nj = 0; nj < 4; nj++)
            #pragma unroll
            for (int p = 0; p < 2; p++) {
                int row = r0 + wy * 64 + mi * 16 + (l >> 2) + 8 * p;
                int col = n0 + wx * 32 + nj * 8 + (l & 3) * 2;
                float2 o;
                o.x = acc[mi][nj][2 * p]     + bO[col];
                o.y = acc[mi][nj][2 * p + 1] + bO[col + 1];
                *(float2*)(out + (size_t)row * Dm + col) = o;
            }
}

// -------- V transpose: [bh][s][d] -> [bh][d][s] ------------------------------
__global__ __launch_bounds__(256) void vtrans() {
    __shared__ bf16 t0[64][72], t1[64][72];
    int bh = blockIdx.y, s0 = blockIdx.x * 64;
    int tid = threadIdx.x;
    #pragma unroll
    for (int i = 0; i < 2; i++) {
        int idx = tid + i * 256;
        int row = idx >> 3, j = (idx & 7) * 8;
        size_t src = ((size_t)bh * Sl + s0 + row) * 64 + j;
        *(float4*)&t0[row][j] = *(const float4*)(g_vh + src);
        *(float4*)&t1[row][j] = *(const float4*)(g_vl + src);
    }
    __syncthreads();
    int d = tid >> 2, g = tid & 3;
    __align__(16) bf16 bh16[16], bl16[16];
    #pragma unroll
    for (int jj = 0; jj < 16; jj++) {
        bh16[jj] = t0[g * 16 + jj][d];
        bl16[jj] = t1[g * 16 + jj][d];
    }
    size_t dst = ((size_t)bh * 64 + d) * Sl + s0 + g * 16;
    *(uint4*)(g_vth + dst)     = ((uint4*)bh16)[0];
    *(uint4*)(g_vth + dst + 8) = ((uint4*)bh16)[1];
    *(uint4*)(g_vtl + dst)     = ((uint4*)bl16)[0];
    *(uint4*)(g_vtl + dst + 8) = ((uint4*)bl16)[1];
}

// -------- totalV --------------------------------------------------------------
__global__ __launch_bounds__(256) void vtot_kernel() {
    __shared__ float part[4][64];
    int bh = blockIdx.x;
    int d = threadIdx.x & 63, c = threadIdx.x >> 6;
    float s = 0.f;
    for (int i = 0; i < 512; i++) {
        size_t o = ((size_t)bh * Sl + c * 512 + i) * 64 + d;
        s += __bfloat162float(g_vh[o]) + __bfloat162float(g_vl[o]);
    }
    part[c][d] = s;
    __syncthreads();
    if (threadIdx.x < 64) {
        int dd = threadIdx.x;
        g_vt[bh * 64 + dd] = part[0][dd] + part[1][dd] + part[2][dd] + part[3][dd];
    }
}

// -------- attention -----------------------------------------------------------
// p_k = exp(s_k)-1 for k<=q else 0 ;  z = (totalV + sum p v) / (2048 + sum p)
#define ATT_SMEM (4*18432 + 512 + 256)

__global__ __launch_bounds__(128) void attn_kernel() {
    extern __shared__ char sm[];
    typedef bf16 Seg[64][72];
    Seg* Qs = (Seg*)(sm);             // [2]
    Seg* Ks = (Seg*)(sm + 18432);
    Seg* Vs = (Seg*)(sm + 36864);     // [d][keys]
    Seg* Ps = (Seg*)(sm + 55296);
    float* red  = (float*)(sm + 73728);   // [64][2]
    float* invs = (float*)(sm + 73728 + 512);

    const int qb = 31 - blockIdx.x;
    const int h = blockIdx.y, b = blockIdx.z;
    const int bh = b * Hn + h;
    const int q0 = qb * 64;
    const int tid = threadIdx.x, wid = tid >> 5, l = tid & 31;
    const int wy = wid >> 1, wx = wid & 1;
    const int lr = l >> 2, lc = (l & 3) * 2;

    // load Q tile (both segs)
    #pragma unroll
    for (int i = 0; i < 4; i++) {
        int idx = tid + i * 128;
        int row = idx >> 3, j = (idx & 7) * 8;
        size_t src = ((size_t)bh * Sl + q0 + row) * 64 + j;
        *(float4*)&Qs[0][row][j] = *(const float4*)(g_qh + src);
        *(float4*)&Qs[1][row][j] = *(const float4*)(g_ql + src);
    }

    float o[2][4][4] = {};
    float lsum[4] = {};

    for (int kt = 0; kt <= qb; kt++) {
        __syncthreads();
        #pragma unroll
        for (int i = 0; i < 4; i++) {
            int idx = tid + i * 128;
            int row = idx >> 3, j = (idx & 7) * 8;
            size_t ksrc = ((size_t)bh * Sl + kt * 64 + row) * 64 + j;
            size_t vsrc = ((size_t)bh * 64 + row) * Sl + kt * 64 + j;
            *(float4*)&Ks[0][row][j] = *(const float4*)(g_kh + ksrc);
            *(float4*)&Ks[1][row][j] = *(const float4*)(g_kl + ksrc);
            *(float4*)&Vs[0][row][j] = *(const float4*)(g_vth + vsrc);
            *(float4*)&Vs[1][row][j] = *(const float4*)(g_vtl + vsrc);
        }
        __syncthreads();

        // ---- QK^T (3-term split) ----
        float sc[2][4][4] = {};
        #pragma unroll
        for (int sp = 0; sp < 3; sp++) {
            const int asg = (sp == 1), bsg = (sp == 2);
            #pragma unroll
            for (int ks = 0; ks < 4; ks++) {
                int kb = ks * 16 + lc;
                uint32_t a[2][4], bq[4][2];
                #pragma unroll
                for (int mi = 0; mi < 2; mi++) {
                    int r = wy * 32 + mi * 16 + lr;
                    a[mi][0] = *(const uint32_t*)&Qs[asg][r][kb];
                    a[mi][1] = *(const uint32_t*)&Qs[asg][r + 8][kb];
                    a[mi][2] = *(const uint32_t*)&Qs[asg][r][kb + 8];
                    a[mi][3] = *(const uint32_t*)&Qs[asg][r + 8][kb + 8];
                }
                #pragma unroll
                for (int nj = 0; nj < 4; nj++) {
                    int n = wx * 32 + nj * 8 + lr;
                    bq[nj][0] = *(const uint32_t*)&Ks[bsg][n][kb];
                    bq[nj][1] = *(const uint32_t*)&Ks[bsg][n][kb + 8];
                }
                #pragma unroll
                for (int mi = 0; mi < 2; mi++)
                    #pragma unroll
                    for (int nj = 0; nj < 4; nj++)
                        mma_bf16(sc[mi][nj], a[mi][0], a[mi][1], a[mi][2], a[mi][3],
                                 bq[nj][0], bq[nj][1]);
            }
        }

        // ---- mask + exp-1 + split + store P ----
        const bool diag = (kt == qb);
        #pragma unroll
        for (int mi = 0; mi < 2; mi++)
            #pragma unroll
            for (int nj = 0; nj < 4; nj++)
                #pragma unroll
                for (int p = 0; p < 2; p++) {
                    int qr = wy * 32 + mi * 16 + lr + 8 * p;
                    int kc = wx * 32 + nj * 8 + lc;
                    float s0 = sc[mi][nj][2 * p], s1 = sc[mi][nj][2 * p + 1];
                    float p0, p1;
                    if (diag) {
                        int qg = q0 + qr, kg = kt * 64 + kc;
                        p0 = (kg     <= qg) ? (expf(s0 * 0.125f) - 1.f) : 0.f;
                        p1 = (kg + 1 <= qg) ? (expf(s1 * 0.125f) - 1.f) : 0.f;
                    } else {
                        p0 = expf(s0 * 0.125f) - 1.f;
                        p1 = expf(s1 * 0.125f) - 1.f;
                    }
                    lsum[mi * 2 + p] += p0 + p1;
                    bf16 h0, l0, h1, l1;
                    split2(p0, h0, l0); split2(p1, h1, l1);
                    bf162 hv; hv.x = h0; hv.y = h1;
                    bf162 lv; lv.x = l0; lv.y = l1;
                    *(bf162*)&Ps[0][qr][kc] = hv;
                    *(bf162*)&Ps[1][qr][kc] = lv;
                }
        __syncthreads();

        // ---- P.V (3-term split) ----
        #pragma unroll
        for (int sp = 0; sp < 3; sp++) {
            const int asg = (sp == 1), bsg = (sp == 2);
            #pragma unroll
            for (int ks = 0; ks < 4; ks++) {
                int kb = ks * 16 + lc;
                uint32_t a[2][4], bq[4][2];
                #pragma unroll
                for (int mi = 0; mi < 2; mi++) {
                    int r = wy * 32 + mi * 16 + lr;
                    a[mi][0] = *(const uint32_t*)&Ps[asg][r][kb];
                    a[mi][1] = *(const uint32_t*)&Ps[asg][r + 8][kb];
                    a[mi][2] = *(const uint32_t*)&Ps[asg][r][kb + 8];
                    a[mi][3] = *(const uint32_t*)&Ps[asg][r + 8][kb + 8];
                }
                #pragma unroll
                for (int nj = 0; nj < 4; nj++) {
                    int n = wx * 32 + nj * 8 + lr;
                    bq[nj][0] = *(const uint32_t*)&Vs[bsg][n][kb];
                    bq[nj][1] = *(const uint32_t*)&Vs[bsg][n][kb + 8];
                }
                #pragma unroll
                for (int mi = 0; mi < 2; mi++)
                    #pragma unroll
                    for (int nj = 0; nj < 4; nj++)
                        mma_bf16(o[mi][nj], a[mi][0], a[mi][1], a[mi][2], a[mi][3],
                                 bq[nj][0], bq[nj][1]);
            }
        }
    }

    // ---- row-sum reduction ----
    #pragma unroll
    for (int s = 0; s < 4; s++) {
        lsum[s] += __shfl_xor_sync(0xffffffffu, lsum[s], 1);
        lsum[s] += __shfl_xor_sync(0xffffffffu, lsum[s], 2);
    }
    __syncthreads();
    if ((l & 3) == 0) {
        #pragma unroll
        for (int mi = 0; mi < 2; mi++)
            #pragma unroll
            for (int p = 0; p < 2; p++) {
                int qr = wy * 32 + mi * 16 + lr + 8 * p;
                red[qr * 2 + wx] = lsum[mi * 2 + p];
            }
    }
    __syncthreads();
    if (tid < 64) invs[tid] = 1.f / (2048.f + red[tid * 2] + red[tid * 2 + 1]);
    __syncthreads();

    // ---- epilogue: z = (vtot + o) * inv, write extended bf16 ----
    const float* vtotp = g_vt + bh * 64;
    #pragma unroll
    for (int mi = 0; mi < 2; mi++)
        #pragma unroll
        for (int nj = 0; nj < 4; nj++)
            #pragma unroll
            for (int p = 0; p < 2; p++) {
                int qr = wy * 32 + mi * 16 + lr + 8 * p;
                int dc = wx * 32 + nj * 8 + lc;
                float inv = invs[qr];
                float z0 = (vtotp[dc]     + o[mi][nj][2 * p])     * inv;
                float z1 = (vtotp[dc + 1] + o[mi][nj][2 * p + 1]) * inv;
                bf16 h0, l0, h1, l1;
                split2(z0, h0, l0); split2(z1, h1, l1);
                bf162 hv; hv.x = h0; hv.y = h1;
                bf162 lv; lv.x = l0; lv.y = l1;
                int rglob = b * Sl + q0 + qr;
                int hd = h * 64 + dc;
                bf16* zr = g_ze + (size_t)rglob * KE;
                *(bf162*)(zr + hd)        = hv;
                *(bf162*)(zr + 1024 + hd) = lv;
                *(bf162*)(zr + 2048 + hd) = hv;
            }
}

// ---------------------------------------------------------------------------
extern "C" void kernel_launch(void* const* d_in, const int* in_sizes, int n_in,
                              void* d_out, int out_size) {
    const float* x  = (const float*)d_in[0];
    const float* WQ = (const float*)d_in[1];
    const float* bQ = (const float*)d_in[2];
    const float* WK = (const float*)d_in[3];
    const float* bK = (const float*)d_in[4];
    const float* WV = (const float*)d_in[5];
    const float* bV = (const float*)d_in[6];
    const float* WO = (const float*)d_in[7];
    const float* bO = (const float*)d_in[8];
    float* out = (float*)d_out;

    cudaFuncSetAttribute(attn_kernel,
        cudaFuncAttributeMaxDynamicSharedMemorySize, ATT_SMEM);

    split_x<<<(BSR * 1024 / 4) / 256, 256>>>(x);
    tw_qkv<<<dim3(16, 48), 256>>>(WQ, WK, WV);
    tw_o<<<dim3(16, 16), 256>>>(WO);

    gemm_qkv<<<dim3(32, 24), 256>>>(bQ, bK, bV);

    vtrans<<<dim3(32, Bsz * Hn), 256>>>();
    vtot_kernel<<<Bsz * Hn, 256>>>();

    attn_kernel<<<dim3(32, Hn, Bsz), 128, ATT_SMEM>>>();

    gemm_o<<<dim3(32, 8), 256>>>(bO, out);
}

// round 5
// speedup vs baseline: 2.3059x; 1.2028x over previous
#include <cuda_runtime.h>
#include <cuda_bf16.h>
#include <math.h>
#include <stdint.h>

#define Bsz 2
#define Sl  2048
#define Hn  16
#define Dh  64
#define Dm  1024
#define BSR 4096
#define KE  3072     // extended K = 3 * 1024

typedef __nv_bfloat16 bf16;
typedef __nv_bfloat162 bf162;

#define HEAD_ELEMS ((size_t)Bsz*Hn*Sl*Dh)

// -------- scratch: device globals only (no allocation) ----------------------
__device__ __align__(16) bf16 g_xe [(size_t)BSR*KE];    // x extended  [r][k'']
__device__ __align__(16) bf16 g_ze [(size_t)BSR*KE];    // z extended
__device__ __align__(16) bf16 g_we [(size_t)KE*KE];     // W_qkv^T ext [n][k'']
__device__ __align__(16) bf16 g_woe[(size_t)Dm*KE];     // W_O^T  ext  [n][k'']
__device__ __align__(16) bf16 g_qh[HEAD_ELEMS], g_ql[HEAD_ELEMS];  // [bh][s][d]
__device__ __align__(16) bf16 g_kh[HEAD_ELEMS], g_kl[HEAD_ELEMS];
__device__ __align__(16) bf16 g_vh[HEAD_ELEMS], g_vl[HEAD_ELEMS];
__device__ __align__(16) bf16 g_vth[HEAD_ELEMS], g_vtl[HEAD_ELEMS]; // [bh][d][s]
__device__ float g_vt[Bsz*Hn*Dh];

// -------- helpers ------------------------------------------------------------
__device__ __forceinline__ uint32_t smem_u32(const void* p) {
    uint32_t a;
    asm("{ .reg .u64 t; cvta.to.shared.u64 t, %1; cvt.u32.u64 %0, t; }"
        : "=r"(a) : "l"(p));
    return a;
}
__device__ __forceinline__ void cpa16(uint32_t dst, const void* src) {
    asm volatile("cp.async.ca.shared.global [%0], [%1], 16;" :: "r"(dst), "l"(src));
}
#define CP_COMMIT() asm volatile("cp.async.commit_group;")
#define CP_WAIT0()  asm volatile("cp.async.wait_group 0;")
#define CP_WAIT1()  asm volatile("cp.async.wait_group 1;")

__device__ __forceinline__ void ldsm4(uint32_t r[4], uint32_t addr) {
    asm volatile("ldmatrix.sync.aligned.m8n8.x4.shared.b16 {%0,%1,%2,%3}, [%4];"
        : "=r"(r[0]), "=r"(r[1]), "=r"(r[2]), "=r"(r[3]) : "r"(addr));
}

__device__ __forceinline__ void mma_bf16(float c[4],
    uint32_t a0, uint32_t a1, uint32_t a2, uint32_t a3,
    uint32_t b0, uint32_t b1) {
    asm volatile(
        "mma.sync.aligned.m16n8k16.row.col.f32.bf16.bf16.f32 "
        "{%0,%1,%2,%3}, {%4,%5,%6,%7}, {%8,%9}, {%0,%1,%2,%3};"
        : "+f"(c[0]), "+f"(c[1]), "+f"(c[2]), "+f"(c[3])
        : "r"(a0), "r"(a1), "r"(a2), "r"(a3), "r"(b0), "r"(b1));
}

__device__ __forceinline__ void split2(float v, bf16& h, bf16& l) {
    h = __float2bfloat16_rn(v);
    l = __float2bfloat16_rn(v - __bfloat162float(h));
}

// -------- prep: split x into extended-K bf16 ---------------------------------
__global__ __launch_bounds__(256) void split_x(const float* __restrict__ x) {
    size_t i = ((size_t)blockIdx.x * 256 + threadIdx.x) * 4;
    float4 v = *reinterpret_cast<const float4*>(x + i);
    int r = (int)(i >> 10), m = (int)(i & 1023);
    bf16* row = g_xe + (size_t)r * KE;
    bf16 hx, lx, hy, ly, hz, lz, hw, lw;
    split2(v.x, hx, lx); split2(v.y, hy, ly);
    split2(v.z, hz, lz); split2(v.w, hw, lw);
    bf162 h01; h01.x = hx; h01.y = hy;
    bf162 h23; h23.x = hz; h23.y = hw;
    bf162 l01; l01.x = lx; l01.y = ly;
    bf162 l23; l23.x = lz; l23.y = lw;
    *(bf162*)(row + m)          = h01; *(bf162*)(row + m + 2)        = h23;
    *(bf162*)(row + 1024 + m)   = l01; *(bf162*)(row + 1024 + m + 2) = l23;
    *(bf162*)(row + 2048 + m)   = h01; *(bf162*)(row + 2048 + m + 2) = h23;
}

// -------- prep: transpose+split QKV weights ----------------------------------
__global__ __launch_bounds__(256) void tw_qkv(
    const float* __restrict__ WQ, const float* __restrict__ WK,
    const float* __restrict__ WV) {
    __shared__ float tile[64][68];
    int th = blockIdx.y;
    int t = th >> 4, h = th & 15;
    int m0 = blockIdx.x * 64;
    const float* W = ((t == 0) ? WQ : (t == 1) ? WK : WV) + (size_t)h * Dm * Dh;
    int tid = threadIdx.x;
    {
        int row = tid >> 2, fg = tid & 3;
        #pragma unroll
        for (int jj = 0; jj < 4; jj++) {
            int c = fg * 16 + jj * 4;
            *(float4*)&tile[row][c] =
                *(const float4*)(W + (size_t)(m0 + row) * Dh + c);
        }
    }
    __syncthreads();
    int dd = tid >> 2, ch = tid & 3;
    __align__(16) bf16 hb[16], lb[16];
    #pragma unroll
    for (int jj = 0; jj < 16; jj++) {
        float w = tile[ch * 16 + jj][dd];
        split2(w, hb[jj], lb[jj]);
    }
    int n = t * 1024 + h * 64 + dd;
    size_t base = (size_t)n * KE + m0 + ch * 16;
    uint4* hp = (uint4*)hb; uint4* lp = (uint4*)lb;
    *(uint4*)(g_we + base)            = hp[0]; *(uint4*)(g_we + base + 8)        = hp[1];
    *(uint4*)(g_we + base + 1024)     = hp[0]; *(uint4*)(g_we + base + 1024 + 8) = hp[1];
    *(uint4*)(g_we + base + 2048)     = lp[0]; *(uint4*)(g_we + base + 2048 + 8) = lp[1];
}

// -------- prep: transpose+split WO -------------------------------------------
__global__ __launch_bounds__(256) void tw_o(const float* __restrict__ WO) {
    __shared__ float tile[64][68];
    int mo0 = blockIdx.x * 64, hd0 = blockIdx.y * 64;
    int tid = threadIdx.x;
    {
        int row = tid >> 2, fg = tid & 3;
        #pragma unroll
        for (int jj = 0; jj < 4; jj++) {
            int c = fg * 16 + jj * 4;
            *(float4*)&tile[row][c] =
                *(const float4*)(WO + (size_t)(hd0 + row) * Dm + mo0 + c);
        }
    }
    __syncthreads();
    int mo = tid >> 2, ch = tid & 3;
    __align__(16) bf16 hb[16], lb[16];
    #pragma unroll
    for (int jj = 0; jj < 16; jj++) {
        float w = tile[ch * 16 + jj][mo];
        split2(w, hb[jj], lb[jj]);
    }
    int n = mo0 + mo;
    size_t base = (size_t)n * KE + hd0 + ch * 16;
    uint4* hp = (uint4*)hb; uint4* lp = (uint4*)lb;
    *(uint4*)(g_woe + base)            = hp[0]; *(uint4*)(g_woe + base + 8)        = hp[1];
    *(uint4*)(g_woe + base + 1024)     = hp[0]; *(uint4*)(g_woe + base + 1024 + 8) = hp[1];
    *(uint4*)(g_woe + base + 2048)     = lp[0]; *(uint4*)(g_woe + base + 2048 + 8) = lp[1];
}

// -------- GEMM: C(128x128) = Ae(128xKE).Be(128xKE)^T, 3-stage, ldmatrix ------
#define GST_B 10240                 // 128*40*2 per stage
#define SMEM_GEMM (3*GST_B*2)       // 61440

__device__ __forceinline__ void gemm_issue(
    const bf16* __restrict__ Ag, const bf16* __restrict__ Bg,
    uint32_t sA, uint32_t sB, int r0, int n0, int st, int kt, int tid) {
    const int lrow = tid >> 1, lj = (tid & 1) * 16;
    const bf16* ag = Ag + (size_t)(r0 + lrow) * KE + kt * 32 + lj;
    const bf16* bg = Bg + (size_t)(n0 + lrow) * KE + kt * 32 + lj;
    uint32_t da = sA + (uint32_t)st * GST_B + (uint32_t)(lrow * 40 + lj) * 2;
    uint32_t db = sB + (uint32_t)st * GST_B + (uint32_t)(lrow * 40 + lj) * 2;
    cpa16(da, ag); cpa16(da + 16, ag + 8);
    cpa16(db, bg); cpa16(db + 16, bg + 8);
}

__device__ __forceinline__ void gemm_main(
    const bf16* __restrict__ Ag, const bf16* __restrict__ Bg,
    int r0, int n0, char* dsm, float acc[4][4][4]) {
    const int tid = threadIdx.x, wid = tid >> 5, l = tid & 31;
    const int wy = wid >> 2, wx = wid & 3;
    const int g = l >> 3, lr8 = l & 7;
    uint32_t sA = smem_u32(dsm);
    uint32_t sB = sA + 3 * GST_B;
    const uint32_t aOff = (uint32_t)((wy * 64 + (g & 1) * 8 + lr8) * 40 + (g >> 1) * 8) * 2;
    const uint32_t bOff = (uint32_t)((wx * 32 + (g >> 1) * 8 + lr8) * 40 + (g & 1) * 8) * 2;

    gemm_issue(Ag, Bg, sA, sB, r0, n0, 0, 0, tid); CP_COMMIT();
    gemm_issue(Ag, Bg, sA, sB, r0, n0, 1, 1, tid); CP_COMMIT();

    for (int kt = 0; kt < 96; kt++) {
        CP_WAIT1();
        __syncthreads();
        if (kt + 2 < 96) {
            gemm_issue(Ag, Bg, sA, sB, r0, n0, (kt + 2) % 3, kt + 2, tid);
            CP_COMMIT();
        }
        uint32_t aB = sA + (uint32_t)(kt % 3) * GST_B;
        uint32_t bB = sB + (uint32_t)(kt % 3) * GST_B;
        #pragma unroll
        for (int ks = 0; ks < 2; ks++) {
            uint32_t a[4][4], bq[2][4];
            #pragma unroll
            for (int mi = 0; mi < 4; mi++)
                ldsm4(a[mi], aB + aOff + (uint32_t)(mi * 16 * 40 + ks * 16) * 2);
            #pragma unroll
            for (int p = 0; p < 2; p++)
                ldsm4(bq[p], bB + bOff + (uint32_t)(p * 16 * 40 + ks * 16) * 2);
            #pragma unroll
            for (int mi = 0; mi < 4; mi++)
                #pragma unroll
                for (int nj = 0; nj < 4; nj++)
                    mma_bf16(acc[mi][nj], a[mi][0], a[mi][1], a[mi][2], a[mi][3],
                             bq[nj >> 1][(nj & 1) * 2], bq[nj >> 1][(nj & 1) * 2 + 1]);
        }
    }
}

// -------- QKV projection GEMM ------------------------------------------------
__global__ __launch_bounds__(256) void gemm_qkv(
    const float* __restrict__ bQ, const float* __restrict__ bK,
    const float* __restrict__ bV) {
    extern __shared__ char dsm[];
    const int r0 = blockIdx.x * 128, n0 = blockIdx.y * 128;
    float acc[4][4][4] = {};
    gemm_main(g_xe, g_we, r0, n0, dsm, acc);

    const int tid = threadIdx.x, wid = tid >> 5, l = tid & 31;
    const int wy = wid >> 2, wx = wid & 3;
    const int t = n0 >> 10, hd0 = n0 & 1023;
    const float* bb = (t == 0) ? bQ : (t == 1) ? bK : bV;
    bf16* dh = (t == 0) ? g_qh : (t == 1) ? g_kh : g_vh;
    bf16* dl = (t == 0) ? g_ql : (t == 1) ? g_kl : g_vl;
    #pragma unroll
    for (int mi = 0; mi < 4; mi++)
        #pragma unroll
        for (int nj = 0; nj < 4; nj++)
            #pragma unroll
            for (int p = 0; p < 2; p++) {
                int row = r0 + wy * 64 + mi * 16 + (l >> 2) + 8 * p;
                int hd = hd0 + wx * 32 + nj * 8 + (l & 3) * 2;
                float v0 = acc[mi][nj][2 * p]     + bb[hd];
                float v1 = acc[mi][nj][2 * p + 1] + bb[hd + 1];
                int h = hd >> 6, d = hd & 63, b = row >> 11, s = row & 2047;
                size_t o = ((size_t)(b * Hn + h) * Sl + s) * 64 + d;
                bf16 h0, l0, h1, l1;
                split2(v0, h0, l0); split2(v1, h1, l1);
                bf162 hv; hv.x = h0; hv.y = h1;
                bf162 lv; lv.x = l0; lv.y = l1;
                *(bf162*)(dh + o) = hv;
                *(bf162*)(dl + o) = lv;
            }
}

// -------- output projection GEMM ---------------------------------------------
__global__ __launch_bounds__(256) void gemm_o(
    const float* __restrict__ bO, float* __restrict__ out) {
    extern __shared__ char dsm[];
    const int r0 = blockIdx.x * 128, n0 = blockIdx.y * 128;
    float acc[4][4][4] = {};
    gemm_main(g_ze, g_woe, r0, n0, dsm, acc);

    const int tid = threadIdx.x, wid = tid >> 5, l = tid & 31;
    const int wy = wid >> 2, wx = wid & 3;
    #pragma unroll
    for (int mi = 0; mi < 4; mi++)
        #pragma unroll
        for (int nj = 0; nj < 4; nj++)
            #pragma unroll
            for (int p = 0; p < 2; p++) {
                int row = r0 + wy * 64 + mi * 16 + (l >> 2) + 8 * p;
                int col = n0 + wx * 32 + nj * 8 + (l & 3) * 2;
                float2 o;
                o.x = acc[mi][nj][2 * p]     + bO[col];
                o.y = acc[mi][nj][2 * p + 1] + bO[col + 1];
                *(float2*)(out + (size_t)row * Dm + col) = o;
            }
}

// -------- V transpose: [bh][s][d] -> [bh][d][s] ------------------------------
__global__ __launch_bounds__(256) void vtrans() {
    __shared__ bf16 t0[64][72], t1[64][72];
    int bh = blockIdx.y, s0 = blockIdx.x * 64;
    int tid = threadIdx.x;
    #pragma unroll
    for (int i = 0; i < 2; i++) {
        int idx = tid + i * 256;
        int row = idx >> 3, j = (idx & 7) * 8;
        size_t src = ((size_t)bh * Sl + s0 + row) * 64 + j;
        *(float4*)&t0[row][j] = *(const float4*)(g_vh + src);
        *(float4*)&t1[row][j] = *(const float4*)(g_vl + src);
    }
    __syncthreads();
    int d = tid >> 2, g = tid & 3;
    __align__(16) bf16 bh16[16], bl16[16];
    #pragma unroll
    for (int jj = 0; jj < 16; jj++) {
        bh16[jj] = t0[g * 16 + jj][d];
        bl16[jj] = t1[g * 16 + jj][d];
    }
    size_t dst = ((size_t)bh * 64 + d) * Sl + s0 + g * 16;
    *(uint4*)(g_vth + dst)     = ((uint4*)bh16)[0];
    *(uint4*)(g_vth + dst + 8) = ((uint4*)bh16)[1];
    *(uint4*)(g_vtl + dst)     = ((uint4*)bl16)[0];
    *(uint4*)(g_vtl + dst + 8) = ((uint4*)bl16)[1];
}

// -------- totalV --------------------------------------------------------------
__global__ __launch_bounds__(256) void vtot_kernel() {
    __shared__ float part[4][64];
    int bh = blockIdx.x;
    int d = threadIdx.x & 63, c = threadIdx.x >> 6;
    float s = 0.f;
    for (int i = 0; i < 512; i++) {
        size_t o = ((size_t)bh * Sl + c * 512 + i) * 64 + d;
        s += __bfloat162float(g_vh[o]) + __bfloat162float(g_vl[o]);
    }
    part[c][d] = s;
    __syncthreads();
    if (threadIdx.x < 64) {
        int dd = threadIdx.x;
        g_vt[bh * 64 + dd] = part[0][dd] + part[1][dd] + part[2][dd] + part[3][dd];
    }
}

// -------- attention -----------------------------------------------------------
// p_k = exp(s_k)-1 for k<=q else 0 ; z = (totalV + sum p v) / (2048 + sum p)
// 256 threads, warp tile 16x32, 2-stage cp.async K/V prefetch, ldmatrix frags.
#define SEG_B 9216                     // 64*72*2
#define AQ    0
#define AK    18432                    // 2 stages x 2 segs
#define AV    55296
#define AP    92160
#define ARED  110592
#define AINV  111104
#define ATT_SMEM 111360

__global__ __launch_bounds__(256) void attn_kernel() {
    extern __shared__ char sm[];
    const uint32_t sb = smem_u32(sm);
    const uint32_t sQ = sb + AQ, sK = sb + AK, sV = sb + AV, sP = sb + AP;
    float* red  = (float*)(sm + ARED);
    float* invs = (float*)(sm + AINV);

    const int qb = 31 - blockIdx.x;                 // heavy blocks first
    const int h = blockIdx.y, b = blockIdx.z;
    const int bh = b * Hn + h;
    const int q0 = qb * 64;
    const int tid = threadIdx.x, wid = tid >> 5, l = tid & 31;
    const int wy = wid >> 1, wx = wid & 1;
    const int lr = l >> 2, lc = (l & 3) * 2;
    const int g = l >> 3, lr8 = l & 7;
    const uint32_t aOff = (uint32_t)((wy * 16 + (g & 1) * 8 + lr8) * 72 + (g >> 1) * 8) * 2;
    const uint32_t bOff = (uint32_t)((wx * 32 + (g >> 1) * 8 + lr8) * 72 + (g & 1) * 8) * 2;

    // load Q tile (both segs), plain loads into smem
    #pragma unroll
    for (int i = 0; i < 2; i++) {
        int idx = tid + i * 256;
        int row = idx >> 3, j = (idx & 7) * 8;
        size_t src = ((size_t)bh * Sl + q0 + row) * 64 + j;
        *(float4*)(sm + AQ + (row * 72 + j) * 2)         = *(const float4*)(g_qh + src);
        *(float4*)(sm + AQ + SEG_B + (row * 72 + j) * 2) = *(const float4*)(g_ql + src);
    }

    // K/V tile issue helper (cp.async, 8x16B per thread)
    auto issue_tile = [&](int st, int kt) {
        #pragma unroll
        for (int i = 0; i < 2; i++) {
            int idx = tid + i * 256;
            int row = idx >> 3, j = (idx & 7) * 8;
            uint32_t so = (uint32_t)(row * 72 + j) * 2;
            size_t ksrc = ((size_t)bh * Sl + kt * 64 + row) * 64 + j;
            size_t vsrc = ((size_t)bh * 64 + row) * Sl + kt * 64 + j;
            cpa16(sK + (st * 2 + 0) * SEG_B + so, g_kh + ksrc);
            cpa16(sK + (st * 2 + 1) * SEG_B + so, g_kl + ksrc);
            cpa16(sV + (st * 2 + 0) * SEG_B + so, g_vth + vsrc);
            cpa16(sV + (st * 2 + 1) * SEG_B + so, g_vtl + vsrc);
        }
    };

    issue_tile(0, 0); CP_COMMIT();

    float o[4][4] = {};
    float lsum[2] = {};

    for (int kt = 0; kt <= qb; kt++) {
        __syncthreads();                       // prev compute done; slot free
        const bool pre = (kt + 1 <= qb);
        if (pre) { issue_tile((kt + 1) & 1, kt + 1); CP_COMMIT(); }
        if (pre) { CP_WAIT1(); } else { CP_WAIT0(); }
        __syncthreads();
        const int buf = kt & 1;

        // ---- QK^T (3-term split) ----
        float sc[4][4] = {};
        #pragma unroll
        for (int sp = 0; sp < 3; sp++) {
            const int asg = (sp == 1), bsg = (sp == 2);
            const uint32_t aBase = sQ + (uint32_t)asg * SEG_B + aOff;
            const uint32_t bBase = sK + (uint32_t)(buf * 2 + bsg) * SEG_B + bOff;
            #pragma unroll
            for (int ks = 0; ks < 4; ks++) {
                uint32_t a[4], bq[2][4];
                ldsm4(a, aBase + (uint32_t)(ks * 16) * 2);
                #pragma unroll
                for (int p = 0; p < 2; p++)
                    ldsm4(bq[p], bBase + (uint32_t)(p * 16 * 72 + ks * 16) * 2);
                #pragma unroll
                for (int nj = 0; nj < 4; nj++)
                    mma_bf16(sc[nj], a[0], a[1], a[2], a[3],
                             bq[nj >> 1][(nj & 1) * 2], bq[nj >> 1][(nj & 1) * 2 + 1]);
            }
        }

        // ---- mask + exp-1 + split + store P ----
        const bool diag = (kt == qb);
        #pragma unroll
        for (int nj = 0; nj < 4; nj++)
            #pragma unroll
            for (int p = 0; p < 2; p++) {
                int qr = wy * 16 + lr + 8 * p;
                int kc = wx * 32 + nj * 8 + lc;
                float s0 = sc[nj][2 * p], s1 = sc[nj][2 * p + 1];
                float p0, p1;
                if (diag) {
                    int qg = q0 + qr, kg = kt * 64 + kc;
                    p0 = (kg     <= qg) ? (__expf(s0 * 0.125f) - 1.f) : 0.f;
                    p1 = (kg + 1 <= qg) ? (__expf(s1 * 0.125f) - 1.f) : 0.f;
                } else {
                    p0 = __expf(s0 * 0.125f) - 1.f;
                    p1 = __expf(s1 * 0.125f) - 1.f;
                }
                lsum[p] += p0 + p1;
                bf16 h0, l0, h1, l1;
                split2(p0, h0, l0); split2(p1, h1, l1);
                bf162 hv; hv.x = h0; hv.y = h1;
                bf162 lv; lv.x = l0; lv.y = l1;
                uint32_t po = (uint32_t)(qr * 72 + kc) * 2;
                *(bf162*)(sm + AP + po)         = hv;
                *(bf162*)(sm + AP + SEG_B + po) = lv;
            }
        __syncthreads();

        // ---- P.V (3-term split) ----
        #pragma unroll
        for (int sp = 0; sp < 3; sp++) {
            const int asg = (sp == 1), bsg = (sp == 2);
            const uint32_t aBase = sP + (uint32_t)asg * SEG_B + aOff;
            const uint32_t bBase = sV + (uint32_t)(buf * 2 + bsg) * SEG_B + bOff;
            #pragma unroll
            for (int ks = 0; ks < 4; ks++) {
                uint32_t a[4], bq[2][4];
                ldsm4(a, aBase + (uint32_t)(ks * 16) * 2);
                #pragma unroll
                for (int p = 0; p < 2; p++)
                    ldsm4(bq[p], bBase + (uint32_t)(p * 16 * 72 + ks * 16) * 2);
                #pragma unroll
                for (int nj = 0; nj < 4; nj++)
                    mma_bf16(o[nj], a[0], a[1], a[2], a[3],
                             bq[nj >> 1][(nj & 1) * 2], bq[nj >> 1][(nj & 1) * 2 + 1]);
            }
        }
    }

    // ---- row-sum reduction ----
    #pragma unroll
    for (int p = 0; p < 2; p++) {
        lsum[p] += __shfl_xor_sync(0xffffffffu, lsum[p], 1);
        lsum[p] += __shfl_xor_sync(0xffffffffu, lsum[p], 2);
    }
    __syncthreads();
    if ((l & 3) == 0) {
        #pragma unroll
        for (int p = 0; p < 2; p++)
            red[(wy * 16 + lr + 8 * p) * 2 + wx] = lsum[p];
    }
    __syncthreads();
    if (tid < 64) invs[tid] = 1.f / (2048.f + red[tid * 2] + red[tid * 2 + 1]);
    __syncthreads();

    // ---- epilogue: z = (vtot + o) * inv, write extended bf16 ----
    const float* vtotp = g_vt + bh * 64;
    #pragma unroll
    for (int nj = 0; nj < 4; nj++)
        #pragma unroll
        for (int p = 0; p < 2; p++) {
            int qr = wy * 16 + lr + 8 * p;
            int dc = wx * 32 + nj * 8 + lc;
            float inv = invs[qr];
            float z0 = (vtotp[dc]     + o[nj][2 * p])     * inv;
            float z1 = (vtotp[dc + 1] + o[nj][2 * p + 1]) * inv;
            bf16 h0, l0, h1, l1;
            split2(z0, h0, l0); split2(z1, h1, l1);
            bf162 hv; hv.x = h0; hv.y = h1;
            bf162 lv; lv.x = l0; lv.y = l1;
            int rglob = b * Sl + q0 + qr;
            int hd = h * 64 + dc;
            bf16* zr = g_ze + (size_t)rglob * KE;
            *(bf162*)(zr + hd)        = hv;
            *(bf162*)(zr + 1024 + hd) = lv;
            *(bf162*)(zr + 2048 + hd) = hv;
        }
}

// ---------------------------------------------------------------------------
extern "C" void kernel_launch(void* const* d_in, const int* in_sizes, int n_in,
                              void* d_out, int out_size) {
    const float* x  = (const float*)d_in[0];
    const float* WQ = (const float*)d_in[1];
    const float* bQ = (const float*)d_in[2];
    const float* WK = (const float*)d_in[3];
    const float* bK = (const float*)d_in[4];
    const float* WV = (const float*)d_in[5];
    const float* bV = (const float*)d_in[6];
    const float* WO = (const float*)d_in[7];
    const float* bO = (const float*)d_in[8];
    float* out = (float*)d_out;

    cudaFuncSetAttribute(gemm_qkv, cudaFuncAttributeMaxDynamicSharedMemorySize, SMEM_GEMM);
    cudaFuncSetAttribute(gemm_o,   cudaFuncAttributeMaxDynamicSharedMemorySize, SMEM_GEMM);
    cudaFuncSetAttribute(attn_kernel, cudaFuncAttributeMaxDynamicSharedMemorySize, ATT_SMEM);

    split_x<<<(BSR * 1024 / 4) / 256, 256>>>(x);
    tw_qkv<<<dim3(16, 48), 256>>>(WQ, WK, WV);
    tw_o<<<dim3(16, 16), 256>>>(WO);

    gemm_qkv<<<dim3(32, 24), 256, SMEM_GEMM>>>(bQ, bK, bV);

    vtrans<<<dim3(32, Bsz * Hn), 256>>>();
    vtot_kernel<<<Bsz * Hn, 256>>>();

    attn_kernel<<<dim3(32, Hn, Bsz), 256, ATT_SMEM>>>();

    gemm_o<<<dim3(32, 8), 256, SMEM_GEMM>>>(bO, out);
}

// round 7
// speedup vs baseline: 2.4339x; 1.0555x over previous
#include <cuda_runtime.h>
#include <cuda_bf16.h>
#include <math.h>
#include <stdint.h>

#define Bsz 2
#define Sl  2048
#define Hn  16
#define Dh  64
#define Dm  1024
#define BSR 4096
#define KE  3072     // extended K = 3 * 1024

typedef __nv_bfloat16 bf16;
typedef __nv_bfloat162 bf162;

#define HEAD_ELEMS ((size_t)Bsz*Hn*Sl*Dh)

// -------- scratch: device globals only (no allocation) ----------------------
__device__ __align__(16) bf16 g_xe [(size_t)BSR*KE];
__device__ __align__(16) bf16 g_ze [(size_t)BSR*KE];
__device__ __align__(16) bf16 g_we [(size_t)KE*KE];
__device__ __align__(16) bf16 g_woe[(size_t)Dm*KE];
__device__ __align__(16) bf16 g_qh[HEAD_ELEMS], g_ql[HEAD_ELEMS];  // [bh][s][d]
__device__ __align__(16) bf16 g_kh[HEAD_ELEMS], g_kl[HEAD_ELEMS];
__device__ __align__(16) bf16 g_vh[HEAD_ELEMS], g_vl[HEAD_ELEMS];
__device__ float g_vt[Bsz*Hn*Dh];

// -------- helpers ------------------------------------------------------------
__device__ __forceinline__ uint32_t smem_u32(const void* p) {
    uint32_t a;
    asm("{ .reg .u64 t; cvta.to.shared.u64 t, %1; cvt.u32.u64 %0, t; }"
        : "=r"(a) : "l"(p));
    return a;
}
__device__ __forceinline__ void cpa16(uint32_t dst, const void* src) {
    asm volatile("cp.async.ca.shared.global [%0], [%1], 16;" :: "r"(dst), "l"(src));
}
#define CP_COMMIT() asm volatile("cp.async.commit_group;")
#define CP_WAIT0()  asm volatile("cp.async.wait_group 0;")
#define CP_WAIT1()  asm volatile("cp.async.wait_group 1;")

__device__ __forceinline__ void ldsm4(uint32_t r[4], uint32_t addr) {
    asm volatile("ldmatrix.sync.aligned.m8n8.x4.shared.b16 {%0,%1,%2,%3}, [%4];"
        : "=r"(r[0]), "=r"(r[1]), "=r"(r[2]), "=r"(r[3]) : "r"(addr));
}
__device__ __forceinline__ void ldsm4t(uint32_t r[4], uint32_t addr) {
    asm volatile("ldmatrix.sync.aligned.m8n8.x4.trans.shared.b16 {%0,%1,%2,%3}, [%4];"
        : "=r"(r[0]), "=r"(r[1]), "=r"(r[2]), "=r"(r[3]) : "r"(addr));
}

__device__ __forceinline__ void mma_bf16(float c[4],
    uint32_t a0, uint32_t a1, uint32_t a2, uint32_t a3,
    uint32_t b0, uint32_t b1) {
    asm volatile(
        "mma.sync.aligned.m16n8k16.row.col.f32.bf16.bf16.f32 "
        "{%0,%1,%2,%3}, {%4,%5,%6,%7}, {%8,%9}, {%0,%1,%2,%3};"
        : "+f"(c[0]), "+f"(c[1]), "+f"(c[2]), "+f"(c[3])
        : "r"(a0), "r"(a1), "r"(a2), "r"(a3), "r"(b0), "r"(b1));
}

__device__ __forceinline__ void split2(float v, bf16& h, bf16& l) {
    h = __float2bfloat16_rn(v);
    l = __float2bfloat16_rn(v - __bfloat162float(h));
}

// -------- prep: split x into extended-K bf16 ---------------------------------
__global__ __launch_bounds__(256) void split_x(const float* __restrict__ x) {
    size_t i = ((size_t)blockIdx.x * 256 + threadIdx.x) * 4;
    float4 v = *reinterpret_cast<const float4*>(x + i);
    int r = (int)(i >> 10), m = (int)(i & 1023);
    bf16* row = g_xe + (size_t)r * KE;
    bf16 hx, lx, hy, ly, hz, lz, hw, lw;
    split2(v.x, hx, lx); split2(v.y, hy, ly);
    split2(v.z, hz, lz); split2(v.w, hw, lw);
    bf162 h01; h01.x = hx; h01.y = hy;
    bf162 h23; h23.x = hz; h23.y = hw;
    bf162 l01; l01.x = lx; l01.y = ly;
    bf162 l23; l23.x = lz; l23.y = lw;
    *(bf162*)(row + m)          = h01; *(bf162*)(row + m + 2)        = h23;
    *(bf162*)(row + 1024 + m)   = l01; *(bf162*)(row + 1024 + m + 2) = l23;
    *(bf162*)(row + 2048 + m)   = h01; *(bf162*)(row + 2048 + m + 2) = h23;
}

// -------- prep: transpose+split QKV weights ----------------------------------
__global__ __launch_bounds__(256) void tw_qkv(
    const float* __restrict__ WQ, const float* __restrict__ WK,
    const float* __restrict__ WV) {
    __shared__ float tile[64][68];
    int th = blockIdx.y;
    int t = th >> 4, h = th & 15;
    int m0 = blockIdx.x * 64;
    const float* W = ((t == 0) ? WQ : (t == 1) ? WK : WV) + (size_t)h * Dm * Dh;
    int tid = threadIdx.x;
    {
        int row = tid >> 2, fg = tid & 3;
        #pragma unroll
        for (int jj = 0; jj < 4; jj++) {
            int c = fg * 16 + jj * 4;
            *(float4*)&tile[row][c] =
                *(const float4*)(W + (size_t)(m0 + row) * Dh + c);
        }
    }
    __syncthreads();
    int dd = tid >> 2, ch = tid & 3;
    __align__(16) bf16 hb[16], lb[16];
    #pragma unroll
    for (int jj = 0; jj < 16; jj++) {
        float w = tile[ch * 16 + jj][dd];
        split2(w, hb[jj], lb[jj]);
    }
    int n = t * 1024 + h * 64 + dd;
    size_t base = (size_t)n * KE + m0 + ch * 16;
    uint4* hp = (uint4*)hb; uint4* lp = (uint4*)lb;
    *(uint4*)(g_we + base)            = hp[0]; *(uint4*)(g_we + base + 8)        = hp[1];
    *(uint4*)(g_we + base + 1024)     = hp[0]; *(uint4*)(g_we + base + 1024 + 8) = hp[1];
    *(uint4*)(g_we + base + 2048)     = lp[0]; *(uint4*)(g_we + base + 2048 + 8) = lp[1];
}

// -------- prep: transpose+split WO -------------------------------------------
__global__ __launch_bounds__(256) void tw_o(const float* __restrict__ WO) {
    __shared__ float tile[64][68];
    int mo0 = blockIdx.x * 64, hd0 = blockIdx.y * 64;
    int tid = threadIdx.x;
    {
        int row = tid >> 2, fg = tid & 3;
        #pragma unroll
        for (int jj = 0; jj < 4; jj++) {
            int c = fg * 16 + jj * 4;
            *(float4*)&tile[row][c] =
                *(const float4*)(WO + (size_t)(hd0 + row) * Dm + mo0 + c);
        }
    }
    __syncthreads();
    int mo = tid >> 2, ch = tid & 3;
    __align__(16) bf16 hb[16], lb[16];
    #pragma unroll
    for (int jj = 0; jj < 16; jj++) {
        float w = tile[ch * 16 + jj][mo];
        split2(w, hb[jj], lb[jj]);
    }
    int n = mo0 + mo;
    size_t base = (size_t)n * KE + hd0 + ch * 16;
    uint4* hp = (uint4*)hb; uint4* lp = (uint4*)lb;
    *(uint4*)(g_woe + base)            = hp[0]; *(uint4*)(g_woe + base + 8)        = hp[1];
    *(uint4*)(g_woe + base + 1024)     = hp[0]; *(uint4*)(g_woe + base + 1024 + 8) = hp[1];
    *(uint4*)(g_woe + base + 2048)     = lp[0]; *(uint4*)(g_woe + base + 2048 + 8) = lp[1];
}

// -------- GEMM: C(128x256) = Ae(128xKE).Be(256xKE)^T, 3-stage, ldmatrix ------
#define GA_B 10240                  // 128*40*2 per stage
#define GB_B 20480                  // 256*40*2 per stage
#define SMEM_GEMM (3*(GA_B+GB_B))   // 92160

__device__ __forceinline__ void gemm_issue(
    const bf16* __restrict__ Ag, const bf16* __restrict__ Bg,
    uint32_t sA, uint32_t sB, int r0, int n0, int st, int kt, int tid) {
    #pragma unroll
    for (int r = 0; r < 2; r++) {
        int e = tid + r * 256, row = e >> 2, grp = e & 3;
        cpa16(sA + (uint32_t)st * GA_B + (uint32_t)(row * 40 + grp * 8) * 2,
              Ag + (size_t)(r0 + row) * KE + kt * 32 + grp * 8);
    }
    #pragma unroll
    for (int r = 0; r < 4; r++) {
        int e = tid + r * 256, row = e >> 2, grp = e & 3;
        cpa16(sB + (uint32_t)st * GB_B + (uint32_t)(row * 40 + grp * 8) * 2,
              Bg + (size_t)(n0 + row) * KE + kt * 32 + grp * 8);
    }
}

__device__ __forceinline__ void gemm_main(
    const bf16* __restrict__ Ag, const bf16* __restrict__ Bg,
    int r0, int n0, char* dsm, float acc[4][8][4]) {
    const int tid = threadIdx.x, wid = tid >> 5, l = tid & 31;
    const int wy = wid >> 2, wx = wid & 3;
    const int g = l >> 3, lr8 = l & 7;
    uint32_t sA = smem_u32(dsm);
    uint32_t sB = sA + 3 * GA_B;
    const uint32_t aOff = (uint32_t)((wy * 64 + (g & 1) * 8 + lr8) * 40 + (g >> 1) * 8) * 2;
    const uint32_t bOff = (uint32_t)((wx * 64 + (g >> 1) * 8 + lr8) * 40 + (g & 1) * 8) * 2;

    gemm_issue(Ag, Bg, sA, sB, r0, n0, 0, 0, tid); CP_COMMIT();
    gemm_issue(Ag, Bg, sA, sB, r0, n0, 1, 1, tid); CP_COMMIT();

    for (int kt = 0; kt < 96; kt++) {
        CP_WAIT1();
        __syncthreads();
        if (kt + 2 < 96) {
            gemm_issue(Ag, Bg, sA, sB, r0, n0, (kt + 2) % 3, kt + 2, tid);
            CP_COMMIT();
        }
        uint32_t aB = sA + (uint32_t)(kt % 3) * GA_B + aOff;
        uint32_t bB = sB + (uint32_t)(kt % 3) * GB_B + bOff;
        #pragma unroll
        for (int ks = 0; ks < 2; ks++) {
            uint32_t a[4][4], bq[4][4];
            #pragma unroll
            for (int mi = 0; mi < 4; mi++)
                ldsm4(a[mi], aB + (uint32_t)(mi * 16 * 40 + ks * 16) * 2);
            #pragma unroll
            for (int p = 0; p < 4; p++)
                ldsm4(bq[p], bB + (uint32_t)(p * 16 * 40 + ks * 16) * 2);
            #pragma unroll
            for (int mi = 0; mi < 4; mi++)
                #pragma unroll
                for (int p = 0; p < 4; p++) {
                    mma_bf16(acc[mi][p * 2],     a[mi][0], a[mi][1], a[mi][2], a[mi][3],
                             bq[p][0], bq[p][1]);
                    mma_bf16(acc[mi][p * 2 + 1], a[mi][0], a[mi][1], a[mi][2], a[mi][3],
                             bq[p][2], bq[p][3]);
                }
        }
        __syncthreads();
    }
}

// -------- QKV projection GEMM ------------------------------------------------
__global__ __launch_bounds__(256, 1) void gemm_qkv(
    const float* __restrict__ bQ, const float* __restrict__ bK,
    const float* __restrict__ bV) {
    extern __shared__ char dsm[];
    const int r0 = blockIdx.x * 128, n0 = blockIdx.y * 256;
    float acc[4][8][4] = {};
    gemm_main(g_xe, g_we, r0, n0, dsm, acc);

    const int tid = threadIdx.x, wid = tid >> 5, l = tid & 31;
    const int wy = wid >> 2, wx = wid & 3;
    const int t = n0 >> 10;
    const float* bb = (t == 0) ? bQ : (t == 1) ? bK : bV;
    bf16* dh = (t == 0) ? g_qh : (t == 1) ? g_kh : g_vh;
    bf16* dl = (t == 0) ? g_ql : (t == 1) ? g_kl : g_vl;
    #pragma unroll
    for (int mi = 0; mi < 4; mi++)
        #pragma unroll
        for (int nj = 0; nj < 8; nj++)
            #pragma unroll
            for (int p = 0; p < 2; p++) {
                int row = r0 + wy * 64 + mi * 16 + (l >> 2) + 8 * p;
                int hd = (n0 & 1023) + wx * 64 + nj * 8 + (l & 3) * 2;
                float v0 = acc[mi][nj][2 * p]     + bb[hd];
                float v1 = acc[mi][nj][2 * p + 1] + bb[hd + 1];
                int h = hd >> 6, d = hd & 63, b = row >> 11, s = row & 2047;
                size_t o = ((size_t)(b * Hn + h) * Sl + s) * 64 + d;
                bf16 h0, l0, h1, l1;
                split2(v0, h0, l0); split2(v1, h1, l1);
                bf162 hv; hv.x = h0; hv.y = h1;
                bf162 lv; lv.x = l0; lv.y = l1;
                *(bf162*)(dh + o) = hv;
                *(bf162*)(dl + o) = lv;
            }
}

// -------- output projection GEMM ---------------------------------------------
__global__ __launch_bounds__(256, 1) void gemm_o(
    const float* __restrict__ bO, float* __restrict__ out) {
    extern __shared__ char dsm[];
    const int r0 = blockIdx.x * 128, n0 = blockIdx.y * 256;
    float acc[4][8][4] = {};
    gemm_main(g_ze, g_woe, r0, n0, dsm, acc);

    const int tid = threadIdx.x, wid = tid >> 5, l = tid & 31;
    const int wy = wid >> 2, wx = wid & 3;
    #pragma unroll
    for (int mi = 0; mi < 4; mi++)
        #pragma unroll
        for (int nj = 0; nj < 8; nj++)
            #pragma unroll
            for (int p = 0; p < 2; p++) {
                int row = r0 + wy * 64 + mi * 16 + (l >> 2) + 8 * p;
                int col = n0 + wx * 64 + nj * 8 + (l & 3) * 2;
                float2 o;
                o.x = acc[mi][nj][2 * p]     + bO[col];
                o.y = acc[mi][nj][2 * p + 1] + bO[col + 1];
                *(float2*)(out + (size_t)row * Dm + col) = o;
            }
}

// -------- totalV --------------------------------------------------------------
__global__ __launch_bounds__(256) void vtot_kernel() {
    __shared__ float part[4][64];
    int bh = blockIdx.x;
    int d = threadIdx.x & 63, c = threadIdx.x >> 6;
    float s = 0.f;
    for (int i = 0; i < 512; i++) {
        size_t o = ((size_t)bh * Sl + c * 512 + i) * 64 + d;
        s += __bfloat162float(g_vh[o]) + __bfloat162float(g_vl[o]);
    }
    part[c][d] = s;
    __syncthreads();
    if (threadIdx.x < 64) {
        int dd = threadIdx.x;
        g_vt[bh * 64 + dd] = part[0][dd] + part[1][dd] + part[2][dd] + part[3][dd];
    }
}

// -------- attention: register-P flash loop -----------------------------------
// p_k = exp(s_k)-1 for k<=q else 0 ; z = (totalV + sum p v) / (2048 + sum p)
// 8 warps: wy=wid>>1 (q 16-rows), wx=wid&1 (32-key slice). P never touches smem.
#define SEG_B 9216                     // 64*72*2
#define AQ    0
#define AK    18432                    // 2 stages x 2 segs
#define AV    55296                    // 2 stages x 2 segs
#define ARED  92160                    // 64*2 floats
#define ATT_SMEM 92928

__global__ __launch_bounds__(256, 2) void attn_kernel() {
    extern __shared__ char sm[];
    const uint32_t sb = smem_u32(sm);
    const uint32_t sQ = sb + AQ, sK = sb + AK, sV = sb + AV;
    float* red = (float*)(sm + ARED);

    const int qb = 31 - blockIdx.x;                 // heavy blocks first
    const int h = blockIdx.y, b = blockIdx.z;
    const int bh = b * Hn + h;
    const int q0 = qb * 64;
    const int tid = threadIdx.x, wid = tid >> 5, l = tid & 31;
    const int wy = wid >> 1, wx = wid & 1;
    const int lr = l >> 2, lc = (l & 3) * 2;
    const int g = l >> 3, lr8 = l & 7;
    const uint32_t aOff = (uint32_t)((wy * 16 + (g & 1) * 8 + lr8) * 72 + (g >> 1) * 8) * 2;
    const uint32_t kOff = (uint32_t)((wx * 32 + (g >> 1) * 8 + lr8) * 72 + (g & 1) * 8) * 2;
    const uint32_t vOff = (uint32_t)((wx * 32 + (g & 1) * 8 + lr8) * 72 + (g >> 1) * 8) * 2;

    // load Q tile (both segs)
    #pragma unroll
    for (int i = 0; i < 2; i++) {
        int idx = tid + i * 256;
        int row = idx >> 3, j = (idx & 7) * 8;
        size_t src = ((size_t)bh * Sl + q0 + row) * 64 + j;
        *(float4*)(sm + AQ + (row * 72 + j) * 2)         = *(const float4*)(g_qh + src);
        *(float4*)(sm + AQ + SEG_B + (row * 72 + j) * 2) = *(const float4*)(g_ql + src);
    }

    auto issue_tile = [&](int st, int kt) {
        #pragma unroll
        for (int i = 0; i < 2; i++) {
            int idx = tid + i * 256;
            int row = idx >> 3, j = (idx & 7) * 8;
            uint32_t so = (uint32_t)(row * 72 + j) * 2;
            size_t src = ((size_t)bh * Sl + kt * 64 + row) * 64 + j;
            cpa16(sK + (st * 2 + 0) * SEG_B + so, g_kh + src);
            cpa16(sK + (st * 2 + 1) * SEG_B + so, g_kl + src);
            cpa16(sV + (st * 2 + 0) * SEG_B + so, g_vh + src);
            cpa16(sV + (st * 2 + 1) * SEG_B + so, g_vl + src);
        }
    };

    issue_tile(0, 0); CP_COMMIT();

    float o[8][4] = {};
    float lsum[2] = {};

    for (int kt = 0; kt <= qb; kt++) {
        __syncthreads();
        const bool pre = (kt + 1 <= qb);
        if (pre) { issue_tile((kt + 1) & 1, kt + 1); CP_COMMIT(); }
        if (pre) { CP_WAIT1(); } else { CP_WAIT0(); }
        __syncthreads();
        const int buf = kt & 1;

        // ---- QK^T (3-term split): warp's 16q x 32k slice ----
        float sc[4][4] = {};
        #pragma unroll
        for (int sp = 0; sp < 3; sp++) {
            const int asg = (sp == 1), bsg = (sp == 2);
            const uint32_t aBase = sQ + (uint32_t)asg * SEG_B + aOff;
            const uint32_t bBase = sK + (uint32_t)(buf * 2 + bsg) * SEG_B + kOff;
            #pragma unroll
            for (int ks = 0; ks < 4; ks++) {
                uint32_t a[4], b0[4], b1[4];
                ldsm4(a, aBase + (uint32_t)(ks * 16) * 2);
                ldsm4(b0, bBase + (uint32_t)(ks * 16) * 2);
                ldsm4(b1, bBase + (uint32_t)(16 * 72 + ks * 16) * 2);
                mma_bf16(sc[0], a[0], a[1], a[2], a[3], b0[0], b0[1]);
                mma_bf16(sc[1], a[0], a[1], a[2], a[3], b0[2], b0[3]);
                mma_bf16(sc[2], a[0], a[1], a[2], a[3], b1[0], b1[1]);
                mma_bf16(sc[3], a[0], a[1], a[2], a[3], b1[2], b1[3]);
            }
        }

        // ---- mask + expm1 in-register ----
        const bool diag = (kt == qb);
        #pragma unroll
        for (int nj = 0; nj < 4; nj++)
            #pragma unroll
            for (int c = 0; c < 4; c++) {
                float p;
                if (diag) {
                    int qg = q0 + wy * 16 + lr + 8 * (c >> 1);
                    int kg = kt * 64 + wx * 32 + nj * 8 + lc + (c & 1);
                    p = (kg <= qg) ? (__expf(sc[nj][c] * 0.125f) - 1.f) : 0.f;
                } else {
                    p = __expf(sc[nj][c] * 0.125f) - 1.f;
                }
                lsum[c >> 1] += p;
                sc[nj][c] = p;
            }

        // ---- build P A-fragments in registers (C-frag -> A-frag identity) ----
        uint32_t ph[2][4], pl[2][4];
        #pragma unroll
        for (int j = 0; j < 2; j++) {
            bf162 hv, lv;
            #define MKFRAG(dst_h, dst_l, A, B) do {                               \
                hv.x = __float2bfloat16_rn(A); hv.y = __float2bfloat16_rn(B);     \
                lv.x = __float2bfloat16_rn((A) - __bfloat162float(hv.x));         \
                lv.y = __float2bfloat16_rn((B) - __bfloat162float(hv.y));         \
                dst_h = *(uint32_t*)&hv; dst_l = *(uint32_t*)&lv;                 \
            } while (0)
            MKFRAG(ph[j][0], pl[j][0], sc[2*j][0],   sc[2*j][1]);
            MKFRAG(ph[j][1], pl[j][1], sc[2*j][2],   sc[2*j][3]);
            MKFRAG(ph[j][2], pl[j][2], sc[2*j+1][0], sc[2*j+1][1]);
            MKFRAG(ph[j][3], pl[j][3], sc[2*j+1][2], sc[2*j+1][3]);
            #undef MKFRAG
        }

        // ---- P.V over this warp's 32-key slice (V via ldmatrix.trans) ----
        #pragma unroll
        for (int sp = 0; sp < 3; sp++) {
            const uint32_t (*A)[4] = (sp == 1) ? pl : ph;
            const int vseg = (sp == 2);
            const uint32_t vBase = sV + (uint32_t)(buf * 2 + vseg) * SEG_B + vOff;
            #pragma unroll
            for (int j = 0; j < 2; j++) {
                #pragma unroll
                for (int p = 0; p < 4; p++) {
                    uint32_t bv[4];
                    ldsm4t(bv, vBase + (uint32_t)(j * 16 * 72 + p * 16) * 2);
                    mma_bf16(o[p * 2],     A[j][0], A[j][1], A[j][2], A[j][3], bv[0], bv[1]);
                    mma_bf16(o[p * 2 + 1], A[j][0], A[j][1], A[j][2], A[j][3], bv[2], bv[3]);
                }
            }
        }
    }

    // ---- row-sum reduction (within quad over warp's 32 cols) ----
    #pragma unroll
    for (int p = 0; p < 2; p++) {
        lsum[p] += __shfl_xor_sync(0xffffffffu, lsum[p], 1);
        lsum[p] += __shfl_xor_sync(0xffffffffu, lsum[p], 2);
    }
    __syncthreads();                     // all K/V reads done; scratch reuse safe
    float* scr = (float*)(sm + AK);      // 4 wy x 32 lanes x 32 floats = 16KB
    if ((l & 3) == 0) {
        #pragma unroll
        for (int p = 0; p < 2; p++)
            red[(wy * 16 + lr + 8 * p) * 2 + wx] = lsum[p];
    }
    if (wx == 1) {
        #pragma unroll
        for (int nj = 0; nj < 8; nj++)
            #pragma unroll
            for (int c = 0; c < 4; c++)
                scr[(wy * 32 + l) * 32 + nj * 4 + c] = o[nj][c];
    }
    __syncthreads();

    if (wx == 0) {
        #pragma unroll
        for (int nj = 0; nj < 8; nj++)
            #pragma unroll
            for (int c = 0; c < 4; c++)
                o[nj][c] += scr[(wy * 32 + l) * 32 + nj * 4 + c];

        const float* vtotp = g_vt + bh * 64;
        #pragma unroll
        for (int half = 0; half < 2; half++) {
            int qr = wy * 16 + lr + 8 * half;
            float inv = 1.f / (2048.f + red[qr * 2] + red[qr * 2 + 1]);
            int rglob = b * Sl + q0 + qr;
            bf16* zr = g_ze + (size_t)rglob * KE + h * 64;
            #pragma unroll
            for (int nj = 0; nj < 8; nj++) {
                int d = nj * 8 + lc;
                float z0 = (vtotp[d]     + o[nj][half * 2])     * inv;
                float z1 = (vtotp[d + 1] + o[nj][half * 2 + 1]) * inv;
                bf16 h0, l0, h1, l1;
                split2(z0, h0, l0); split2(z1, h1, l1);
                bf162 hv; hv.x = h0; hv.y = h1;
                bf162 lv; lv.x = l0; lv.y = l1;
                *(bf162*)(zr + d)        = hv;
                *(bf162*)(zr + 1024 + d) = lv;
                *(bf162*)(zr + 2048 + d) = hv;
            }
        }
    }
}

// ---------------------------------------------------------------------------
extern "C" void kernel_launch(void* const* d_in, const int* in_sizes, int n_in,
                              void* d_out, int out_size) {
    const float* x  = (const float*)d_in[0];
    const float* WQ = (const float*)d_in[1];
    const float* bQ = (const float*)d_in[2];
    const float* WK = (const float*)d_in[3];
    const float* bK = (const float*)d_in[4];
    const float* WV = (const float*)d_in[5];
    const float* bV = (const float*)d_in[6];
    const float* WO = (const float*)d_in[7];
    const float* bO = (const float*)d_in[8];
    float* out = (float*)d_out;

    cudaFuncSetAttribute(gemm_qkv, cudaFuncAttributeMaxDynamicSharedMemorySize, SMEM_GEMM);
    cudaFuncSetAttribute(gemm_o,   cudaFuncAttributeMaxDynamicSharedMemorySize, SMEM_GEMM);
    cudaFuncSetAttribute(attn_kernel, cudaFuncAttributeMaxDynamicSharedMemorySize, ATT_SMEM);

    split_x<<<(BSR * 1024 / 4) / 256, 256>>>(x);
    tw_qkv<<<dim3(16, 48), 256>>>(WQ, WK, WV);
    tw_o<<<dim3(16, 16), 256>>>(WO);

    gemm_qkv<<<dim3(32, 12), 256, SMEM_GEMM>>>(bQ, bK, bV);

    vtot_kernel<<<Bsz * Hn, 256>>>();

    attn_kernel<<<dim3(32, Hn, Bsz), 256, ATT_SMEM>>>();

    gemm_o<<<dim3(32, 4), 256, SMEM_GEMM>>>(bO, out);
}

// round 11
// speedup vs baseline: 2.5340x; 1.0411x over previous
#include <cuda_runtime.h>
#include <cuda_bf16.h>
#include <math.h>
#include <stdint.h>

#define Bsz 2
#define Sl  2048
#define Hn  16
#define Dh  64
#define Dm  1024
#define BSR 4096
#define KE  3072     // extended K = 3 * 1024

typedef __nv_bfloat16 bf16;
typedef __nv_bfloat162 bf162;

#define HEAD_ELEMS ((size_t)Bsz*Hn*Sl*Dh)

// -------- scratch: device globals only (no allocation) ----------------------
__device__ __align__(16) bf16 g_xe [(size_t)BSR*KE];
__device__ __align__(16) bf16 g_ze [(size_t)BSR*KE];
__device__ __align__(16) bf16 g_we [(size_t)KE*KE];
__device__ __align__(16) bf16 g_woe[(size_t)Dm*KE];
__device__ __align__(16) bf16 g_qh[HEAD_ELEMS], g_ql[HEAD_ELEMS];  // [bh][s][d]
__device__ __align__(16) bf16 g_kh[HEAD_ELEMS], g_kl[HEAD_ELEMS];
__device__ __align__(16) bf16 g_vh[HEAD_ELEMS], g_vl[HEAD_ELEMS];
__device__ float g_vt[Bsz*Hn*Dh];

// -------- helpers ------------------------------------------------------------
__device__ __forceinline__ uint32_t smem_u32(const void* p) {
    uint32_t a;
    asm("{ .reg .u64 t; cvta.to.shared.u64 t, %1; cvt.u32.u64 %0, t; }"
        : "=r"(a) : "l"(p));
    return a;
}
__device__ __forceinline__ void cpa16(uint32_t dst, const void* src) {
    asm volatile("cp.async.ca.shared.global [%0], [%1], 16;" :: "r"(dst), "l"(src));
}
#define CP_COMMIT() asm volatile("cp.async.commit_group;")
#define CP_WAIT0()  asm volatile("cp.async.wait_group 0;")
#define CP_WAIT2()  asm volatile("cp.async.wait_group 2;")

__device__ __forceinline__ void ldsm4(uint32_t r[4], uint32_t addr) {
    asm volatile("ldmatrix.sync.aligned.m8n8.x4.shared.b16 {%0,%1,%2,%3}, [%4];"
        : "=r"(r[0]), "=r"(r[1]), "=r"(r[2]), "=r"(r[3]) : "r"(addr));
}
__device__ __forceinline__ void ldsm4t(uint32_t r[4], uint32_t addr) {
    asm volatile("ldmatrix.sync.aligned.m8n8.x4.trans.shared.b16 {%0,%1,%2,%3}, [%4];"
        : "=r"(r[0]), "=r"(r[1]), "=r"(r[2]), "=r"(r[3]) : "r"(addr));
}

__device__ __forceinline__ void mma_bf16(float c[4],
    uint32_t a0, uint32_t a1, uint32_t a2, uint32_t a3,
    uint32_t b0, uint32_t b1) {
    asm volatile(
        "mma.sync.aligned.m16n8k16.row.col.f32.bf16.bf16.f32 "
        "{%0,%1,%2,%3}, {%4,%5,%6,%7}, {%8,%9}, {%0,%1,%2,%3};"
        : "+f"(c[0]), "+f"(c[1]), "+f"(c[2]), "+f"(c[3])
        : "r"(a0), "r"(a1), "r"(a2), "r"(a3), "r"(b0), "r"(b1));
}

__device__ __forceinline__ void split2(float v, bf16& h, bf16& l) {
    h = __float2bfloat16_rn(v);
    l = __float2bfloat16_rn(v - __bfloat162float(h));
}

// -------- prep: split x into extended-K bf16 ---------------------------------
__global__ __launch_bounds__(256) void split_x(const float* __restrict__ x) {
    size_t i = ((size_t)blockIdx.x * 256 + threadIdx.x) * 4;
    float4 v = *reinterpret_cast<const float4*>(x + i);
    int r = (int)(i >> 10), m = (int)(i & 1023);
    bf16* row = g_xe + (size_t)r * KE;
    bf16 hx, lx, hy, ly, hz, lz, hw, lw;
    split2(v.x, hx, lx); split2(v.y, hy, ly);
    split2(v.z, hz, lz); split2(v.w, hw, lw);
    bf162 h01; h01.x = hx; h01.y = hy;
    bf162 h23; h23.x = hz; h23.y = hw;
    bf162 l01; l01.x = lx; l01.y = ly;
    bf162 l23; l23.x = lz; l23.y = lw;
    *(bf162*)(row + m)          = h01; *(bf162*)(row + m + 2)        = h23;
    *(bf162*)(row + 1024 + m)   = l01; *(bf162*)(row + 1024 + m + 2) = l23;
    *(bf162*)(row + 2048 + m)   = h01; *(bf162*)(row + 2048 + m + 2) = h23;
}

// -------- prep: transpose+split QKV weights ----------------------------------
__global__ __launch_bounds__(256) void tw_qkv(
    const float* __restrict__ WQ, const float* __restrict__ WK,
    const float* __restrict__ WV) {
    __shared__ float tile[64][68];
    int th = blockIdx.y;
    int t = th >> 4, h = th & 15;
    int m0 = blockIdx.x * 64;
    const float* W = ((t == 0) ? WQ : (t == 1) ? WK : WV) + (size_t)h * Dm * Dh;
    int tid = threadIdx.x;
    {
        int row = tid >> 2, fg = tid & 3;
        #pragma unroll
        for (int jj = 0; jj < 4; jj++) {
            int c = fg * 16 + jj * 4;
            *(float4*)&tile[row][c] =
                *(const float4*)(W + (size_t)(m0 + row) * Dh + c);
        }
    }
    __syncthreads();
    int dd = tid >> 2, ch = tid & 3;
    __align__(16) bf16 hb[16], lb[16];
    #pragma unroll
    for (int jj = 0; jj < 16; jj++) {
        float w = tile[ch * 16 + jj][dd];
        split2(w, hb[jj], lb[jj]);
    }
    int n = t * 1024 + h * 64 + dd;
    size_t base = (size_t)n * KE + m0 + ch * 16;
    uint4* hp = (uint4*)hb; uint4* lp = (uint4*)lb;
    *(uint4*)(g_we + base)            = hp[0]; *(uint4*)(g_we + base + 8)        = hp[1];
    *(uint4*)(g_we + base + 1024)     = hp[0]; *(uint4*)(g_we + base + 1024 + 8) = hp[1];
    *(uint4*)(g_we + base + 2048)     = lp[0]; *(uint4*)(g_we + base + 2048 + 8) = lp[1];
}

// -------- prep: transpose+split WO -------------------------------------------
__global__ __launch_bounds__(256) void tw_o(const float* __restrict__ WO) {
    __shared__ float tile[64][68];
    int mo0 = blockIdx.x * 64, hd0 = blockIdx.y * 64;
    int tid = threadIdx.x;
    {
        int row = tid >> 2, fg = tid & 3;
        #pragma unroll
        for (int jj = 0; jj < 4; jj++) {
            int c = fg * 16 + jj * 4;
            *(float4*)&tile[row][c] =
                *(const float4*)(WO + (size_t)(hd0 + row) * Dm + mo0 + c);
        }
    }
    __syncthreads();
    int mo = tid >> 2, ch = tid & 3;
    __align__(16) bf16 hb[16], lb[16];
    #pragma unroll
    for (int jj = 0; jj < 16; jj++) {
        float w = tile[ch * 16 + jj][mo];
        split2(w, hb[jj], lb[jj]);
    }
    int n = mo0 + mo;
    size_t base = (size_t)n * KE + hd0 + ch * 16;
    uint4* hp = (uint4*)hb; uint4* lp = (uint4*)lb;
    *(uint4*)(g_woe + base)            = hp[0]; *(uint4*)(g_woe + base + 8)        = hp[1];
    *(uint4*)(g_woe + base + 1024)     = hp[0]; *(uint4*)(g_woe + base + 1024 + 8) = hp[1];
    *(uint4*)(g_woe + base + 2048)     = lp[0]; *(uint4*)(g_woe + base + 2048 + 8) = lp[1];
}

// -------- GEMM: C(128x128) = Ae(128xKE).Be(128xKE)^T --------------------------
// 4-stage cp.async, cutlass order: WAIT -> sync -> issue(kt+3) -> compute(kt).
#define GA_B 10240                  // 128*40*2 per stage
#define SMEM_GEMM (8*GA_B)          // 4 stages x (A+B) = 81920

__device__ __forceinline__ void gemm_issue(
    const bf16* __restrict__ Ag, const bf16* __restrict__ Bg,
    uint32_t sA, uint32_t sB, int r0, int n0, int st, int kt, int tid) {
    #pragma unroll
    for (int r = 0; r < 2; r++) {
        int e = tid + r * 256, row = e >> 2, grp = e & 3;
        cpa16(sA + (uint32_t)st * GA_B + (uint32_t)(row * 40 + grp * 8) * 2,
              Ag + (size_t)(r0 + row) * KE + kt * 32 + grp * 8);
    }
    #pragma unroll
    for (int r = 0; r < 2; r++) {
        int e = tid + r * 256, row = e >> 2, grp = e & 3;
        cpa16(sB + (uint32_t)st * GA_B + (uint32_t)(row * 40 + grp * 8) * 2,
              Bg + (size_t)(n0 + row) * KE + kt * 32 + grp * 8);
    }
}

__device__ __forceinline__ void gemm_main(
    const bf16* __restrict__ Ag, const bf16* __restrict__ Bg,
    int r0, int n0, char* dsm, float acc[2][8][4]) {
    const int tid = threadIdx.x, wid = tid >> 5, l = tid & 31;
    const int wy = wid >> 1, wx = wid & 1;
    const int g = l >> 3, lr8 = l & 7;
    uint32_t sA = smem_u32(dsm);
    uint32_t sB = sA + 4 * GA_B;
    const uint32_t aOff = (uint32_t)((wy * 32 + (g & 1) * 8 + lr8) * 40 + (g >> 1) * 8) * 2;
    const uint32_t bOff = (uint32_t)((wx * 64 + (g >> 1) * 8 + lr8) * 40 + (g & 1) * 8) * 2;

    #pragma unroll
    for (int s = 0; s < 3; s++) {
        gemm_issue(Ag, Bg, sA, sB, r0, n0, s, s, tid);
        CP_COMMIT();
    }

    for (int kt = 0; kt < 96; kt++) {
        CP_WAIT2();                      // own groups: tiles <= kt landed
        __syncthreads();                 // publish all threads' tile kt; WAR ok
        if (kt + 3 < 96)
            gemm_issue(Ag, Bg, sA, sB, r0, n0, (kt + 3) & 3, kt + 3, tid);
        CP_COMMIT();                     // unconditional: pads wait2 window in tail
        uint32_t aB = sA + (uint32_t)(kt & 3) * GA_B + aOff;
        uint32_t bB = sB + (uint32_t)(kt & 3) * GA_B + bOff;
        #pragma unroll
        for (int ks = 0; ks < 2; ks++) {
            uint32_t a[2][4], bq[4][4];
            #pragma unroll
            for (int mi = 0; mi < 2; mi++)
                ldsm4(a[mi], aB + (uint32_t)(mi * 16 * 40 + ks * 16) * 2);
            #pragma unroll
            for (int p = 0; p < 4; p++)
                ldsm4(bq[p], bB + (uint32_t)(p * 16 * 40 + ks * 16) * 2);
            #pragma unroll
            for (int mi = 0; mi < 2; mi++)
                #pragma unroll
                for (int p = 0; p < 4; p++) {
                    mma_bf16(acc[mi][p * 2],     a[mi][0], a[mi][1], a[mi][2], a[mi][3],
                             bq[p][0], bq[p][1]);
                    mma_bf16(acc[mi][p * 2 + 1], a[mi][0], a[mi][1], a[mi][2], a[mi][3],
                             bq[p][2], bq[p][3]);
                }
        }
    }
}

// -------- QKV projection GEMM ------------------------------------------------
__global__ __launch_bounds__(256, 2) void gemm_qkv(
    const float* __restrict__ bQ, const float* __restrict__ bK,
    const float* __restrict__ bV) {
    extern __shared__ char dsm[];
    const int r0 = blockIdx.x * 128, n0 = blockIdx.y * 128;
    float acc[2][8][4] = {};
    gemm_main(g_xe, g_we, r0, n0, dsm, acc);

    const int tid = threadIdx.x, wid = tid >> 5, l = tid & 31;
    const int wy = wid >> 1, wx = wid & 1;
    const int t = n0 >> 10;
    const float* bb = (t == 0) ? bQ : (t == 1) ? bK : bV;
    bf16* dh = (t == 0) ? g_qh : (t == 1) ? g_kh : g_vh;
    bf16* dl = (t == 0) ? g_ql : (t == 1) ? g_kl : g_vl;
    #pragma unroll
    for (int mi = 0; mi < 2; mi++)
        #pragma unroll
        for (int nj = 0; nj < 8; nj++)
            #pragma unroll
            for (int p = 0; p < 2; p++) {
                int row = r0 + wy * 32 + mi * 16 + (l >> 2) + 8 * p;
                int hd = (n0 & 1023) + wx * 64 + nj * 8 + (l & 3) * 2;
                float v0 = acc[mi][nj][2 * p]     + bb[hd];
                float v1 = acc[mi][nj][2 * p + 1] + bb[hd + 1];
                int h = hd >> 6, d = hd & 63, b = row >> 11, s = row & 2047;
                size_t o = ((size_t)(b * Hn + h) * Sl + s) * 64 + d;
                bf16 h0, l0, h1, l1;
                split2(v0, h0, l0); split2(v1, h1, l1);
                bf162 hv; hv.x = h0; hv.y = h1;
                bf162 lv; lv.x = l0; lv.y = l1;
                *(bf162*)(dh + o) = hv;
                *(bf162*)(dl + o) = lv;
            }
}

// -------- output projection GEMM ---------------------------------------------
__global__ __launch_bounds__(256, 2) void gemm_o(
    const float* __restrict__ bO, float* __restrict__ out) {
    extern __shared__ char dsm[];
    const int r0 = blockIdx.x * 128, n0 = blockIdx.y * 128;
    float acc[2][8][4] = {};
    gemm_main(g_ze, g_woe, r0, n0, dsm, acc);

    const int tid = threadIdx.x, wid = tid >> 5, l = tid & 31;
    const int wy = wid >> 1, wx = wid & 1;
    #pragma unroll
    for (int mi = 0; mi < 2; mi++)
        #pragma unroll
        for (int nj = 0; nj < 8; nj++)
            #pragma unroll
            for (int p = 0; p < 2; p++) {
                int row = r0 + wy * 32 + mi * 16 + (l >> 2) + 8 * p;
                int col = n0 + wx * 64 + nj * 8 + (l & 3) * 2;
                float2 o;
                o.x = acc[mi][nj][2 * p]     + bO[col];
                o.y = acc[mi][nj][2 * p + 1] + bO[col + 1];
                *(float2*)(out + (size_t)row * Dm + col) = o;
            }
}

// -------- totalV --------------------------------------------------------------
__global__ __launch_bounds__(256) void vtot_kernel() {
    __shared__ float part[4][64];
    int bh = blockIdx.x;
    int d = threadIdx.x & 63, c = threadIdx.x >> 6;
    float s = 0.f;
    for (int i = 0; i < 512; i++) {
        size_t o = ((size_t)bh * Sl + c * 512 + i) * 64 + d;
        s += __bfloat162float(g_vh[o]) + __bfloat162float(g_vl[o]);
    }
    part[c][d] = s;
    __syncthreads();
    if (threadIdx.x < 64) {
        int dd = threadIdx.x;
        g_vt[bh * 64 + dd] = part[0][dd] + part[1][dd] + part[2][dd] + part[3][dd];
    }
}

// -------- attention: register-P flash loop -----------------------------------
// p_k = exp(s_k)-1 for k<=q else 0 ; z = (totalV + sum p v) / (2048 + sum p)
// Pipeline order: WAIT0 -> sync -> issue(kt+1) -> compute(kt).
#define SEG_B 9216                     // 64*72*2
#define AQ    0
#define AK    18432                    // 2 stages x 2 segs
#define AV    55296                    // 2 stages x 2 segs
#define ARED  92160                    // 64*2 floats
#define ATT_SMEM 92928

__global__ __launch_bounds__(256, 2) void attn_kernel() {
    extern __shared__ char sm[];
    const uint32_t sb = smem_u32(sm);
    const uint32_t sQ = sb + AQ, sK = sb + AK, sV = sb + AV;
    float* red = (float*)(sm + ARED);

    const int qb = 31 - blockIdx.x;                 // heavy blocks first
    const int h = blockIdx.y, b = blockIdx.z;
    const int bh = b * Hn + h;
    const int q0 = qb * 64;
    const int tid = threadIdx.x, wid = tid >> 5, l = tid & 31;
    const int wy = wid >> 1, wx = wid & 1;
    const int lr = l >> 2, lc = (l & 3) * 2;
    const int g = l >> 3, lr8 = l & 7;
    const uint32_t aOff = (uint32_t)((wy * 16 + (g & 1) * 8 + lr8) * 72 + (g >> 1) * 8) * 2;
    const uint32_t kOff = (uint32_t)((wx * 32 + (g >> 1) * 8 + lr8) * 72 + (g & 1) * 8) * 2;
    const uint32_t vOff = (uint32_t)((wx * 32 + (g & 1) * 8 + lr8) * 72 + (g >> 1) * 8) * 2;

    // load Q tile (both segs)
    #pragma unroll
    for (int i = 0; i < 2; i++) {
        int idx = tid + i * 256;
        int row = idx >> 3, j = (idx & 7) * 8;
        size_t src = ((size_t)bh * Sl + q0 + row) * 64 + j;
        *(float4*)(sm + AQ + (row * 72 + j) * 2)         = *(const float4*)(g_qh + src);
        *(float4*)(sm + AQ + SEG_B + (row * 72 + j) * 2) = *(const float4*)(g_ql + src);
    }

    auto issue_tile = [&](int st, int kt) {
        #pragma unroll
        for (int i = 0; i < 2; i++) {
            int idx = tid + i * 256;
            int row = idx >> 3, j = (idx & 7) * 8;
            uint32_t so = (uint32_t)(row * 72 + j) * 2;
            size_t src = ((size_t)bh * Sl + kt * 64 + row) * 64 + j;
            cpa16(sK + (st * 2 + 0) * SEG_B + so, g_kh + src);
            cpa16(sK + (st * 2 + 1) * SEG_B + so, g_kl + src);
            cpa16(sV + (st * 2 + 0) * SEG_B + so, g_vh + src);
            cpa16(sV + (st * 2 + 1) * SEG_B + so, g_vl + src);
        }
    };

    issue_tile(0, 0); CP_COMMIT();

    float o[8][4] = {};
    float lsum[2] = {};

    for (int kt = 0; kt <= qb; kt++) {
        CP_WAIT0();                      // tile kt landed (own groups drained)
        __syncthreads();                 // publish; Q stores covered at kt=0
        if (kt + 1 <= qb) { issue_tile((kt + 1) & 1, kt + 1); CP_COMMIT(); }
        const int buf = kt & 1;

        // ---- QK^T (3-term split): warp's 16q x 32k slice ----
        float sc[4][4] = {};
        #pragma unroll
        for (int sp = 0; sp < 3; sp++) {
            const int asg = (sp == 1), bsg = (sp == 2);
            const uint32_t aBase = sQ + (uint32_t)asg * SEG_B + aOff;
            const uint32_t bBase = sK + (uint32_t)(buf * 2 + bsg) * SEG_B + kOff;
            #pragma unroll
            for (int ks = 0; ks < 4; ks++) {
                uint32_t a[4], b0[4], b1[4];
                ldsm4(a, aBase + (uint32_t)(ks * 16) * 2);
                ldsm4(b0, bBase + (uint32_t)(ks * 16) * 2);
                ldsm4(b1, bBase + (uint32_t)(16 * 72 + ks * 16) * 2);
                mma_bf16(sc[0], a[0], a[1], a[2], a[3], b0[0], b0[1]);
                mma_bf16(sc[1], a[0], a[1], a[2], a[3], b0[2], b0[3]);
                mma_bf16(sc[2], a[0], a[1], a[2], a[3], b1[0], b1[1]);
                mma_bf16(sc[3], a[0], a[1], a[2], a[3], b1[2], b1[3]);
            }
        }

        // ---- mask + expm1 in-register ----
        const bool diag = (kt == qb);
        #pragma unroll
        for (int nj = 0; nj < 4; nj++)
            #pragma unroll
            for (int c = 0; c < 4; c++) {
                float p;
                if (diag) {
                    int qg = q0 + wy * 16 + lr + 8 * (c >> 1);
                    int kg = kt * 64 + wx * 32 + nj * 8 + lc + (c & 1);
                    p = (kg <= qg) ? (__expf(sc[nj][c] * 0.125f) - 1.f) : 0.f;
                } else {
                    p = __expf(sc[nj][c] * 0.125f) - 1.f;
                }
                lsum[c >> 1] += p;
                sc[nj][c] = p;
            }

        // ---- build P A-fragments in registers (C-frag -> A-frag identity) ----
        uint32_t ph[2][4], pl[2][4];
        #pragma unroll
        for (int j = 0; j < 2; j++) {
            bf162 hv, lv;
            #define MKFRAG(dst_h, dst_l, A, B) do {                               \
                hv.x = __float2bfloat16_rn(A); hv.y = __float2bfloat16_rn(B);     \
                lv.x = __float2bfloat16_rn((A) - __bfloat162float(hv.x));         \
                lv.y = __float2bfloat16_rn((B) - __bfloat162float(hv.y));         \
                dst_h = *(uint32_t*)&hv; dst_l = *(uint32_t*)&lv;                 \
            } while (0)
            MKFRAG(ph[j][0], pl[j][0], sc[2*j][0],   sc[2*j][1]);
            MKFRAG(ph[j][1], pl[j][1], sc[2*j][2],   sc[2*j][3]);
            MKFRAG(ph[j][2], pl[j][2], sc[2*j+1][0], sc[2*j+1][1]);
            MKFRAG(ph[j][3], pl[j][3], sc[2*j+1][2], sc[2*j+1][3]);
            #undef MKFRAG
        }

        // ---- P.V over this warp's 32-key slice (V via ldmatrix.trans) ----
        #pragma unroll
        for (int sp = 0; sp < 3; sp++) {
            const uint32_t (*A)[4] = (sp == 1) ? pl : ph;
            const int vseg = (sp == 2);
            const uint32_t vBase = sV + (uint32_t)(buf * 2 + vseg) * SEG_B + vOff;
            #pragma unroll
            for (int j = 0; j < 2; j++) {
                #pragma unroll
                for (int p = 0; p < 4; p++) {
                    uint32_t bv[4];
                    ldsm4t(bv, vBase + (uint32_t)(j * 16 * 72 + p * 16) * 2);
                    mma_bf16(o[p * 2],     A[j][0], A[j][1], A[j][2], A[j][3], bv[0], bv[1]);
                    mma_bf16(o[p * 2 + 1], A[j][0], A[j][1], A[j][2], A[j][3], bv[2], bv[3]);
                }
            }
        }
    }

    // ---- row-sum reduction (within quad over warp's 32 cols) ----
    #pragma unroll
    for (int p = 0; p < 2; p++) {
        lsum[p] += __shfl_xor_sync(0xffffffffu, lsum[p], 1);
        lsum[p] += __shfl_xor_sync(0xffffffffu, lsum[p], 2);
    }
    CP_WAIT0();                          // drain any stray copies before reuse
    __syncthreads();                     // all K/V reads done; scratch reuse safe
    float* scr = (float*)(sm + AK);      // 4 wy x 32 lanes x 32 floats = 16KB
    if ((l & 3) == 0) {
        #pragma unroll
        for (int p = 0; p < 2; p++)
            red[(wy * 16 + lr + 8 * p) * 2 + wx] = lsum[p];
    }
    if (wx == 1) {
        #pragma unroll
        for (int nj = 0; nj < 8; nj++)
            #pragma unroll
            for (int c = 0; c < 4; c++)
                scr[(wy * 32 + l) * 32 + nj * 4 + c] = o[nj][c];
    }
    __syncthreads();

    if (wx == 0) {
        #pragma unroll
        for (int nj = 0; nj < 8; nj++)
            #pragma unroll
            for (int c = 0; c < 4; c++)
                o[nj][c] += scr[(wy * 32 + l) * 32 + nj * 4 + c];

        const float* vtotp = g_vt + bh * 64;
        #pragma unroll
        for (int half = 0; half < 2; half++) {
            int qr = wy * 16 + lr + 8 * half;
            float inv = 1.f / (2048.f + red[qr * 2] + red[qr * 2 + 1]);
            int rglob = b * Sl + q0 + qr;
            bf16* zr = g_ze + (size_t)rglob * KE + h * 64;
            #pragma unroll
            for (int nj = 0; nj < 8; nj++) {
                int d = nj * 8 + lc;
                float z0 = (vtotp[d]     + o[nj][half * 2])     * inv;
                float z1 = (vtotp[d + 1] + o[nj][half * 2 + 1]) * inv;
                bf16 h0, l0, h1, l1;
                split2(z0, h0, l0); split2(z1, h1, l1);
                bf162 hv; hv.x = h0; hv.y = h1;
                bf162 lv; lv.x = l0; lv.y = l1;
                *(bf162*)(zr + d)        = hv;
                *(bf162*)(zr + 1024 + d) = lv;
                *(bf162*)(zr + 2048 + d) = hv;
            }
        }
    }
}

// ---------------------------------------------------------------------------
extern "C" void kernel_launch(void* const* d_in, const int* in_sizes, int n_in,
                              void* d_out, int out_size) {
    const float* x  = (const float*)d_in[0];
    const float* WQ = (const float*)d_in[1];
    const float* bQ = (const float*)d_in[2];
    const float* WK = (const float*)d_in[3];
    const float* bK = (const float*)d_in[4];
    const float* WV = (const float*)d_in[5];
    const float* bV = (const float*)d_in[6];
    const float* WO = (const float*)d_in[7];
    const float* bO = (const float*)d_in[8];
    float* out = (float*)d_out;

    cudaFuncSetAttribute(gemm_qkv, cudaFuncAttributeMaxDynamicSharedMemorySize, SMEM_GEMM);
    cudaFuncSetAttribute(gemm_o,   cudaFuncAttributeMaxDynamicSharedMemorySize, SMEM_GEMM);
    cudaFuncSetAttribute(attn_kernel, cudaFuncAttributeMaxDynamicSharedMemorySize, ATT_SMEM);

    split_x<<<(BSR * 1024 / 4) / 256, 256>>>(x);
    tw_qkv<<<dim3(16, 48), 256>>>(WQ, WK, WV);
    tw_o<<<dim3(16, 16), 256>>>(WO);

    gemm_qkv<<<dim3(32, 24), 256, SMEM_GEMM>>>(bQ, bK, bV);

    vtot_kernel<<<Bsz * Hn, 256>>>();

    attn_kernel<<<dim3(32, Hn, Bsz), 256, ATT_SMEM>>>();

    gemm_o<<<dim3(32, 8), 256, SMEM_GEMM>>>(bO, out);
}

// round 12
// speedup vs baseline: 2.5793x; 1.0179x over previous
#include <cuda_runtime.h>
#include <cuda_bf16.h>
#include <math.h>
#include <stdint.h>

#define Bsz 2
#define Sl  2048
#define Hn  16
#define Dh  64
#define Dm  1024
#define BSR 4096
#define KE  3072     // extended K = 3 * 1024

typedef __nv_bfloat16 bf16;
typedef __nv_bfloat162 bf162;

#define HEAD_ELEMS ((size_t)Bsz*Hn*Sl*Dh)

// -------- scratch: device globals only (no allocation) ----------------------
__device__ __align__(16) bf16 g_xe [(size_t)BSR*KE];
__device__ __align__(16) bf16 g_ze [(size_t)BSR*KE];
__device__ __align__(16) bf16 g_we [(size_t)KE*KE];
__device__ __align__(16) bf16 g_woe[(size_t)Dm*KE];
__device__ __align__(16) bf16 g_qh[HEAD_ELEMS], g_ql[HEAD_ELEMS];  // [bh][s][d]
__device__ __align__(16) bf16 g_kh[HEAD_ELEMS], g_kl[HEAD_ELEMS];
__device__ __align__(16) bf16 g_vh[HEAD_ELEMS], g_vl[HEAD_ELEMS];
__device__ float g_vt[Bsz*Hn*Dh];

// -------- helpers ------------------------------------------------------------
__device__ __forceinline__ uint32_t smem_u32(const void* p) {
    uint32_t a;
    asm("{ .reg .u64 t; cvta.to.shared.u64 t, %1; cvt.u32.u64 %0, t; }"
        : "=r"(a) : "l"(p));
    return a;
}
__device__ __forceinline__ void cpa16(uint32_t dst, const void* src) {
    asm volatile("cp.async.ca.shared.global [%0], [%1], 16;" :: "r"(dst), "l"(src));
}
#define CP_COMMIT() asm volatile("cp.async.commit_group;")
#define CP_WAIT0()  asm volatile("cp.async.wait_group 0;")
#define CP_WAIT2()  asm volatile("cp.async.wait_group 2;")

__device__ __forceinline__ void ldsm4(uint32_t r[4], uint32_t addr) {
    asm volatile("ldmatrix.sync.aligned.m8n8.x4.shared.b16 {%0,%1,%2,%3}, [%4];"
        : "=r"(r[0]), "=r"(r[1]), "=r"(r[2]), "=r"(r[3]) : "r"(addr));
}
__device__ __forceinline__ void ldsm4t(uint32_t r[4], uint32_t addr) {
    asm volatile("ldmatrix.sync.aligned.m8n8.x4.trans.shared.b16 {%0,%1,%2,%3}, [%4];"
        : "=r"(r[0]), "=r"(r[1]), "=r"(r[2]), "=r"(r[3]) : "r"(addr));
}

__device__ __forceinline__ void mma_bf16(float c[4],
    uint32_t a0, uint32_t a1, uint32_t a2, uint32_t a3,
    uint32_t b0, uint32_t b1) {
    asm volatile(
        "mma.sync.aligned.m16n8k16.row.col.f32.bf16.bf16.f32 "
        "{%0,%1,%2,%3}, {%4,%5,%6,%7}, {%8,%9}, {%0,%1,%2,%3};"
        : "+f"(c[0]), "+f"(c[1]), "+f"(c[2]), "+f"(c[3])
        : "r"(a0), "r"(a1), "r"(a2), "r"(a3), "r"(b0), "r"(b1));
}

__device__ __forceinline__ void split2(float v, bf16& h, bf16& l) {
    h = __float2bfloat16_rn(v);
    l = __float2bfloat16_rn(v - __bfloat162float(h));
}

// -------- prep: split x into extended-K bf16 ---------------------------------
__global__ __launch_bounds__(256) void split_x(const float* __restrict__ x) {
    size_t i = ((size_t)blockIdx.x * 256 + threadIdx.x) * 4;
    float4 v = *reinterpret_cast<const float4*>(x + i);
    int r = (int)(i >> 10), m = (int)(i & 1023);
    bf16* row = g_xe + (size_t)r * KE;
    bf16 hx, lx, hy, ly, hz, lz, hw, lw;
    split2(v.x, hx, lx); split2(v.y, hy, ly);
    split2(v.z, hz, lz); split2(v.w, hw, lw);
    bf162 h01; h01.x = hx; h01.y = hy;
    bf162 h23; h23.x = hz; h23.y = hw;
    bf162 l01; l01.x = lx; l01.y = ly;
    bf162 l23; l23.x = lz; l23.y = lw;
    *(bf162*)(row + m)          = h01; *(bf162*)(row + m + 2)        = h23;
    *(bf162*)(row + 1024 + m)   = l01; *(bf162*)(row + 1024 + m + 2) = l23;
    *(bf162*)(row + 2048 + m)   = h01; *(bf162*)(row + 2048 + m + 2) = h23;
}

// -------- prep: transpose+split QKV weights ----------------------------------
__global__ __launch_bounds__(256) void tw_qkv(
    const float* __restrict__ WQ, const float* __restrict__ WK,
    const float* __restrict__ WV) {
    __shared__ float tile[64][68];
    int th = blockIdx.y;
    int t = th >> 4, h = th & 15;
    int m0 = blockIdx.x * 64;
    const float* W = ((t == 0) ? WQ : (t == 1) ? WK : WV) + (size_t)h * Dm * Dh;
    int tid = threadIdx.x;
    {
        int row = tid >> 2, fg = tid & 3;
        #pragma unroll
        for (int jj = 0; jj < 4; jj++) {
            int c = fg * 16 + jj * 4;
            *(float4*)&tile[row][c] =
                *(const float4*)(W + (size_t)(m0 + row) * Dh + c);
        }
    }
    __syncthreads();
    int dd = tid >> 2, ch = tid & 3;
    __align__(16) bf16 hb[16], lb[16];
    #pragma unroll
    for (int jj = 0; jj < 16; jj++) {
        float w = tile[ch * 16 + jj][dd];
        split2(w, hb[jj], lb[jj]);
    }
    int n = t * 1024 + h * 64 + dd;
    size_t base = (size_t)n * KE + m0 + ch * 16;
    uint4* hp = (uint4*)hb; uint4* lp = (uint4*)lb;
    *(uint4*)(g_we + base)            = hp[0]; *(uint4*)(g_we + base + 8)        = hp[1];
    *(uint4*)(g_we + base + 1024)     = hp[0]; *(uint4*)(g_we + base + 1024 + 8) = hp[1];
    *(uint4*)(g_we + base + 2048)     = lp[0]; *(uint4*)(g_we + base + 2048 + 8) = lp[1];
}

// -------- prep: transpose+split WO -------------------------------------------
__global__ __launch_bounds__(256) void tw_o(const float* __restrict__ WO) {
    __shared__ float tile[64][68];
    int mo0 = blockIdx.x * 64, hd0 = blockIdx.y * 64;
    int tid = threadIdx.x;
    {
        int row = tid >> 2, fg = tid & 3;
        #pragma unroll
        for (int jj = 0; jj < 4; jj++) {
            int c = fg * 16 + jj * 4;
            *(float4*)&tile[row][c] =
                *(const float4*)(WO + (size_t)(hd0 + row) * Dm + mo0 + c);
        }
    }
    __syncthreads();
    int mo = tid >> 2, ch = tid & 3;
    __align__(16) bf16 hb[16], lb[16];
    #pragma unroll
    for (int jj = 0; jj < 16; jj++) {
        float w = tile[ch * 16 + jj][mo];
        split2(w, hb[jj], lb[jj]);
    }
    int n = mo0 + mo;
    size_t base = (size_t)n * KE + hd0 + ch * 16;
    uint4* hp = (uint4*)hb; uint4* lp = (uint4*)lb;
    *(uint4*)(g_woe + base)            = hp[0]; *(uint4*)(g_woe + base + 8)        = hp[1];
    *(uint4*)(g_woe + base + 1024)     = hp[0]; *(uint4*)(g_woe + base + 1024 + 8) = hp[1];
    *(uint4*)(g_woe + base + 2048)     = lp[0]; *(uint4*)(g_woe + base + 2048 + 8) = lp[1];
}

// -------- GEMM: C(128x128) = Ae(128xKE).Be(128xKE)^T --------------------------
// 4-stage cp.async, cutlass order: WAIT -> sync -> issue(kt+3) -> compute(kt).
#define GA_B 10240                  // 128*40*2 per stage
#define SMEM_GEMM (8*GA_B)          // 4 stages x (A+B) = 81920

__device__ __forceinline__ void gemm_issue(
    const bf16* __restrict__ Ag, const bf16* __restrict__ Bg,
    uint32_t sA, uint32_t sB, int r0, int n0, int st, int kt, int tid) {
    #pragma unroll
    for (int r = 0; r < 2; r++) {
        int e = tid + r * 256, row = e >> 2, grp = e & 3;
        cpa16(sA + (uint32_t)st * GA_B + (uint32_t)(row * 40 + grp * 8) * 2,
              Ag + (size_t)(r0 + row) * KE + kt * 32 + grp * 8);
    }
    #pragma unroll
    for (int r = 0; r < 2; r++) {
        int e = tid + r * 256, row = e >> 2, grp = e & 3;
        cpa16(sB + (uint32_t)st * GA_B + (uint32_t)(row * 40 + grp * 8) * 2,
              Bg + (size_t)(n0 + row) * KE + kt * 32 + grp * 8);
    }
}

__device__ __forceinline__ void gemm_main(
    const bf16* __restrict__ Ag, const bf16* __restrict__ Bg,
    int r0, int n0, char* dsm, float acc[2][8][4]) {
    const int tid = threadIdx.x, wid = tid >> 5, l = tid & 31;
    const int wy = wid >> 1, wx = wid & 1;
    const int g = l >> 3, lr8 = l & 7;
    uint32_t sA = smem_u32(dsm);
    uint32_t sB = sA + 4 * GA_B;
    const uint32_t aOff = (uint32_t)((wy * 32 + (g & 1) * 8 + lr8) * 40 + (g >> 1) * 8) * 2;
    const uint32_t bOff = (uint32_t)((wx * 64 + (g >> 1) * 8 + lr8) * 40 + (g & 1) * 8) * 2;

    #pragma unroll
    for (int s = 0; s < 3; s++) {
        gemm_issue(Ag, Bg, sA, sB, r0, n0, s, s, tid);
        CP_COMMIT();
    }

    for (int kt = 0; kt < 96; kt++) {
        CP_WAIT2();                      // own groups: tiles <= kt landed
        __syncthreads();                 // publish all threads' tile kt; WAR ok
        if (kt + 3 < 96)
            gemm_issue(Ag, Bg, sA, sB, r0, n0, (kt + 3) & 3, kt + 3, tid);
        CP_COMMIT();                     // unconditional: pads wait2 window in tail
        uint32_t aB = sA + (uint32_t)(kt & 3) * GA_B + aOff;
        uint32_t bB = sB + (uint32_t)(kt & 3) * GA_B + bOff;
        #pragma unroll
        for (int ks = 0; ks < 2; ks++) {
            uint32_t a[2][4], bq[4][4];
            #pragma unroll
            for (int mi = 0; mi < 2; mi++)
                ldsm4(a[mi], aB + (uint32_t)(mi * 16 * 40 + ks * 16) * 2);
            #pragma unroll
            for (int p = 0; p < 4; p++)
                ldsm4(bq[p], bB + (uint32_t)(p * 16 * 40 + ks * 16) * 2);
            #pragma unroll
            for (int mi = 0; mi < 2; mi++)
                #pragma unroll
                for (int p = 0; p < 4; p++) {
                    mma_bf16(acc[mi][p * 2],     a[mi][0], a[mi][1], a[mi][2], a[mi][3],
                             bq[p][0], bq[p][1]);
                    mma_bf16(acc[mi][p * 2 + 1], a[mi][0], a[mi][1], a[mi][2], a[mi][3],
                             bq[p][2], bq[p][3]);
                }
        }
    }
}

// -------- QKV projection GEMM ------------------------------------------------
__global__ __launch_bounds__(256, 2) void gemm_qkv(
    const float* __restrict__ bQ, const float* __restrict__ bK,
    const float* __restrict__ bV) {
    extern __shared__ char dsm[];
    const int r0 = blockIdx.x * 128, n0 = blockIdx.y * 128;
    float acc[2][8][4] = {};
    gemm_main(g_xe, g_we, r0, n0, dsm, acc);

    const int tid = threadIdx.x, wid = tid >> 5, l = tid & 31;
    const int wy = wid >> 1, wx = wid & 1;
    const int t = n0 >> 10;
    const float* bb = (t == 0) ? bQ : (t == 1) ? bK : bV;
    bf16* dh = (t == 0) ? g_qh : (t == 1) ? g_kh : g_vh;
    bf16* dl = (t == 0) ? g_ql : (t == 1) ? g_kl : g_vl;
    #pragma unroll
    for (int mi = 0; mi < 2; mi++)
        #pragma unroll
        for (int nj = 0; nj < 8; nj++)
            #pragma unroll
            for (int p = 0; p < 2; p++) {
                int row = r0 + wy * 32 + mi * 16 + (l >> 2) + 8 * p;
                int hd = (n0 & 1023) + wx * 64 + nj * 8 + (l & 3) * 2;
                float v0 = acc[mi][nj][2 * p]     + bb[hd];
                float v1 = acc[mi][nj][2 * p + 1] + bb[hd + 1];
                int h = hd >> 6, d = hd & 63, b = row >> 11, s = row & 2047;
                size_t o = ((size_t)(b * Hn + h) * Sl + s) * 64 + d;
                bf16 h0, l0, h1, l1;
                split2(v0, h0, l0); split2(v1, h1, l1);
                bf162 hv; hv.x = h0; hv.y = h1;
                bf162 lv; lv.x = l0; lv.y = l1;
                *(bf162*)(dh + o) = hv;
                *(bf162*)(dl + o) = lv;
            }
}

// -------- output projection GEMM ---------------------------------------------
__global__ __launch_bounds__(256, 2) void gemm_o(
    const float* __restrict__ bO, float* __restrict__ out) {
    extern __shared__ char dsm[];
    const int r0 = blockIdx.x * 128, n0 = blockIdx.y * 128;
    float acc[2][8][4] = {};
    gemm_main(g_ze, g_woe, r0, n0, dsm, acc);

    const int tid = threadIdx.x, wid = tid >> 5, l = tid & 31;
    const int wy = wid >> 1, wx = wid & 1;
    #pragma unroll
    for (int mi = 0; mi < 2; mi++)
        #pragma unroll
        for (int nj = 0; nj < 8; nj++)
            #pragma unroll
            for (int p = 0; p < 2; p++) {
                int row = r0 + wy * 32 + mi * 16 + (l >> 2) + 8 * p;
                int col = n0 + wx * 64 + nj * 8 + (l & 3) * 2;
                float2 o;
                o.x = acc[mi][nj][2 * p]     + bO[col];
                o.y = acc[mi][nj][2 * p + 1] + bO[col + 1];
                *(float2*)(out + (size_t)row * Dm + col) = o;
            }
}

// -------- totalV --------------------------------------------------------------
__global__ __launch_bounds__(256) void vtot_kernel() {
    __shared__ float part[4][64];
    int bh = blockIdx.x;
    int d = threadIdx.x & 63, c = threadIdx.x >> 6;
    float s = 0.f;
    for (int i = 0; i < 512; i++) {
        size_t o = ((size_t)bh * Sl + c * 512 + i) * 64 + d;
        s += __bfloat162float(g_vh[o]) + __bfloat162float(g_vl[o]);
    }
    part[c][d] = s;
    __syncthreads();
    if (threadIdx.x < 64) {
        int dd = threadIdx.x;
        g_vt[bh * 64 + dd] = part[0][dd] + part[1][dd] + part[2][dd] + part[3][dd];
    }
}

// -------- attention: register-P flash loop, hoisted fragments -----------------
// p_k = exp(s_k)-1 for k<=q else 0 ; z = (totalV + sum p v) / (2048 + sum p)
// Each Q/K/V fragment is ldmatrix'd ONCE per tile and reused across the 3
// split passes (Qh.Kh + Ql.Kh + Qh.Kl; Ph.Vh + Pl.Vh + Ph.Vl).
#define SEG_B 9216                     // 64*72*2
#define AQ    0
#define AK    18432                    // 2 stages x 2 segs
#define AV    55296                    // 2 stages x 2 segs
#define ARED  92160                    // 64*2 floats
#define ATT_SMEM 92928

__global__ __launch_bounds__(256, 2) void attn_kernel() {
    extern __shared__ char sm[];
    const uint32_t sb = smem_u32(sm);
    const uint32_t sQ = sb + AQ, sK = sb + AK, sV = sb + AV;
    float* red = (float*)(sm + ARED);

    const int qb = 31 - blockIdx.x;                 // heavy blocks first
    const int h = blockIdx.y, b = blockIdx.z;
    const int bh = b * Hn + h;
    const int q0 = qb * 64;
    const int tid = threadIdx.x, wid = tid >> 5, l = tid & 31;
    const int wy = wid >> 1, wx = wid & 1;
    const int lr = l >> 2, lc = (l & 3) * 2;
    const int g = l >> 3, lr8 = l & 7;
    const uint32_t aOff = (uint32_t)((wy * 16 + (g & 1) * 8 + lr8) * 72 + (g >> 1) * 8) * 2;
    const uint32_t kOff = (uint32_t)((wx * 32 + (g >> 1) * 8 + lr8) * 72 + (g & 1) * 8) * 2;
    const uint32_t vOff = (uint32_t)((wx * 32 + (g & 1) * 8 + lr8) * 72 + (g >> 1) * 8) * 2;

    // load Q tile (both segs)
    #pragma unroll
    for (int i = 0; i < 2; i++) {
        int idx = tid + i * 256;
        int row = idx >> 3, j = (idx & 7) * 8;
        size_t src = ((size_t)bh * Sl + q0 + row) * 64 + j;
        *(float4*)(sm + AQ + (row * 72 + j) * 2)         = *(const float4*)(g_qh + src);
        *(float4*)(sm + AQ + SEG_B + (row * 72 + j) * 2) = *(const float4*)(g_ql + src);
    }

    auto issue_tile = [&](int st, int kt) {
        #pragma unroll
        for (int i = 0; i < 2; i++) {
            int idx = tid + i * 256;
            int row = idx >> 3, j = (idx & 7) * 8;
            uint32_t so = (uint32_t)(row * 72 + j) * 2;
            size_t src = ((size_t)bh * Sl + kt * 64 + row) * 64 + j;
            cpa16(sK + (st * 2 + 0) * SEG_B + so, g_kh + src);
            cpa16(sK + (st * 2 + 1) * SEG_B + so, g_kl + src);
            cpa16(sV + (st * 2 + 0) * SEG_B + so, g_vh + src);
            cpa16(sV + (st * 2 + 1) * SEG_B + so, g_vl + src);
        }
    };

    issue_tile(0, 0); CP_COMMIT();

    float o[8][4] = {};
    float lsum[2] = {};

    for (int kt = 0; kt <= qb; kt++) {
        CP_WAIT0();                      // tile kt landed (own groups drained)
        __syncthreads();                 // publish; Q stores covered at kt=0
        if (kt + 1 <= qb) { issue_tile((kt + 1) & 1, kt + 1); CP_COMMIT(); }
        const int buf = kt & 1;

        // ---- QK^T, 3-term split with hoisted fragments ----
        float sc[4][4] = {};
        {
            const uint32_t qhB = sQ + aOff;
            const uint32_t qlB = sQ + SEG_B + aOff;
            const uint32_t khB = sK + (uint32_t)(buf * 2 + 0) * SEG_B + kOff;
            const uint32_t klB = sK + (uint32_t)(buf * 2 + 1) * SEG_B + kOff;
            #pragma unroll
            for (int ks = 0; ks < 4; ks++) {
                const uint32_t kso = (uint32_t)(ks * 16) * 2;
                uint32_t qh[4], ql[4], kh0[4], kh1[4], kl0[4], kl1[4];
                ldsm4(qh, qhB + kso);
                ldsm4(ql, qlB + kso);
                ldsm4(kh0, khB + kso);
                ldsm4(kh1, khB + (uint32_t)(16 * 72) * 2 + kso);
                ldsm4(kl0, klB + kso);
                ldsm4(kl1, klB + (uint32_t)(16 * 72) * 2 + kso);
                // Qh.Kh
                mma_bf16(sc[0], qh[0], qh[1], qh[2], qh[3], kh0[0], kh0[1]);
                mma_bf16(sc[1], qh[0], qh[1], qh[2], qh[3], kh0[2], kh0[3]);
                mma_bf16(sc[2], qh[0], qh[1], qh[2], qh[3], kh1[0], kh1[1]);
                mma_bf16(sc[3], qh[0], qh[1], qh[2], qh[3], kh1[2], kh1[3]);
                // Ql.Kh
                mma_bf16(sc[0], ql[0], ql[1], ql[2], ql[3], kh0[0], kh0[1]);
                mma_bf16(sc[1], ql[0], ql[1], ql[2], ql[3], kh0[2], kh0[3]);
                mma_bf16(sc[2], ql[0], ql[1], ql[2], ql[3], kh1[0], kh1[1]);
                mma_bf16(sc[3], ql[0], ql[1], ql[2], ql[3], kh1[2], kh1[3]);
                // Qh.Kl
                mma_bf16(sc[0], qh[0], qh[1], qh[2], qh[3], kl0[0], kl0[1]);
                mma_bf16(sc[1], qh[0], qh[1], qh[2], qh[3], kl0[2], kl0[3]);
                mma_bf16(sc[2], qh[0], qh[1], qh[2], qh[3], kl1[0], kl1[1]);
                mma_bf16(sc[3], qh[0], qh[1], qh[2], qh[3], kl1[2], kl1[3]);
            }
        }

        // ---- mask + expm1 in-register ----
        const bool diag = (kt == qb);
        #pragma unroll
        for (int nj = 0; nj < 4; nj++)
            #pragma unroll
            for (int c = 0; c < 4; c++) {
                float p;
                if (diag) {
                    int qg = q0 + wy * 16 + lr + 8 * (c >> 1);
                    int kg = kt * 64 + wx * 32 + nj * 8 + lc + (c & 1);
                    p = (kg <= qg) ? (__expf(sc[nj][c] * 0.125f) - 1.f) : 0.f;
                } else {
                    p = __expf(sc[nj][c] * 0.125f) - 1.f;
                }
                lsum[c >> 1] += p;
                sc[nj][c] = p;
            }

        // ---- build P A-fragments in registers (C-frag -> A-frag identity) ----
        uint32_t ph[2][4], pl[2][4];
        #pragma unroll
        for (int j = 0; j < 2; j++) {
            bf162 hv, lv;
            #define MKFRAG(dst_h, dst_l, A, B) do {                               \
                hv.x = __float2bfloat16_rn(A); hv.y = __float2bfloat16_rn(B);     \
                lv.x = __float2bfloat16_rn((A) - __bfloat162float(hv.x));         \
                lv.y = __float2bfloat16_rn((B) - __bfloat162float(hv.y));         \
                dst_h = *(uint32_t*)&hv; dst_l = *(uint32_t*)&lv;                 \
            } while (0)
            MKFRAG(ph[j][0], pl[j][0], sc[2*j][0],   sc[2*j][1]);
            MKFRAG(ph[j][1], pl[j][1], sc[2*j][2],   sc[2*j][3]);
            MKFRAG(ph[j][2], pl[j][2], sc[2*j+1][0], sc[2*j+1][1]);
            MKFRAG(ph[j][3], pl[j][3], sc[2*j+1][2], sc[2*j+1][3]);
            #undef MKFRAG
        }

        // ---- P.V, 3-term split with hoisted V fragments ----
        {
            const uint32_t vhB = sV + (uint32_t)(buf * 2 + 0) * SEG_B + vOff;
            const uint32_t vlB = sV + (uint32_t)(buf * 2 + 1) * SEG_B + vOff;
            #pragma unroll
            for (int j = 0; j < 2; j++) {
                const uint32_t jo = (uint32_t)(j * 16 * 72) * 2;
                #pragma unroll
                for (int p = 0; p < 4; p++) {
                    const uint32_t po = (uint32_t)(p * 16) * 2;
                    uint32_t vh[4], vl[4];
                    ldsm4t(vh, vhB + jo + po);
                    ldsm4t(vl, vlB + jo + po);
                    // Ph.Vh
                    mma_bf16(o[p * 2],     ph[j][0], ph[j][1], ph[j][2], ph[j][3], vh[0], vh[1]);
                    mma_bf16(o[p * 2 + 1], ph[j][0], ph[j][1], ph[j][2], ph[j][3], vh[2], vh[3]);
                    // Pl.Vh
                    mma_bf16(o[p * 2],     pl[j][0], pl[j][1], pl[j][2], pl[j][3], vh[0], vh[1]);
                    mma_bf16(o[p * 2 + 1], pl[j][0], pl[j][1], pl[j][2], pl[j][3], vh[2], vh[3]);
                    // Ph.Vl
                    mma_bf16(o[p * 2],     ph[j][0], ph[j][1], ph[j][2], ph[j][3], vl[0], vl[1]);
                    mma_bf16(o[p * 2 + 1], ph[j][0], ph[j][1], ph[j][2], ph[j][3], vl[2], vl[3]);
                }
            }
        }
    }

    // ---- row-sum reduction (within quad over warp's 32 cols) ----
    #pragma unroll
    for (int p = 0; p < 2; p++) {
        lsum[p] += __shfl_xor_sync(0xffffffffu, lsum[p], 1);
        lsum[p] += __shfl_xor_sync(0xffffffffu, lsum[p], 2);
    }
    CP_WAIT0();                          // drain any stray copies before reuse
    __syncthreads();                     // all K/V reads done; scratch reuse safe
    float* scr = (float*)(sm + AK);      // 4 wy x 32 lanes x 32 floats = 16KB
    if ((l & 3) == 0) {
        #pragma unroll
        for (int p = 0; p < 2; p++)
            red[(wy * 16 + lr + 8 * p) * 2 + wx] = lsum[p];
    }
    if (wx == 1) {
        #pragma unroll
        for (int nj = 0; nj < 8; nj++)
            #pragma unroll
            for (int c = 0; c < 4; c++)
                scr[(wy * 32 + l) * 32 + nj * 4 + c] = o[nj][c];
    }
    __syncthreads();

    if (wx == 0) {
        #pragma unroll
        for (int nj = 0; nj < 8; nj++)
            #pragma unroll
            for (int c = 0; c < 4; c++)
                o[nj][c] += scr[(wy * 32 + l) * 32 + nj * 4 + c];

        const float* vtotp = g_vt + bh * 64;
        #pragma unroll
        for (int half = 0; half < 2; half++) {
            int qr = wy * 16 + lr + 8 * half;
            float inv = 1.f / (2048.f + red[qr * 2] + red[qr * 2 + 1]);
            int rglob = b * Sl + q0 + qr;
            bf16* zr = g_ze + (size_t)rglob * KE + h * 64;
            #pragma unroll
            for (int nj = 0; nj < 8; nj++) {
                int d = nj * 8 + lc;
                float z0 = (vtotp[d]     + o[nj][half * 2])     * inv;
                float z1 = (vtotp[d + 1] + o[nj][half * 2 + 1]) * inv;
                bf16 h0, l0, h1, l1;
                split2(z0, h0, l0); split2(z1, h1, l1);
                bf162 hv; hv.x = h0; hv.y = h1;
                bf162 lv; lv.x = l0; lv.y = l1;
                *(bf162*)(zr + d)        = hv;
                *(bf162*)(zr + 1024 + d) = lv;
                *(bf162*)(zr + 2048 + d) = hv;
            }
        }
    }
}

// ---------------------------------------------------------------------------
extern "C" void kernel_launch(void* const* d_in, const int* in_sizes, int n_in,
                              void* d_out, int out_size) {
    const float* x  = (const float*)d_in[0];
    const float* WQ = (const float*)d_in[1];
    const float* bQ = (const float*)d_in[2];
    const float* WK = (const float*)d_in[3];
    const float* bK = (const float*)d_in[4];
    const float* WV = (const float*)d_in[5];
    const float* bV = (const float*)d_in[6];
    const float* WO = (const float*)d_in[7];
    const float* bO = (const float*)d_in[8];
    float* out = (float*)d_out;

    cudaFuncSetAttribute(gemm_qkv, cudaFuncAttributeMaxDynamicSharedMemorySize, SMEM_GEMM);
    cudaFuncSetAttribute(gemm_o,   cudaFuncAttributeMaxDynamicSharedMemorySize, SMEM_GEMM);
    cudaFuncSetAttribute(attn_kernel, cudaFuncAttributeMaxDynamicSharedMemorySize, ATT_SMEM);

    split_x<<<(BSR * 1024 / 4) / 256, 256>>>(x);
    tw_qkv<<<dim3(16, 48), 256>>>(WQ, WK, WV);
    tw_o<<<dim3(16, 16), 256>>>(WO);

    gemm_qkv<<<dim3(32, 24), 256, SMEM_GEMM>>>(bQ, bK, bV);

    vtot_kernel<<<Bsz * Hn, 256>>>();

    attn_kernel<<<dim3(32, Hn, Bsz), 256, ATT_SMEM>>>();

    gemm_o<<<dim3(32, 8), 256, SMEM_GEMM>>>(bO, out);
}

// round 14
// speedup vs baseline: 2.8658x; 1.1111x over previous
#include <cuda_runtime.h>
#include <cuda_bf16.h>
#include <math.h>
#include <stdint.h>

#define Bsz 2
#define Sl  2048
#define Hn  16
#define Dh  64
#define Dm  1024
#define BSR 4096

typedef __nv_bfloat16 bf16;
typedef __nv_bfloat162 bf162;

#define HEAD_ELEMS ((size_t)Bsz*Hn*Sl*Dh)

// -------- scratch: device globals only (no allocation) ----------------------
__device__ __align__(16) bf16 g_xh [(size_t)BSR*Dm], g_xl [(size_t)BSR*Dm];
__device__ __align__(16) bf16 g_zh [(size_t)BSR*Dm], g_zl [(size_t)BSR*Dm];
__device__ __align__(16) bf16 g_wh [(size_t)3*Hn*Dh*Dm], g_wl [(size_t)3*Hn*Dh*Dm];
__device__ __align__(16) bf16 g_woh[(size_t)Dm*Dm], g_wol[(size_t)Dm*Dm];
__device__ __align__(16) bf16 g_qh[HEAD_ELEMS], g_ql[HEAD_ELEMS];  // [bh][s][d]
__device__ __align__(16) bf16 g_kh[HEAD_ELEMS], g_kl[HEAD_ELEMS];
__device__ __align__(16) bf16 g_vh[HEAD_ELEMS], g_vl[HEAD_ELEMS];
__device__ float g_vt[Bsz*Hn*Dh];

// -------- helpers ------------------------------------------------------------
__device__ __forceinline__ uint32_t smem_u32(const void* p) {
    uint32_t a;
    asm("{ .reg .u64 t; cvta.to.shared.u64 t, %1; cvt.u32.u64 %0, t; }"
        : "=r"(a) : "l"(p));
    return a;
}
__device__ __forceinline__ void cpa16(uint32_t dst, const void* src) {
    asm volatile("cp.async.ca.shared.global [%0], [%1], 16;" :: "r"(dst), "l"(src));
}
#define CP_COMMIT() asm volatile("cp.async.commit_group;")
#define CP_WAIT0()  asm volatile("cp.async.wait_group 0;")

__device__ __forceinline__ void ldsm4(uint32_t r[4], uint32_t addr) {
    asm volatile("ldmatrix.sync.aligned.m8n8.x4.shared.b16 {%0,%1,%2,%3}, [%4];"
        : "=r"(r[0]), "=r"(r[1]), "=r"(r[2]), "=r"(r[3]) : "r"(addr));
}
__device__ __forceinline__ void ldsm4t(uint32_t r[4], uint32_t addr) {
    asm volatile("ldmatrix.sync.aligned.m8n8.x4.trans.shared.b16 {%0,%1,%2,%3}, [%4];"
        : "=r"(r[0]), "=r"(r[1]), "=r"(r[2]), "=r"(r[3]) : "r"(addr));
}

__device__ __forceinline__ void mma_bf16(float c[4],
    uint32_t a0, uint32_t a1, uint32_t a2, uint32_t a3,
    uint32_t b0, uint32_t b1) {
    asm volatile(
        "mma.sync.aligned.m16n8k16.row.col.f32.bf16.bf16.f32 "
        "{%0,%1,%2,%3}, {%4,%5,%6,%7}, {%8,%9}, {%0,%1,%2,%3};"
        : "+f"(c[0]), "+f"(c[1]), "+f"(c[2]), "+f"(c[3])
        : "r"(a0), "r"(a1), "r"(a2), "r"(a3), "r"(b0), "r"(b1));
}

__device__ __forceinline__ void split2(float v, bf16& h, bf16& l) {
    h = __float2bfloat16_rn(v);
    l = __float2bfloat16_rn(v - __bfloat162float(h));
}

// -------- prep: split x into hi/lo bf16 --------------------------------------
__global__ __launch_bounds__(256) void split_x(const float* __restrict__ x) {
    size_t i = ((size_t)blockIdx.x * 256 + threadIdx.x) * 4;
    float4 v = *reinterpret_cast<const float4*>(x + i);
    bf16 hx, lx, hy, ly, hz, lz, hw, lw;
    split2(v.x, hx, lx); split2(v.y, hy, ly);
    split2(v.z, hz, lz); split2(v.w, hw, lw);
    bf162 h01; h01.x = hx; h01.y = hy;
    bf162 h23; h23.x = hz; h23.y = hw;
    bf162 l01; l01.x = lx; l01.y = ly;
    bf162 l23; l23.x = lz; l23.y = lw;
    *(bf162*)(g_xh + i)     = h01; *(bf162*)(g_xh + i + 2) = h23;
    *(bf162*)(g_xl + i)     = l01; *(bf162*)(g_xl + i + 2) = l23;
}

// -------- prep: transpose+split QKV weights  W[h][m][d] -> [n][m] ------------
__global__ __launch_bounds__(256) void tw_qkv(
    const float* __restrict__ WQ, const float* __restrict__ WK,
    const float* __restrict__ WV) {
    __shared__ float tile[64][68];
    int th = blockIdx.y;
    int t = th >> 4, h = th & 15;
    int m0 = blockIdx.x * 64;
    const float* W = ((t == 0) ? WQ : (t == 1) ? WK : WV) + (size_t)h * Dm * Dh;
    int tid = threadIdx.x;
    {
        int row = tid >> 2, fg = tid & 3;
        #pragma unroll
        for (int jj = 0; jj < 4; jj++) {
            int c = fg * 16 + jj * 4;
            *(float4*)&tile[row][c] =
                *(const float4*)(W + (size_t)(m0 + row) * Dh + c);
        }
    }
    __syncthreads();
    int dd = tid >> 2, ch = tid & 3;
    __align__(16) bf16 hb[16], lb[16];
    #pragma unroll
    for (int jj = 0; jj < 16; jj++) {
        float w = tile[ch * 16 + jj][dd];
        split2(w, hb[jj], lb[jj]);
    }
    int n = t * 1024 + h * 64 + dd;
    size_t base = (size_t)n * Dm + m0 + ch * 16;
    uint4* hp = (uint4*)hb; uint4* lp = (uint4*)lb;
    *(uint4*)(g_wh + base) = hp[0]; *(uint4*)(g_wh + base + 8) = hp[1];
    *(uint4*)(g_wl + base) = lp[0]; *(uint4*)(g_wl + base + 8) = lp[1];
}

// -------- prep: transpose+split WO  WO[hd][mout] -> [mout][hd] ---------------
__global__ __launch_bounds__(256) void tw_o(const float* __restrict__ WO) {
    __shared__ float tile[64][68];
    int mo0 = blockIdx.x * 64, hd0 = blockIdx.y * 64;
    int tid = threadIdx.x;
    {
        int row = tid >> 2, fg = tid & 3;
        #pragma unroll
        for (int jj = 0; jj < 4; jj++) {
            int c = fg * 16 + jj * 4;
            *(float4*)&tile[row][c] =
                *(const float4*)(WO + (size_t)(hd0 + row) * Dm + mo0 + c);
        }
    }
    __syncthreads();
    int mo = tid >> 2, ch = tid & 3;
    __align__(16) bf16 hb[16], lb[16];
    #pragma unroll
    for (int jj = 0; jj < 16; jj++) {
        float w = tile[ch * 16 + jj][mo];
        split2(w, hb[jj], lb[jj]);
    }
    int n = mo0 + mo;
    size_t base = (size_t)n * Dm + hd0 + ch * 16;
    uint4* hp = (uint4*)hb; uint4* lp = (uint4*)lb;
    *(uint4*)(g_woh + base) = hp[0]; *(uint4*)(g_woh + base + 8) = hp[1];
    *(uint4*)(g_wol + base) = lp[0]; *(uint4*)(g_wol + base + 8) = lp[1];
}

// -------- GEMM: C(128x128) = Ah.Bh^T + Al.Bh^T + Ah.Bl^T over K=1024 ---------
// Hoisted 3-term split: Ah/Al/Bh/Bl tiles per 32-K step, fragments reused.
// 2-stage cp.async, order: WAIT0 -> sync -> issue(kt+1) -> compute(kt).
#define GT_B  10240                 // one 128x(32+8) bf16 tile
#define GST_B (4*GT_B)              // stage = Ah|Al|Bh|Bl
#define SMEM_GEMM (2*GST_B)         // 81920

__device__ __forceinline__ void gemm_issue(
    const bf16* __restrict__ Ah, const bf16* __restrict__ Al,
    const bf16* __restrict__ Bh, const bf16* __restrict__ Bl,
    uint32_t sb, int r0, int n0, int st, int kt, int tid) {
    #pragma unroll
    for (int r = 0; r < 2; r++) {
        int e = tid + r * 256, row = e >> 2, grp = e & 3;
        uint32_t so = (uint32_t)st * GST_B + (uint32_t)(row * 40 + grp * 8) * 2;
        size_t ao = (size_t)(r0 + row) * Dm + kt * 32 + grp * 8;
        size_t bo = (size_t)(n0 + row) * Dm + kt * 32 + grp * 8;
        cpa16(sb + so,             Ah + ao);
        cpa16(sb + GT_B + so,      Al + ao);
        cpa16(sb + 2 * GT_B + so,  Bh + bo);
        cpa16(sb + 3 * GT_B + so,  Bl + bo);
    }
}

__device__ __forceinline__ void gemm_main(
    const bf16* __restrict__ Ah, const bf16* __restrict__ Al,
    const bf16* __restrict__ Bh, const bf16* __restrict__ Bl,
    int r0, int n0, char* dsm, float acc[2][8][4]) {
    const int tid = threadIdx.x, wid = tid >> 5, l = tid & 31;
    const int wy = wid >> 1, wx = wid & 1;
    const int g = l >> 3, lr8 = l & 7;
    uint32_t sb = smem_u32(dsm);
    const uint32_t aOff = (uint32_t)((wy * 32 + (g & 1) * 8 + lr8) * 40 + (g >> 1) * 8) * 2;
    const uint32_t bOff = (uint32_t)((wx * 64 + (g >> 1) * 8 + lr8) * 40 + (g & 1) * 8) * 2;

    gemm_issue(Ah, Al, Bh, Bl, sb, r0, n0, 0, 0, tid); CP_COMMIT();

    for (int kt = 0; kt < 32; kt++) {
        CP_WAIT0();                      // own groups: tile kt landed
        __syncthreads();                 // publish tile kt; prev reads done
        if (kt + 1 < 32) {
            gemm_issue(Ah, Al, Bh, Bl, sb, r0, n0, (kt + 1) & 1, kt + 1, tid);
            CP_COMMIT();
        }
        uint32_t stB = sb + (uint32_t)(kt & 1) * GST_B;
        #pragma unroll
        for (int ks = 0; ks < 2; ks++) {
            const uint32_t kso = (uint32_t)(ks * 16) * 2;
            uint32_t ah[2][4], al[2][4];
            #pragma unroll
            for (int mi = 0; mi < 2; mi++) {
                ldsm4(ah[mi], stB + aOff + (uint32_t)(mi * 16 * 40) * 2 + kso);
                ldsm4(al[mi], stB + GT_B + aOff + (uint32_t)(mi * 16 * 40) * 2 + kso);
            }
            #pragma unroll
            for (int p = 0; p < 4; p++) {
                const uint32_t po = (uint32_t)(p * 16 * 40) * 2 + kso;
                uint32_t bh[4], bl[4];
                ldsm4(bh, stB + 2 * GT_B + bOff + po);
                ldsm4(bl, stB + 3 * GT_B + bOff + po);
                #pragma unroll
                for (int mi = 0; mi < 2; mi++) {
                    mma_bf16(acc[mi][p * 2],     ah[mi][0], ah[mi][1], ah[mi][2], ah[mi][3], bh[0], bh[1]);
                    mma_bf16(acc[mi][p * 2 + 1], ah[mi][0], ah[mi][1], ah[mi][2], ah[mi][3], bh[2], bh[3]);
                    mma_bf16(acc[mi][p * 2],     al[mi][0], al[mi][1], al[mi][2], al[mi][3], bh[0], bh[1]);
                    mma_bf16(acc[mi][p * 2 + 1], al[mi][0], al[mi][1], al[mi][2], al[mi][3], bh[2], bh[3]);
                    mma_bf16(acc[mi][p * 2],     ah[mi][0], ah[mi][1], ah[mi][2], ah[mi][3], bl[0], bl[1]);
                    mma_bf16(acc[mi][p * 2 + 1], ah[mi][0], ah[mi][1], ah[mi][2], ah[mi][3], bl[2], bl[3]);
                }
            }
        }
    }
}

// -------- QKV projection GEMM ------------------------------------------------
__global__ __launch_bounds__(256, 2) void gemm_qkv(
    const float* __restrict__ bQ, const float* __restrict__ bK,
    const float* __restrict__ bV) {
    extern __shared__ char dsm[];
    const int r0 = blockIdx.x * 128, n0 = blockIdx.y * 128;
    float acc[2][8][4] = {};
    gemm_main(g_xh, g_xl, g_wh + (size_t)n0 * Dm, g_wl + (size_t)n0 * Dm,
              r0, 0, dsm, acc);

    const int tid = threadIdx.x, wid = tid >> 5, l = tid & 31;
    const int wy = wid >> 1, wx = wid & 1;
    const int t = n0 >> 10;
    const float* bb = (t == 0) ? bQ : (t == 1) ? bK : bV;
    bf16* dh = (t == 0) ? g_qh : (t == 1) ? g_kh : g_vh;
    bf16* dl = (t == 0) ? g_ql : (t == 1) ? g_kl : g_vl;
    #pragma unroll
    for (int mi = 0; mi < 2; mi++)
        #pragma unroll
        for (int nj = 0; nj < 8; nj++)
            #pragma unroll
            for (int p = 0; p < 2; p++) {
                int row = r0 + wy * 32 + mi * 16 + (l >> 2) + 8 * p;
                int hd = (n0 & 1023) + wx * 64 + nj * 8 + (l & 3) * 2;
                float v0 = acc[mi][nj][2 * p]     + bb[hd];
                float v1 = acc[mi][nj][2 * p + 1] + bb[hd + 1];
                int h = hd >> 6, d = hd & 63, b = row >> 11, s = row & 2047;
                size_t o = ((size_t)(b * Hn + h) * Sl + s) * 64 + d;
                bf16 h0, l0, h1, l1;
                split2(v0, h0, l0); split2(v1, h1, l1);
                bf162 hv; hv.x = h0; hv.y = h1;
                bf162 lv; lv.x = l0; lv.y = l1;
                *(bf162*)(dh + o) = hv;
                *(bf162*)(dl + o) = lv;
            }
}

// -------- output projection GEMM ---------------------------------------------
__global__ __launch_bounds__(256, 2) void gemm_o(
    const float* __restrict__ bO, float* __restrict__ out) {
    extern __shared__ char dsm[];
    const int r0 = blockIdx.x * 128, n0 = blockIdx.y * 128;
    float acc[2][8][4] = {};
    gemm_main(g_zh, g_zl, g_woh + (size_t)n0 * Dm, g_wol + (size_t)n0 * Dm,
              r0, 0, dsm, acc);

    const int tid = threadIdx.x, wid = tid >> 5, l = tid & 31;
    const int wy = wid >> 1, wx = wid & 1;
    #pragma unroll
    for (int mi = 0; mi < 2; mi++)
        #pragma unroll
        for (int nj = 0; nj < 8; nj++)
            #pragma unroll
            for (int p = 0; p < 2; p++) {
                int row = r0 + wy * 32 + mi * 16 + (l >> 2) + 8 * p;
                int col = n0 + wx * 64 + nj * 8 + (l & 3) * 2;
                float2 o;
                o.x = acc[mi][nj][2 * p]     + bO[col];
                o.y = acc[mi][nj][2 * p + 1] + bO[col + 1];
                *(float2*)(out + (size_t)row * Dm + col) = o;
            }
}

// -------- totalV --------------------------------------------------------------
__global__ __launch_bounds__(256) void vtot_kernel() {
    __shared__ float part[4][64];
    int bh = blockIdx.x;
    int d = threadIdx.x & 63, c = threadIdx.x >> 6;
    float s = 0.f;
    for (int i = 0; i < 512; i++) {
        size_t o = ((size_t)bh * Sl + c * 512 + i) * 64 + d;
        s += __bfloat162float(g_vh[o]) + __bfloat162float(g_vl[o]);
    }
    part[c][d] = s;
    __syncthreads();
    if (threadIdx.x < 64) {
        int dd = threadIdx.x;
        g_vt[bh * 64 + dd] = part[0][dd] + part[1][dd] + part[2][dd] + part[3][dd];
    }
}

// -------- attention: register-P flash loop, hoisted fragments -----------------
// p_k = exp(s_k)-1 for k<=q else 0 ; z = (totalV + sum p v) / (2048 + sum p)
#define SEG_B 9216                     // 64*72*2
#define AQ    0
#define AK    18432                    // 2 stages x 2 segs
#define AV    55296                    // 2 stages x 2 segs
#define ARED  92160                    // 64*2 floats
#define ATT_SMEM 92928

__global__ __launch_bounds__(256, 2) void attn_kernel() {
    extern __shared__ char sm[];
    const uint32_t sb = smem_u32(sm);
    const uint32_t sQ = sb + AQ, sK = sb + AK, sV = sb + AV;
    float* red = (float*)(sm + ARED);

    const int qb = 31 - blockIdx.x;                 // heavy blocks first
    const int h = blockIdx.y, b = blockIdx.z;
    const int bh = b * Hn + h;
    const int q0 = qb * 64;
    const int tid = threadIdx.x, wid = tid >> 5, l = tid & 31;
    const int wy = wid >> 1, wx = wid & 1;
    const int lr = l >> 2, lc = (l & 3) * 2;
    const int g = l >> 3, lr8 = l & 7;
    const uint32_t aOff = (uint32_t)((wy * 16 + (g & 1) * 8 + lr8) * 72 + (g >> 1) * 8) * 2;
    const uint32_t kOff = (uint32_t)((wx * 32 + (g >> 1) * 8 + lr8) * 72 + (g & 1) * 8) * 2;
    const uint32_t vOff = (uint32_t)((wx * 32 + (g & 1) * 8 + lr8) * 72 + (g >> 1) * 8) * 2;

    // load Q tile (both segs)
    #pragma unroll
    for (int i = 0; i < 2; i++) {
        int idx = tid + i * 256;
        int row = idx >> 3, j = (idx & 7) * 8;
        size_t src = ((size_t)bh * Sl + q0 + row) * 64 + j;
        *(float4*)(sm + AQ + (row * 72 + j) * 2)         = *(const float4*)(g_qh + src);
        *(float4*)(sm + AQ + SEG_B + (row * 72 + j) * 2) = *(const float4*)(g_ql + src);
    }

    auto issue_tile = [&](int st, int kt) {
        #pragma unroll
        for (int i = 0; i < 2; i++) {
            int idx = tid + i * 256;
            int row = idx >> 3, j = (idx & 7) * 8;
            uint32_t so = (uint32_t)(row * 72 + j) * 2;
            size_t src = ((size_t)bh * Sl + kt * 64 + row) * 64 + j;
            cpa16(sK + (st * 2 + 0) * SEG_B + so, g_kh + src);
            cpa16(sK + (st * 2 + 1) * SEG_B + so, g_kl + src);
            cpa16(sV + (st * 2 + 0) * SEG_B + so, g_vh + src);
            cpa16(sV + (st * 2 + 1) * SEG_B + so, g_vl + src);
        }
    };

    issue_tile(0, 0); CP_COMMIT();

    float o[8][4] = {};
    float lsum[2] = {};

    for (int kt = 0; kt <= qb; kt++) {
        CP_WAIT0();                      // tile kt landed (own groups drained)
        __syncthreads();                 // publish; Q stores covered at kt=0
        if (kt + 1 <= qb) { issue_tile((kt + 1) & 1, kt + 1); CP_COMMIT(); }
        const int buf = kt & 1;

        // ---- QK^T, 3-term split with hoisted fragments ----
        float sc[4][4] = {};
        {
            const uint32_t qhB = sQ + aOff;
            const uint32_t qlB = sQ + SEG_B + aOff;
            const uint32_t khB = sK + (uint32_t)(buf * 2 + 0) * SEG_B + kOff;
            const uint32_t klB = sK + (uint32_t)(buf * 2 + 1) * SEG_B + kOff;
            #pragma unroll
            for (int ks = 0; ks < 4; ks++) {
                const uint32_t kso = (uint32_t)(ks * 16) * 2;
                uint32_t qh[4], ql[4], kh0[4], kh1[4], kl0[4], kl1[4];
                ldsm4(qh, qhB + kso);
                ldsm4(ql, qlB + kso);
                ldsm4(kh0, khB + kso);
                ldsm4(kh1, khB + (uint32_t)(16 * 72) * 2 + kso);
                ldsm4(kl0, klB + kso);
                ldsm4(kl1, klB + (uint32_t)(16 * 72) * 2 + kso);
                mma_bf16(sc[0], qh[0], qh[1], qh[2], qh[3], kh0[0], kh0[1]);
                mma_bf16(sc[1], qh[0], qh[1], qh[2], qh[3], kh0[2], kh0[3]);
                mma_bf16(sc[2], qh[0], qh[1], qh[2], qh[3], kh1[0], kh1[1]);
                mma_bf16(sc[3], qh[0], qh[1], qh[2], qh[3], kh1[2], kh1[3]);
                mma_bf16(sc[0], ql[0], ql[1], ql[2], ql[3], kh0[0], kh0[1]);
                mma_bf16(sc[1], ql[0], ql[1], ql[2], ql[3], kh0[2], kh0[3]);
                mma_bf16(sc[2], ql[0], ql[1], ql[2], ql[3], kh1[0], kh1[1]);
                mma_bf16(sc[3], ql[0], ql[1], ql[2], ql[3], kh1[2], kh1[3]);
                mma_bf16(sc[0], qh[0], qh[1], qh[2], qh[3], kl0[0], kl0[1]);
                mma_bf16(sc[1], qh[0], qh[1], qh[2], qh[3], kl0[2], kl0[3]);
                mma_bf16(sc[2], qh[0], qh[1], qh[2], qh[3], kl1[0], kl1[1]);
                mma_bf16(sc[3], qh[0], qh[1], qh[2], qh[3], kl1[2], kl1[3]);
            }
        }

        // ---- mask + expm1 in-register ----
        const bool diag = (kt == qb);
        #pragma unroll
        for (int nj = 0; nj < 4; nj++)
            #pragma unroll
            for (int c = 0; c < 4; c++) {
                float p;
                if (diag) {
                    int qg = q0 + wy * 16 + lr + 8 * (c >> 1);
                    int kg = kt * 64 + wx * 32 + nj * 8 + lc + (c & 1);
                    p = (kg <= qg) ? (__expf(sc[nj][c] * 0.125f) - 1.f) : 0.f;
                } else {
                    p = __expf(sc[nj][c] * 0.125f) - 1.f;
                }
                lsum[c >> 1] += p;
                sc[nj][c] = p;
            }

        // ---- build P A-fragments in registers (C-frag -> A-frag identity) ----
        uint32_t ph[2][4], pl[2][4];
        #pragma unroll
        for (int j = 0; j < 2; j++) {
            bf162 hv, lv;
            #define MKFRAG(dst_h, dst_l, A, B) do {                               \
                hv.x = __float2bfloat16_rn(A); hv.y = __float2bfloat16_rn(B);     \
                lv.x = __float2bfloat16_rn((A) - __bfloat162float(hv.x));         \
                lv.y = __float2bfloat16_rn((B) - __bfloat162float(hv.y));         \
                dst_h = *(uint32_t*)&hv; dst_l = *(uint32_t*)&lv;                 \
            } while (0)
            MKFRAG(ph[j][0], pl[j][0], sc[2*j][0],   sc[2*j][1]);
            MKFRAG(ph[j][1], pl[j][1], sc[2*j][2],   sc[2*j][3]);
            MKFRAG(ph[j][2], pl[j][2], sc[2*j+1][0], sc[2*j+1][1]);
            MKFRAG(ph[j][3], pl[j][3], sc[2*j+1][2], sc[2*j+1][3]);
            #undef MKFRAG
        }

        // ---- P.V, 3-term split with hoisted V fragments ----
        {
            const uint32_t vhB = sV + (uint32_t)(buf * 2 + 0) * SEG_B + vOff;
            const uint32_t vlB = sV + (uint32_t)(buf * 2 + 1) * SEG_B + vOff;
            #pragma unroll
            for (int j = 0; j < 2; j++) {
                const uint32_t jo = (uint32_t)(j * 16 * 72) * 2;
                #pragma unroll
                for (int p = 0; p < 4; p++) {
                    const uint32_t po = (uint32_t)(p * 16) * 2;
                    uint32_t vh[4], vl[4];
                    ldsm4t(vh, vhB + jo + po);
                    ldsm4t(vl, vlB + jo + po);
                    mma_bf16(o[p * 2],     ph[j][0], ph[j][1], ph[j][2], ph[j][3], vh[0], vh[1]);
                    mma_bf16(o[p * 2 + 1], ph[j][0], ph[j][1], ph[j][2], ph[j][3], vh[2], vh[3]);
                    mma_bf16(o[p * 2],     pl[j][0], pl[j][1], pl[j][2], pl[j][3], vh[0], vh[1]);
                    mma_bf16(o[p * 2 + 1], pl[j][0], pl[j][1], pl[j][2], pl[j][3], vh[2], vh[3]);
                    mma_bf16(o[p * 2],     ph[j][0], ph[j][1], ph[j][2], ph[j][3], vl[0], vl[1]);
                    mma_bf16(o[p * 2 + 1], ph[j][0], ph[j][1], ph[j][2], ph[j][3], vl[2], vl[3]);
                }
            }
        }
    }

    // ---- row-sum reduction (within quad over warp's 32 cols) ----
    #pragma unroll
    for (int p = 0; p < 2; p++) {
        lsum[p] += __shfl_xor_sync(0xffffffffu, lsum[p], 1);
        lsum[p] += __shfl_xor_sync(0xffffffffu, lsum[p], 2);
    }
    CP_WAIT0();                          // drain any stray copies before reuse
    __syncthreads();                     // all K/V reads done; scratch reuse safe
    float* scr = (float*)(sm + AK);      // 4 wy x 32 lanes x 32 floats = 16KB
    if ((l & 3) == 0) {
        #pragma unroll
        for (int p = 0; p < 2; p++)
            red[(wy * 16 + lr + 8 * p) * 2 + wx] = lsum[p];
    }
    if (wx == 1) {
        #pragma unroll
        for (int nj = 0; nj < 8; nj++)
            #pragma unroll
            for (int c = 0; c < 4; c++)
                scr[(wy * 32 + l) * 32 + nj * 4 + c] = o[nj][c];
    }
    __syncthreads();

    if (wx == 0) {
        #pragma unroll
        for (int nj = 0; nj < 8; nj++)
            #pragma unroll
            for (int c = 0; c < 4; c++)
                o[nj][c] += scr[(wy * 32 + l) * 32 + nj * 4 + c];

        const float* vtotp = g_vt + bh * 64;
        #pragma unroll
        for (int half = 0; half < 2; half++) {
            int qr = wy * 16 + lr + 8 * half;
            float inv = 1.f / (2048.f + red[qr * 2] + red[qr * 2 + 1]);
            int rglob = b * Sl + q0 + qr;
            bf16* zrh = g_zh + (size_t)rglob * Dm + h * 64;
            bf16* zrl = g_zl + (size_t)rglob * Dm + h * 64;
            #pragma unroll
            for (int nj = 0; nj < 8; nj++) {
                int d = nj * 8 + lc;
                float z0 = (vtotp[d]     + o[nj][half * 2])     * inv;
                float z1 = (vtotp[d + 1] + o[nj][half * 2 + 1]) * inv;
                bf16 h0, l0, h1, l1;
                split2(z0, h0, l0); split2(z1, h1, l1);
                bf162 hv; hv.x = h0; hv.y = h1;
                bf162 lv; lv.x = l0; lv.y = l1;
                *(bf162*)(zrh + d) = hv;
                *(bf162*)(zrl + d) = lv;
            }
        }
    }
}

// ---------------------------------------------------------------------------
extern "C" void kernel_launch(void* const* d_in, const int* in_sizes, int n_in,
                              void* d_out, int out_size) {
    const float* x  = (const float*)d_in[0];
    const float* WQ = (const float*)d_in[1];
    const float* bQ = (const float*)d_in[2];
    const float* WK = (const float*)d_in[3];
    const float* bK = (const float*)d_in[4];
    const float* WV = (const float*)d_in[5];
    const float* bV = (const float*)d_in[6];
    const float* WO = (const float*)d_in[7];
    const float* bO = (const float*)d_in[8];
    float* out = (float*)d_out;

    cudaFuncSetAttribute(gemm_qkv, cudaFuncAttributeMaxDynamicSharedMemorySize, SMEM_GEMM);
    cudaFuncSetAttribute(gemm_o,   cudaFuncAttributeMaxDynamicSharedMemorySize, SMEM_GEMM);
    cudaFuncSetAttribute(attn_kernel, cudaFuncAttributeMaxDynamicSharedMemorySize, ATT_SMEM);

    split_x<<<(BSR * Dm / 4) / 256, 256>>>(x);
    tw_qkv<<<dim3(16, 48), 256>>>(WQ, WK, WV);
    tw_o<<<dim3(16, 16), 256>>>(WO);

    gemm_qkv<<<dim3(32, 24), 256, SMEM_GEMM>>>(bQ, bK, bV);

    vtot_kernel<<<Bsz * Hn, 256>>>();

    attn_kernel<<<dim3(32, Hn, Bsz), 256, ATT_SMEM>>>();

    gemm_o<<<dim3(32, 8), 256, SMEM_GEMM>>>(bO, out);
}

// round 17
// speedup vs baseline: 2.9133x; 1.0166x over previous
#include <cuda_runtime.h>
#include <cuda_bf16.h>
#include <math.h>
#include <stdint.h>

#define Bsz 2
#define Sl  2048
#define Hn  16
#define Dh  64
#define Dm  1024
#define BSR 4096

typedef __nv_bfloat16 bf16;
typedef __nv_bfloat162 bf162;

#define HEAD_ELEMS ((size_t)Bsz*Hn*Sl*Dh)

// -------- scratch: device globals only (no allocation) ----------------------
__device__ __align__(16) bf16 g_xh [(size_t)BSR*Dm], g_xl [(size_t)BSR*Dm];
__device__ __align__(16) bf16 g_zh [(size_t)BSR*Dm], g_zl [(size_t)BSR*Dm];
__device__ __align__(16) bf16 g_wh [(size_t)3*Hn*Dh*Dm], g_wl [(size_t)3*Hn*Dh*Dm];
__device__ __align__(16) bf16 g_woh[(size_t)Dm*Dm], g_wol[(size_t)Dm*Dm];
__device__ __align__(16) bf16 g_qh[HEAD_ELEMS], g_ql[HEAD_ELEMS];  // [bh][s][d]
__device__ __align__(16) bf16 g_kh[HEAD_ELEMS], g_kl[HEAD_ELEMS];
__device__ __align__(16) bf16 g_vh[HEAD_ELEMS], g_vl[HEAD_ELEMS];
__device__ float g_vt[Bsz*Hn*Dh];

// -------- helpers ------------------------------------------------------------
__device__ __forceinline__ uint32_t smem_u32(const void* p) {
    uint32_t a;
    asm("{ .reg .u64 t; cvta.to.shared.u64 t, %1; cvt.u32.u64 %0, t; }"
        : "=r"(a) : "l"(p));
    return a;
}
__device__ __forceinline__ void cpa16(uint32_t dst, const void* src) {
    asm volatile("cp.async.ca.shared.global [%0], [%1], 16;" :: "r"(dst), "l"(src));
}
#define CP_COMMIT() asm volatile("cp.async.commit_group;")
#define CP_WAIT0()  asm volatile("cp.async.wait_group 0;")

__device__ __forceinline__ void ldsm4(uint32_t r[4], uint32_t addr) {
    asm volatile("ldmatrix.sync.aligned.m8n8.x4.shared.b16 {%0,%1,%2,%3}, [%4];"
        : "=r"(r[0]), "=r"(r[1]), "=r"(r[2]), "=r"(r[3]) : "r"(addr));
}
__device__ __forceinline__ void ldsm4t(uint32_t r[4], uint32_t addr) {
    asm volatile("ldmatrix.sync.aligned.m8n8.x4.trans.shared.b16 {%0,%1,%2,%3}, [%4];"
        : "=r"(r[0]), "=r"(r[1]), "=r"(r[2]), "=r"(r[3]) : "r"(addr));
}

__device__ __forceinline__ void mma_bf16(float c[4],
    uint32_t a0, uint32_t a1, uint32_t a2, uint32_t a3,
    uint32_t b0, uint32_t b1) {
    asm volatile(
        "mma.sync.aligned.m16n8k16.row.col.f32.bf16.bf16.f32 "
        "{%0,%1,%2,%3}, {%4,%5,%6,%7}, {%8,%9}, {%0,%1,%2,%3};"
        : "+f"(c[0]), "+f"(c[1]), "+f"(c[2]), "+f"(c[3])
        : "r"(a0), "r"(a1), "r"(a2), "r"(a3), "r"(b0), "r"(b1));
}

__device__ __forceinline__ void split2(float v, bf16& h, bf16& l) {
    h = __float2bfloat16_rn(v);
    l = __float2bfloat16_rn(v - __bfloat162float(h));
}

// -------- prep: split x into hi/lo bf16 --------------------------------------
__global__ __launch_bounds__(256) void split_x(const float* __restrict__ x) {
    size_t i = ((size_t)blockIdx.x * 256 + threadIdx.x) * 4;
    float4 v = *reinterpret_cast<const float4*>(x + i);
    bf16 hx, lx, hy, ly, hz, lz, hw, lw;
    split2(v.x, hx, lx); split2(v.y, hy, ly);
    split2(v.z, hz, lz); split2(v.w, hw, lw);
    bf162 h01; h01.x = hx; h01.y = hy;
    bf162 h23; h23.x = hz; h23.y = hw;
    bf162 l01; l01.x = lx; l01.y = ly;
    bf162 l23; l23.x = lz; l23.y = lw;
    *(bf162*)(g_xh + i)     = h01; *(bf162*)(g_xh + i + 2) = h23;
    *(bf162*)(g_xl + i)     = l01; *(bf162*)(g_xl + i + 2) = l23;
}

// -------- prep: transpose+split QKV weights  W[h][m][d] -> [n][m] ------------
__global__ __launch_bounds__(256) void tw_qkv(
    const float* __restrict__ WQ, const float* __restrict__ WK,
    const float* __restrict__ WV) {
    __shared__ float tile[64][68];
    int th = blockIdx.y;
    int t = th >> 4, h = th & 15;
    int m0 = blockIdx.x * 64;
    const float* W = ((t == 0) ? WQ : (t == 1) ? WK : WV) + (size_t)h * Dm * Dh;
    int tid = threadIdx.x;
    {
        int row = tid >> 2, fg = tid & 3;
        #pragma unroll
        for (int jj = 0; jj < 4; jj++) {
            int c = fg * 16 + jj * 4;
            *(float4*)&tile[row][c] =
                *(const float4*)(W + (size_t)(m0 + row) * Dh + c);
        }
    }
    __syncthreads();
    int dd = tid >> 2, ch = tid & 3;
    __align__(16) bf16 hb[16], lb[16];
    #pragma unroll
    for (int jj = 0; jj < 16; jj++) {
        float w = tile[ch * 16 + jj][dd];
        split2(w, hb[jj], lb[jj]);
    }
    int n = t * 1024 + h * 64 + dd;
    size_t base = (size_t)n * Dm + m0 + ch * 16;
    uint4* hp = (uint4*)hb; uint4* lp = (uint4*)lb;
    *(uint4*)(g_wh + base) = hp[0]; *(uint4*)(g_wh + base + 8) = hp[1];
    *(uint4*)(g_wl + base) = lp[0]; *(uint4*)(g_wl + base + 8) = lp[1];
}

// -------- prep: transpose+split WO  WO[hd][mout] -> [mout][hd] ---------------
__global__ __launch_bounds__(256) void tw_o(const float* __restrict__ WO) {
    __shared__ float tile[64][68];
    int mo0 = blockIdx.x * 64, hd0 = blockIdx.y * 64;
    int tid = threadIdx.x;
    {
        int row = tid >> 2, fg = tid & 3;
        #pragma unroll
        for (int jj = 0; jj < 4; jj++) {
            int c = fg * 16 + jj * 4;
            *(float4*)&tile[row][c] =
                *(const float4*)(WO + (size_t)(hd0 + row) * Dm + mo0 + c);
        }
    }
    __syncthreads();
    int mo = tid >> 2, ch = tid & 3;
    __align__(16) bf16 hb[16], lb[16];
    #pragma unroll
    for (int jj = 0; jj < 16; jj++) {
        float w = tile[ch * 16 + jj][mo];
        split2(w, hb[jj], lb[jj]);
    }
    int n = mo0 + mo;
    size_t base = (size_t)n * Dm + hd0 + ch * 16;
    uint4* hp = (uint4*)hb; uint4* lp = (uint4*)lb;
    *(uint4*)(g_woh + base) = hp[0]; *(uint4*)(g_woh + base + 8) = hp[1];
    *(uint4*)(g_wol + base) = lp[0]; *(uint4*)(g_wol + base + 8) = lp[1];
}

// -------- GEMM: C(128x128) = Ah.Bh^T + Al.Bh^T + Ah.Bl^T over K=1024 ---------
// Hoisted 3-term split: Ah/Al/Bh/Bl tiles per 32-K step, fragments reused.
// 2-stage cp.async, order: WAIT0 -> sync -> issue(kt+1) -> compute(kt).
#define GT_B  10240                 // one 128x(32+8) bf16 tile
#define GST_B (4*GT_B)              // stage = Ah|Al|Bh|Bl
#define SMEM_GEMM (2*GST_B)         // 81920

__device__ __forceinline__ void gemm_issue(
    const bf16* __restrict__ Ah, const bf16* __restrict__ Al,
    const bf16* __restrict__ Bh, const bf16* __restrict__ Bl,
    uint32_t sb, int r0, int n0, int st, int kt, int tid) {
    #pragma unroll
    for (int r = 0; r < 2; r++) {
        int e = tid + r * 256, row = e >> 2, grp = e & 3;
        uint32_t so = (uint32_t)st * GST_B + (uint32_t)(row * 40 + grp * 8) * 2;
        size_t ao = (size_t)(r0 + row) * Dm + kt * 32 + grp * 8;
        size_t bo = (size_t)(n0 + row) * Dm + kt * 32 + grp * 8;
        cpa16(sb + so,             Ah + ao);
        cpa16(sb + GT_B + so,      Al + ao);
        cpa16(sb + 2 * GT_B + so,  Bh + bo);
        cpa16(sb + 3 * GT_B + so,  Bl + bo);
    }
}

__device__ __forceinline__ void gemm_main(
    const bf16* __restrict__ Ah, const bf16* __restrict__ Al,
    const bf16* __restrict__ Bh, const bf16* __restrict__ Bl,
    int r0, int n0, char* dsm, float acc[2][8][4]) {
    const int tid = threadIdx.x, wid = tid >> 5, l = tid & 31;
    const int wy = wid >> 1, wx = wid & 1;
    const int g = l >> 3, lr8 = l & 7;
    uint32_t sb = smem_u32(dsm);
    const uint32_t aOff = (uint32_t)((wy * 32 + (g & 1) * 8 + lr8) * 40 + (g >> 1) * 8) * 2;
    const uint32_t bOff = (uint32_t)((wx * 64 + (g >> 1) * 8 + lr8) * 40 + (g & 1) * 8) * 2;

    gemm_issue(Ah, Al, Bh, Bl, sb, r0, n0, 0, 0, tid); CP_COMMIT();

    for (int kt = 0; kt < 32; kt++) {
        CP_WAIT0();                      // own groups: tile kt landed
        __syncthreads();                 // publish tile kt; prev reads done
        if (kt + 1 < 32) {
            gemm_issue(Ah, Al, Bh, Bl, sb, r0, n0, (kt + 1) & 1, kt + 1, tid);
            CP_COMMIT();
        }
        uint32_t stB = sb + (uint32_t)(kt & 1) * GST_B;
        #pragma unroll
        for (int ks = 0; ks < 2; ks++) {
            const uint32_t kso = (uint32_t)(ks * 16) * 2;
            uint32_t ah[2][4], al[2][4];
            #pragma unroll
            for (int mi = 0; mi < 2; mi++) {
                ldsm4(ah[mi], stB + aOff + (uint32_t)(mi * 16 * 40) * 2 + kso);
                ldsm4(al[mi], stB + GT_B + aOff + (uint32_t)(mi * 16 * 40) * 2 + kso);
            }
            #pragma unroll
            for (int p = 0; p < 4; p++) {
                const uint32_t po = (uint32_t)(p * 16 * 40) * 2 + kso;
                uint32_t bh[4], bl[4];
                ldsm4(bh, stB + 2 * GT_B + bOff + po);
                ldsm4(bl, stB + 3 * GT_B + bOff + po);
                #pragma unroll
                for (int mi = 0; mi < 2; mi++) {
                    mma_bf16(acc[mi][p * 2],     ah[mi][0], ah[mi][1], ah[mi][2], ah[mi][3], bh[0], bh[1]);
                    mma_bf16(acc[mi][p * 2 + 1], ah[mi][0], ah[mi][1], ah[mi][2], ah[mi][3], bh[2], bh[3]);
                    mma_bf16(acc[mi][p * 2],     al[mi][0], al[mi][1], al[mi][2], al[mi][3], bh[0], bh[1]);
                    mma_bf16(acc[mi][p * 2 + 1], al[mi][0], al[mi][1], al[mi][2], al[mi][3], bh[2], bh[3]);
                    mma_bf16(acc[mi][p * 2],     ah[mi][0], ah[mi][1], ah[mi][2], ah[mi][3], bl[0], bl[1]);
                    mma_bf16(acc[mi][p * 2 + 1], ah[mi][0], ah[mi][1], ah[mi][2], ah[mi][3], bl[2], bl[3]);
                }
            }
        }
    }
}

// -------- QKV projection GEMM ------------------------------------------------
__global__ __launch_bounds__(256, 2) void gemm_qkv(
    const float* __restrict__ bQ, const float* __restrict__ bK,
    const float* __restrict__ bV) {
    extern __shared__ char dsm[];
    const int r0 = blockIdx.x * 128, n0 = blockIdx.y * 128;
    float acc[2][8][4] = {};
    gemm_main(g_xh, g_xl, g_wh + (size_t)n0 * Dm, g_wl + (size_t)n0 * Dm,
              r0, 0, dsm, acc);

    const int tid = threadIdx.x, wid = tid >> 5, l = tid & 31;
    const int wy = wid >> 1, wx = wid & 1;
    const int t = n0 >> 10;
    const float* bb = (t == 0) ? bQ : (t == 1) ? bK : bV;
    bf16* dh = (t == 0) ? g_qh : (t == 1) ? g_kh : g_vh;
    bf16* dl = (t == 0) ? g_ql : (t == 1) ? g_kl : g_vl;
    #pragma unroll
    for (int mi = 0; mi < 2; mi++)
        #pragma unroll
        for (int nj = 0; nj < 8; nj++)
            #pragma unroll
            for (int p = 0; p < 2; p++) {
                int row = r0 + wy * 32 + mi * 16 + (l >> 2) + 8 * p;
                int hd = (n0 & 1023) + wx * 64 + nj * 8 + (l & 3) * 2;
                float v0 = acc[mi][nj][2 * p]     + bb[hd];
                float v1 = acc[mi][nj][2 * p + 1] + bb[hd + 1];
                int h = hd >> 6, d = hd & 63, b = row >> 11, s = row & 2047;
                size_t o = ((size_t)(b * Hn + h) * Sl + s) * 64 + d;
                bf16 h0, l0, h1, l1;
                split2(v0, h0, l0); split2(v1, h1, l1);
                bf162 hv; hv.x = h0; hv.y = h1;
                bf162 lv; lv.x = l0; lv.y = l1;
                *(bf162*)(dh + o) = hv;
                *(bf162*)(dl + o) = lv;
            }
}

// -------- output projection GEMM ---------------------------------------------
__global__ __launch_bounds__(256, 2) void gemm_o(
    const float* __restrict__ bO, float* __restrict__ out) {
    extern __shared__ char dsm[];
    const int r0 = blockIdx.x * 128, n0 = blockIdx.y * 128;
    float acc[2][8][4] = {};
    gemm_main(g_zh, g_zl, g_woh + (size_t)n0 * Dm, g_wol + (size_t)n0 * Dm,
              r0, 0, dsm, acc);

    const int tid = threadIdx.x, wid = tid >> 5, l = tid & 31;
    const int wy = wid >> 1, wx = wid & 1;
    #pragma unroll
    for (int mi = 0; mi < 2; mi++)
        #pragma unroll
        for (int nj = 0; nj < 8; nj++)
            #pragma unroll
            for (int p = 0; p < 2; p++) {
                int row = r0 + wy * 32 + mi * 16 + (l >> 2) + 8 * p;
                int col = n0 + wx * 64 + nj * 8 + (l & 3) * 2;
                float2 o;
                o.x = acc[mi][nj][2 * p]     + bO[col];
                o.y = acc[mi][nj][2 * p + 1] + bO[col + 1];
                *(float2*)(out + (size_t)row * Dm + col) = o;
            }
}

// -------- totalV --------------------------------------------------------------
__global__ __launch_bounds__(256) void vtot_kernel() {
    __shared__ float part[4][64];
    int bh = blockIdx.x;
    int d = threadIdx.x & 63, c = threadIdx.x >> 6;
    float s = 0.f;
    for (int i = 0; i < 512; i++) {
        size_t o = ((size_t)bh * Sl + c * 512 + i) * 64 + d;
        s += __bfloat162float(g_vh[o]) + __bfloat162float(g_vl[o]);
    }
    part[c][d] = s;
    __syncthreads();
    if (threadIdx.x < 64) {
        int dd = threadIdx.x;
        g_vt[bh * 64 + dd] = part[0][dd] + part[1][dd] + part[2][dd] + part[3][dd];
    }
}

// -------- attention: register-P flash loop, Qh fragments hoisted --------------
// p_k = exp(s_k)-1 for k<=q else 0 ; z = (totalV + sum p v) / (2048 + sum p)
#define SEG_B 9216                     // 64*72*2
#define AQ    0
#define AK    18432                    // 2 stages x 2 segs
#define AV    55296                    // 2 stages x 2 segs
#define ARED  92160                    // 64*2 floats
#define ATT_SMEM 92928

__global__ __launch_bounds__(256, 2) void attn_kernel() {
    extern __shared__ char sm[];
    const uint32_t sb = smem_u32(sm);
    const uint32_t sQ = sb + AQ, sK = sb + AK, sV = sb + AV;
    float* red = (float*)(sm + ARED);

    const int qb = 31 - blockIdx.x;                 // heavy blocks first
    const int h = blockIdx.y, b = blockIdx.z;
    const int bh = b * Hn + h;
    const int q0 = qb * 64;
    const int tid = threadIdx.x, wid = tid >> 5, l = tid & 31;
    const int wy = wid >> 1, wx = wid & 1;
    const int lr = l >> 2, lc = (l & 3) * 2;
    const int g = l >> 3, lr8 = l & 7;
    const uint32_t aOff = (uint32_t)((wy * 16 + (g & 1) * 8 + lr8) * 72 + (g >> 1) * 8) * 2;
    const uint32_t kOff = (uint32_t)((wx * 32 + (g >> 1) * 8 + lr8) * 72 + (g & 1) * 8) * 2;
    const uint32_t vOff = (uint32_t)((wx * 32 + (g & 1) * 8 + lr8) * 72 + (g >> 1) * 8) * 2;

    // load Q tile (both segs) into smem
    #pragma unroll
    for (int i = 0; i < 2; i++) {
        int idx = tid + i * 256;
        int row = idx >> 3, j = (idx & 7) * 8;
        size_t src = ((size_t)bh * Sl + q0 + row) * 64 + j;
        *(float4*)(sm + AQ + (row * 72 + j) * 2)         = *(const float4*)(g_qh + src);
        *(float4*)(sm + AQ + SEG_B + (row * 72 + j) * 2) = *(const float4*)(g_ql + src);
    }

    auto issue_tile = [&](int st, int kt) {
        #pragma unroll
        for (int i = 0; i < 2; i++) {
            int idx = tid + i * 256;
            int row = idx >> 3, j = (idx & 7) * 8;
            uint32_t so = (uint32_t)(row * 72 + j) * 2;
            size_t src = ((size_t)bh * Sl + kt * 64 + row) * 64 + j;
            cpa16(sK + (st * 2 + 0) * SEG_B + so, g_kh + src);
            cpa16(sK + (st * 2 + 1) * SEG_B + so, g_kl + src);
            cpa16(sV + (st * 2 + 0) * SEG_B + so, g_vh + src);
            cpa16(sV + (st * 2 + 1) * SEG_B + so, g_vl + src);
        }
    };

    issue_tile(0, 0); CP_COMMIT();

    // ---- hoist Qh fragments only (16 regs; Ql stays in-loop) ----
    __syncthreads();                     // publish Q smem stores
    uint32_t qfh[4][4];
    #pragma unroll
    for (int ks = 0; ks < 4; ks++)
        ldsm4(qfh[ks], sQ + aOff + (uint32_t)(ks * 16) * 2);

    float o[8][4] = {};
    float lsum[2] = {};

    for (int kt = 0; kt <= qb; kt++) {
        CP_WAIT0();                      // tile kt landed (own groups drained)
        __syncthreads();                 // publish all threads' tile kt
        if (kt + 1 <= qb) { issue_tile((kt + 1) & 1, kt + 1); CP_COMMIT(); }
        const int buf = kt & 1;

        // ---- QK^T, 3-term split; Qh from registers, Ql from smem ----
        float sc[4][4] = {};
        {
            const uint32_t qlB = sQ + SEG_B + aOff;
            const uint32_t khB = sK + (uint32_t)(buf * 2 + 0) * SEG_B + kOff;
            const uint32_t klB = sK + (uint32_t)(buf * 2 + 1) * SEG_B + kOff;
            #pragma unroll
            for (int ks = 0; ks < 4; ks++) {
                const uint32_t kso = (uint32_t)(ks * 16) * 2;
                uint32_t ql[4], kh0[4], kh1[4], kl0[4], kl1[4];
                ldsm4(ql, qlB + kso);
                ldsm4(kh0, khB + kso);
                ldsm4(kh1, khB + (uint32_t)(16 * 72) * 2 + kso);
                ldsm4(kl0, klB + kso);
                ldsm4(kl1, klB + (uint32_t)(16 * 72) * 2 + kso);
                mma_bf16(sc[0], qfh[ks][0], qfh[ks][1], qfh[ks][2], qfh[ks][3], kh0[0], kh0[1]);
                mma_bf16(sc[1], qfh[ks][0], qfh[ks][1], qfh[ks][2], qfh[ks][3], kh0[2], kh0[3]);
                mma_bf16(sc[2], qfh[ks][0], qfh[ks][1], qfh[ks][2], qfh[ks][3], kh1[0], kh1[1]);
                mma_bf16(sc[3], qfh[ks][0], qfh[ks][1], qfh[ks][2], qfh[ks][3], kh1[2], kh1[3]);
                mma_bf16(sc[0], ql[0], ql[1], ql[2], ql[3], kh0[0], kh0[1]);
                mma_bf16(sc[1], ql[0], ql[1], ql[2], ql[3], kh0[2], kh0[3]);
                mma_bf16(sc[2], ql[0], ql[1], ql[2], ql[3], kh1[0], kh1[1]);
                mma_bf16(sc[3], ql[0], ql[1], ql[2], ql[3], kh1[2], kh1[3]);
                mma_bf16(sc[0], qfh[ks][0], qfh[ks][1], qfh[ks][2], qfh[ks][3], kl0[0], kl0[1]);
                mma_bf16(sc[1], qfh[ks][0], qfh[ks][1], qfh[ks][2], qfh[ks][3], kl0[2], kl0[3]);
                mma_bf16(sc[2], qfh[ks][0], qfh[ks][1], qfh[ks][2], qfh[ks][3], kl1[0], kl1[1]);
                mma_bf16(sc[3], qfh[ks][0], qfh[ks][1], qfh[ks][2], qfh[ks][3], kl1[2], kl1[3]);
            }
        }

        // ---- mask + expm1 in-register ----
        const bool diag = (kt == qb);
        #pragma unroll
        for (int nj = 0; nj < 4; nj++)
            #pragma unroll
            for (int c = 0; c < 4; c++) {
                float p;
                if (diag) {
                    int qg = q0 + wy * 16 + lr + 8 * (c >> 1);
                    int kg = kt * 64 + wx * 32 + nj * 8 + lc + (c & 1);
                    p = (kg <= qg) ? (__expf(sc[nj][c] * 0.125f) - 1.f) : 0.f;
                } else {
                    p = __expf(sc[nj][c] * 0.125f) - 1.f;
                }
                lsum[c >> 1] += p;
                sc[nj][c] = p;
            }

        // ---- build P A-fragments in registers (C-frag -> A-frag identity) ----
        uint32_t ph[2][4], pl[2][4];
        #pragma unroll
        for (int j = 0; j < 2; j++) {
            bf162 hv, lv;
            #define MKFRAG(dst_h, dst_l, A, B) do {                               \
                hv.x = __float2bfloat16_rn(A); hv.y = __float2bfloat16_rn(B);     \
                lv.x = __float2bfloat16_rn((A) - __bfloat162float(hv.x));         \
                lv.y = __float2bfloat16_rn((B) - __bfloat162float(hv.y));         \
                dst_h = *(uint32_t*)&hv; dst_l = *(uint32_t*)&lv;                 \
            } while (0)
            MKFRAG(ph[j][0], pl[j][0], sc[2*j][0],   sc[2*j][1]);
            MKFRAG(ph[j][1], pl[j][1], sc[2*j][2],   sc[2*j][3]);
            MKFRAG(ph[j][2], pl[j][2], sc[2*j+1][0], sc[2*j+1][1]);
            MKFRAG(ph[j][3], pl[j][3], sc[2*j+1][2], sc[2*j+1][3]);
            #undef MKFRAG
        }

        // ---- P.V, 3-term split with hoisted V fragments ----
        {
            const uint32_t vhB = sV + (uint32_t)(buf * 2 + 0) * SEG_B + vOff;
            const uint32_t vlB = sV + (uint32_t)(buf * 2 + 1) * SEG_B + vOff;
            #pragma unroll
            for (int j = 0; j < 2; j++) {
                const uint32_t jo = (uint32_t)(j * 16 * 72) * 2;
                #pragma unroll
                for (int p = 0; p < 4; p++) {
                    const uint32_t po = (uint32_t)(p * 16) * 2;
                    uint32_t vh[4], vl[4];
                    ldsm4t(vh, vhB + jo + po);
                    ldsm4t(vl, vlB + jo + po);
                    mma_bf16(o[p * 2],     ph[j][0], ph[j][1], ph[j][2], ph[j][3], vh[0], vh[1]);
                    mma_bf16(o[p * 2 + 1], ph[j][0], ph[j][1], ph[j][2], ph[j][3], vh[2], vh[3]);
                    mma_bf16(o[p * 2],     pl[j][0], pl[j][1], pl[j][2], pl[j][3], vh[0], vh[1]);
                    mma_bf16(o[p * 2 + 1], pl[j][0], pl[j][1], pl[j][2], pl[j][3], vh[2], vh[3]);
                    mma_bf16(o[p * 2],     ph[j][0], ph[j][1], ph[j][2], ph[j][3], vl[0], vl[1]);
                    mma_bf16(o[p * 2 + 1], ph[j][0], ph[j][1], ph[j][2], ph[j][3], vl[2], vl[3]);
                }
            }
        }
    }

    // ---- row-sum reduction (within quad over warp's 32 cols) ----
    #pragma unroll
    for (int p = 0; p < 2; p++) {
        lsum[p] += __shfl_xor_sync(0xffffffffu, lsum[p], 1);
        lsum[p] += __shfl_xor_sync(0xffffffffu, lsum[p], 2);
    }
    CP_WAIT0();                          // drain any stray copies before reuse
    __syncthreads();                     // all K/V reads done; scratch reuse safe
    float* scr = (float*)(sm + AK);      // 4 wy x 32 lanes x 32 floats = 16KB
    if ((l & 3) == 0) {
        #pragma unroll
        for (int p = 0; p < 2; p++)
            red[(wy * 16 + lr + 8 * p) * 2 + wx] = lsum[p];
    }
    if (wx == 1) {
        #pragma unroll
        for (int nj = 0; nj < 8; nj++)
            #pragma unroll
            for (int c = 0; c < 4; c++)
                scr[(wy * 32 + l) * 32 + nj * 4 + c] = o[nj][c];
    }
    __syncthreads();

    if (wx == 0) {
        #pragma unroll
        for (int nj = 0; nj < 8; nj++)
            #pragma unroll
            for (int c = 0; c < 4; c++)
                o[nj][c] += scr[(wy * 32 + l) * 32 + nj * 4 + c];

        const float* vtotp = g_vt + bh * 64;
        #pragma unroll
        for (int half = 0; half < 2; half++) {
            int qr = wy * 16 + lr + 8 * half;
            float inv = 1.f / (2048.f + red[qr * 2] + red[qr * 2 + 1]);
            int rglob = b * Sl + q0 + qr;
            bf16* zrh = g_zh + (size_t)rglob * Dm + h * 64;
            bf16* zrl = g_zl + (size_t)rglob * Dm + h * 64;
            #pragma unroll
            for (int nj = 0; nj < 8; nj++) {
                int d = nj * 8 + lc;
                float z0 = (vtotp[d]     + o[nj][half * 2])     * inv;
                float z1 = (vtotp[d + 1] + o[nj][half * 2 + 1]) * inv;
                bf16 h0, l0, h1, l1;
                split2(z0, h0, l0); split2(z1, h1, l1);
                bf162 hv; hv.x = h0; hv.y = h1;
                bf162 lv; lv.x = l0; lv.y = l1;
                *(bf162*)(zrh + d) = hv;
                *(bf162*)(zrl + d) = lv;
            }
        }
    }
}

// ---------------------------------------------------------------------------
extern "C" void kernel_launch(void* const* d_in, const int* in_sizes, int n_in,
                              void* d_out, int out_size) {
    const float* x  = (const float*)d_in[0];
    const float* WQ = (const float*)d_in[1];
    const float* bQ = (const float*)d_in[2];
    const float* WK = (const float*)d_in[3];
    const float* bK = (const float*)d_in[4];
    const float* WV = (const float*)d_in[5];
    const float* bV = (const float*)d_in[6];
    const float* WO = (const float*)d_in[7];
    const float* bO = (const float*)d_in[8];
    float* out = (float*)d_out;

    cudaFuncSetAttribute(gemm_qkv, cudaFuncAttributeMaxDynamicSharedMemorySize, SMEM_GEMM);
    cudaFuncSetAttribute(gemm_o,   cudaFuncAttributeMaxDynamicSharedMemorySize, SMEM_GEMM);
    cudaFuncSetAttribute(attn_kernel, cudaFuncAttributeMaxDynamicSharedMemorySize, ATT_SMEM);

    split_x<<<(BSR * Dm / 4) / 256, 256>>>(x);
    tw_qkv<<<dim3(16, 48), 256>>>(WQ, WK, WV);
    tw_o<<<dim3(16, 16), 256>>>(WO);

    gemm_qkv<<<dim3(32, 24), 256, SMEM_GEMM>>>(bQ, bK, bV);

    vtot_kernel<<<Bsz * Hn, 256>>>();

    attn_kernel<<<dim3(32, Hn, Bsz), 256, ATT_SMEM>>>();

    gemm_o<<<dim3(32, 8), 256, SMEM_GEMM>>>(bO, out);
}